// round 2
// baseline (speedup 1.0000x reference)
#include <cuda_runtime.h>

#define NBATCH 4
#define NCH 3
#define HH 128
#define WW 128
#define HW 16384
#define NN 65536
#define HID 128
#define NL 6
#define NPRM 5
#define EPSV 1e-5f
#define DTV 0.1f

// ---------------- scratch (device globals; no allocation) ----------------
__device__ float g_f[(size_t)NN * HID];
__device__ float g_A[(size_t)NN * HID];
__device__ float g_Bm[(size_t)NN * HID];
__device__ float g_tmp[(size_t)NN * HID];
__device__ float g_stats[NBATCH * 2 * HID];

__constant__ int c_dr[8] = {-1, -1, -1, 0, 0, 1, 1, 1};
__constant__ int c_dc[8] = {-1, 0, 1, -1, 1, -1, 0, 1};

__device__ __forceinline__ float swishf(float x) {
    return x / (1.0f + __expf(-x));
}

#define ACC_ZERO(acc)                                                  \
    _Pragma("unroll") for (int _i = 0; _i < 4; ++_i)                   \
        _Pragma("unroll") for (int _j = 0; _j < 8; ++_j) acc[_i][_j] = 0.0f;

// 4x8 register-tile GEMM over K=128. A is smem [rows][lda], W is smem [128][ldw].
// Thread computes rows {tr + i*RSTEP}, cols [tc*8, tc*8+8).
template <int RSTEP>
__device__ __forceinline__ void gemm128(const float* __restrict__ As, int lda,
                                        const float* __restrict__ Ws, int ldw,
                                        float acc[4][8], int tr, int tc) {
#pragma unroll 4
    for (int k4 = 0; k4 < 32; ++k4) {
        float4 a[4];
#pragma unroll
        for (int i = 0; i < 4; ++i)
            a[i] = *(const float4*)(As + (tr + i * RSTEP) * lda + k4 * 4);
        const float* wp = Ws + (k4 * 4) * ldw + tc * 8;
#pragma unroll
        for (int kk = 0; kk < 4; ++kk) {
            float4 b0 = *(const float4*)(wp + kk * ldw);
            float4 b1 = *(const float4*)(wp + kk * ldw + 4);
#pragma unroll
            for (int i = 0; i < 4; ++i) {
                float av = ((const float*)(a + i))[kk];
                acc[i][0] = fmaf(av, b0.x, acc[i][0]);
                acc[i][1] = fmaf(av, b0.y, acc[i][1]);
                acc[i][2] = fmaf(av, b0.z, acc[i][2]);
                acc[i][3] = fmaf(av, b0.w, acc[i][3]);
                acc[i][4] = fmaf(av, b1.x, acc[i][4]);
                acc[i][5] = fmaf(av, b1.y, acc[i][5]);
                acc[i][6] = fmaf(av, b1.z, acc[i][6]);
                acc[i][7] = fmaf(av, b1.w, acc[i][7]);
            }
        }
    }
}

// ---------------- embedding: f = swish(swish(e@W1+b1)@W2+b2) ----------------
__global__ __launch_bounds__(256, 2) void k_embed(
    const float* __restrict__ inp, const float* __restrict__ cp,
    const float* __restrict__ W1, const float* __restrict__ b1,
    const float* __restrict__ W2, const float* __restrict__ b2) {
    extern __shared__ float sm[];
    float* e_s = sm;                  // 64*8
    float* W1_s = e_s + 64 * 8;       // 8*128
    float* b1_s = W1_s + 8 * 128;     // 128
    float* h1_s = b1_s + 128;         // 64*132
    float* W2_s = h1_s + 64 * 132;    // 128*128
    float* b2_s = W2_s + 128 * 128;   // 128

    int tid = threadIdx.x;
    int n0 = blockIdx.x * 64;
    int b = n0 / HW;

    for (int i = tid; i < 8 * 128; i += 256) W1_s[i] = W1[i];
    if (tid < 128) { b1_s[tid] = b1[tid]; b2_s[tid] = b2[tid]; }
    for (int i = tid; i < 128 * 32; i += 256)
        ((float4*)W2_s)[i] = ((const float4*)W2)[i];
    if (tid < 64) {
        int n = n0 + tid;
        int rc = n - b * HW;
        int r = rc >> 7, c = rc & 127;
        e_s[tid * 8 + 0] = inp[b * NCH * HW + rc];
        e_s[tid * 8 + 1] = (float)r * (1.0f / 127.0f) * cp[b * NPRM + 1];
        e_s[tid * 8 + 2] = (float)c * (1.0f / 127.0f) * cp[b * NPRM + 0];
#pragma unroll
        for (int p = 0; p < NPRM; ++p) e_s[tid * 8 + 3 + p] = cp[b * NPRM + p];
    }
    __syncthreads();

    int tc = tid & 15, tr = tid >> 4;
#pragma unroll
    for (int i = 0; i < 4; ++i) {
        int row = tr + 16 * i;
#pragma unroll
        for (int j = 0; j < 8; ++j) {
            float s = b1_s[tc * 8 + j];
#pragma unroll
            for (int k = 0; k < 8; ++k)
                s = fmaf(e_s[row * 8 + k], W1_s[k * 128 + tc * 8 + j], s);
            h1_s[row * 132 + tc * 8 + j] = swishf(s);
        }
    }
    __syncthreads();
    float acc[4][8];
    ACC_ZERO(acc);
    gemm128<16>(h1_s, 132, W2_s, 128, acc, tr, tc);
#pragma unroll
    for (int i = 0; i < 4; ++i) {
        int row = tr + 16 * i;
#pragma unroll
        for (int j = 0; j < 8; ++j)
            g_f[(size_t)(n0 + row) * 128 + tc * 8 + j] =
                swishf(acc[i][j] + b2_s[tc * 8 + j]);
    }
}

// ---------------- per layer: A = f@W_t + (params@W_par + b1), Bm = f@W_s ----
__global__ __launch_bounds__(256, 2) void k_msgA(
    const float* __restrict__ cp, const float* __restrict__ msg1W,
    const float* __restrict__ msg1b, int l) {
    extern __shared__ float sm[];
    float* f_s = sm;                 // 64*132
    float* W_s = f_s + 64 * 132;     // 128*128
    float* pc_s = W_s + 128 * 128;   // 128

    int tid = threadIdx.x;
    int n0 = blockIdx.x * 64;
    int b = n0 / HW;
    const float* Wl = msg1W + (size_t)l * 264 * 128;

    if (blockIdx.x == 0)  // zero layernorm stats for this layer
        for (int i = tid; i < NBATCH * 2 * HID; i += 256) g_stats[i] = 0.0f;

    if (tid < 128) {
        float s = msg1b[l * 128 + tid];
#pragma unroll
        for (int p = 0; p < NPRM; ++p)
            s = fmaf(cp[b * NPRM + p], Wl[(259 + p) * 128 + tid], s);
        pc_s[tid] = s;
    }
    for (int i = tid; i < 64 * 32; i += 256) {
        int c = i >> 5, q = i & 31;
        ((float4*)(f_s + c * 132))[q] =
            ((const float4*)(g_f + (size_t)(n0 + c) * 128))[q];
    }
    for (int i = tid; i < 128 * 32; i += 256)
        ((float4*)W_s)[i] = ((const float4*)Wl)[i];  // rows 0..127 (W_t)
    __syncthreads();

    int tc = tid & 15, tr = tid >> 4;
    float acc[4][8];
    ACC_ZERO(acc);
    gemm128<16>(f_s, 132, W_s, 128, acc, tr, tc);
#pragma unroll
    for (int i = 0; i < 4; ++i) {
        int row = tr + 16 * i;
#pragma unroll
        for (int j = 0; j < 8; ++j)
            g_A[(size_t)(n0 + row) * 128 + tc * 8 + j] =
                acc[i][j] + pc_s[tc * 8 + j];
    }
    __syncthreads();
    for (int i = tid; i < 128 * 32; i += 256)
        ((float4*)W_s)[i] = ((const float4*)(Wl + 128 * 128))[i];  // rows 128..255 (W_s)
    __syncthreads();
    ACC_ZERO(acc);
    gemm128<16>(f_s, 132, W_s, 128, acc, tr, tc);
#pragma unroll
    for (int i = 0; i < 4; ++i) {
        int row = tr + 16 * i;
#pragma unroll
        for (int j = 0; j < 8; ++j)
            g_Bm[(size_t)(n0 + row) * 128 + tc * 8 + j] = acc[i][j];
    }
}

// ---------------- fused edge messages + aggregation + update MLP ------------
__global__ __launch_bounds__(512, 1) void k_edge(
    const float* __restrict__ inp, const float* __restrict__ cp,
    const float* __restrict__ msg1W, const float* __restrict__ msg2W,
    const float* __restrict__ msg2b, const float* __restrict__ upd1W,
    const float* __restrict__ upd1b, const float* __restrict__ upd2W,
    const float* __restrict__ upd2b, int l) {
    extern __shared__ float sm[];
    float* A_s = sm;                     // 128*132
    float* M_s = A_s + 128 * 132;        // 128*132
    float* W_s = M_s + 128 * 132;        // 128*128
    float* posW_s = W_s + 128 * 128;     // 8*128
    float* wu_s = posW_s + 8 * 128;      // 128
    float* b2m_s = wu_s + 128;           // 128
    float* pc_s = b2m_s + 128;           // 128
    float* b2u_s = pc_s + 128;           // 128
    float* du_s = b2u_s + 128;           // 128
    float* cp_s = du_s + 128;            // 8

    const int tid = threadIdx.x;
    const int gr = blockIdx.x;      // global grid row 0..511
    const int b = gr >> 7, r = gr & 127;
    const int n0 = gr << 7;         // 128 nodes = one grid row
    const float* W1l = msg1W + (size_t)l * 264 * 128;

    if (tid < 8) cp_s[tid] = (tid < NPRM) ? cp[b * NPRM + tid] : 0.0f;
    if (tid < 128) {
        wu_s[tid] = W1l[256 * 128 + tid];
        b2m_s[tid] = msg2b[l * 128 + tid];
    }
    __syncthreads();
    for (int i = tid; i < 8 * 128; i += 512) {
        int d = i >> 7, j = i & 127;
        float pdx = (float)(-c_dr[d]) * (1.0f / 127.0f) * cp_s[1];
        float pdy = (float)(-c_dc[d]) * (1.0f / 127.0f) * cp_s[0];
        posW_s[i] = pdx * W1l[257 * 128 + j] + pdy * W1l[258 * 128 + j];
    }
    for (int i = tid; i < 128 * 32; i += 512) {
        int c = i >> 5, q = i & 31;
        ((float4*)(A_s + c * 132))[q] =
            ((const float4*)(g_A + (size_t)(n0 + c) * 128))[q];
    }
    for (int i = tid; i < 128 * 32; i += 512)
        ((float4*)W_s)[i] = ((const float4*)(msg2W + (size_t)l * 128 * 128))[i];
    __syncthreads();

    const int tc = tid & 15, tr = tid >> 4;  // tr in [0,32)
    float agg[4][8];
    ACC_ZERO(agg);

    for (int d = 0; d < 8; ++d) {
        int dr = c_dr[d], dc = c_dc[d];
        if (r + dr < 0 || r + dr >= HH) continue;  // uniform per block
        __syncthreads();  // prior GEMM done reading M_s / du_s
        if (tid < 128) {
            int c = tid;
            int n = n0 + c;
            int nb = n + dr * WW + dc;
            nb = min(max(nb, 0), NN - 1);
            int bb = nb >> 14;
            du_s[c] = inp[b * NCH * HW + (n - b * HW)] -
                      inp[bb * NCH * HW + (nb - bb * HW)];
        }
        __syncthreads();
        for (int i = tid; i < 128 * 32; i += 512) {
            int c = i >> 5, q = i & 31;
            int nb = n0 + c + dr * WW + dc;
            nb = min(max(nb, 0), NN - 1);
            float4 bm = ((const float4*)(g_Bm + (size_t)nb * 128))[q];
            float4 ba = ((const float4*)(A_s + c * 132))[q];
            float du = du_s[c];
            const float* wu4 = wu_s + q * 4;
            const float* pw4 = posW_s + d * 128 + q * 4;
            float4 m;
            m.x = swishf(ba.x + bm.x + du * wu4[0] + pw4[0]);
            m.y = swishf(ba.y + bm.y + du * wu4[1] + pw4[1]);
            m.z = swishf(ba.z + bm.z + du * wu4[2] + pw4[2]);
            m.w = swishf(ba.w + bm.w + du * wu4[3] + pw4[3]);
            ((float4*)(M_s + c * 132))[q] = m;
        }
        __syncthreads();
        float acc[4][8];
        ACC_ZERO(acc);
        gemm128<32>(M_s, 132, W_s, 128, acc, tr, tc);
#pragma unroll
        for (int i = 0; i < 4; ++i) {
            int c = tr + 32 * i;
            int cc = c + dc;
            if (cc >= 0 && cc < WW) {
#pragma unroll
                for (int j = 0; j < 8; ++j)
                    agg[i][j] += swishf(acc[i][j] + b2m_s[tc * 8 + j]);
            }
        }
    }

    // -------- aggregation normalize, then update MLP --------
    __syncthreads();  // all GEMM reads of A_s/M_s/W_s done
    int cr = 1 + (r > 0) + (r < HH - 1);
#pragma unroll
    for (int i = 0; i < 4; ++i) {
        int c = tr + 32 * i;
        int ccnt = 1 + (c > 0) + (c < WW - 1);
        float inv = 1.0f / (float)(cr * ccnt - 1);
#pragma unroll
        for (int j = 0; j < 8; ++j)
            M_s[c * 132 + tc * 8 + j] = agg[i][j] * inv;  // agg tile
    }
    if (tid < 128) {
        float s = upd1b[l * 128 + tid];
#pragma unroll
        for (int p = 0; p < NPRM; ++p)
            s = fmaf(cp_s[p], upd1W[(size_t)l * 261 * 128 + (256 + p) * 128 + tid], s);
        pc_s[tid] = s;
        b2u_s[tid] = upd2b[l * 128 + tid];
    }
    for (int i = tid; i < 128 * 32; i += 512) {  // f tile -> A_s
        int c = i >> 5, q = i & 31;
        ((float4*)(A_s + c * 132))[q] =
            ((const float4*)(g_f + (size_t)(n0 + c) * 128))[q];
    }
    for (int i = tid; i < 128 * 32; i += 512)    // upd1_W rows 0..127 (f part)
        ((float4*)W_s)[i] = ((const float4*)(upd1W + (size_t)l * 261 * 128))[i];
    __syncthreads();

    float acc2[4][8];
    ACC_ZERO(acc2);
    gemm128<32>(A_s, 132, W_s, 128, acc2, tr, tc);
    __syncthreads();
    for (int i = tid; i < 128 * 32; i += 512)    // upd1_W rows 128..255 (agg part)
        ((float4*)W_s)[i] =
            ((const float4*)(upd1W + (size_t)l * 261 * 128 + 128 * 128))[i];
    __syncthreads();
    gemm128<32>(M_s, 132, W_s, 128, acc2, tr, tc);
    __syncthreads();  // done reading M_s / W_s
#pragma unroll
    for (int i = 0; i < 4; ++i) {
        int c = tr + 32 * i;
#pragma unroll
        for (int j = 0; j < 8; ++j)
            M_s[c * 132 + tc * 8 + j] = swishf(acc2[i][j] + pc_s[tc * 8 + j]);
    }
    for (int i = tid; i < 128 * 32; i += 512)    // upd2_W
        ((float4*)W_s)[i] = ((const float4*)(upd2W + (size_t)l * 128 * 128))[i];
    __syncthreads();

    float acc3[4][8];
    ACC_ZERO(acc3);
    gemm128<32>(M_s, 132, W_s, 128, acc3, tr, tc);

    float val[4][8];
#pragma unroll
    for (int i = 0; i < 4; ++i) {
        int c = tr + 32 * i;
#pragma unroll
        for (int j = 0; j < 8; ++j)
            val[i][j] = A_s[c * 132 + tc * 8 + j] +
                        swishf(acc3[i][j] + b2u_s[tc * 8 + j]);
        float* gp = g_tmp + (size_t)(n0 + c) * 128 + tc * 8;
        ((float4*)gp)[0] = make_float4(val[i][0], val[i][1], val[i][2], val[i][3]);
        ((float4*)gp)[1] = make_float4(val[i][4], val[i][5], val[i][6], val[i][7]);
    }

    // -------- layernorm stats (sum, sumsq per (batch, channel)) --------
    __syncthreads();  // reuse M_s / A_s as reduction buffers
    float s1[8], s2[8];
#pragma unroll
    for (int j = 0; j < 8; ++j) { s1[j] = 0.0f; s2[j] = 0.0f; }
#pragma unroll
    for (int i = 0; i < 4; ++i)
#pragma unroll
        for (int j = 0; j < 8; ++j) {
            s1[j] += val[i][j];
            s2[j] += val[i][j] * val[i][j];
        }
#pragma unroll
    for (int j = 0; j < 8; ++j) {
        M_s[tr * 132 + tc * 8 + j] = s1[j];
        A_s[tr * 132 + tc * 8 + j] = s2[j];
    }
    __syncthreads();
    if (tid < 128) {
        float S = 0.0f, S2 = 0.0f;
#pragma unroll 8
        for (int g = 0; g < 32; ++g) {
            S += M_s[g * 132 + tid];
            S2 += A_s[g * 132 + tid];
        }
        atomicAdd(&g_stats[b * 2 * HID + tid], S);
        atomicAdd(&g_stats[b * 2 * HID + HID + tid], S2);
    }
}

// ---------------- layernorm apply: f = (tmp - mean) * rsqrt(var + eps) ------
__global__ __launch_bounds__(256) void k_norm() {
    __shared__ float mean_s[HID], rstd_s[HID];
    int b = blockIdx.x >> 9;  // 512 blocks per batch
    if (threadIdx.x < 128) {
        float m = g_stats[b * 2 * HID + threadIdx.x] * (1.0f / (float)HW);
        float v = g_stats[b * 2 * HID + HID + threadIdx.x] * (1.0f / (float)HW) - m * m;
        mean_s[threadIdx.x] = m;
        rstd_s[threadIdx.x] = rsqrtf(v + EPSV);
    }
    __syncthreads();
    size_t base = (size_t)blockIdx.x * 1024;
#pragma unroll
    for (int k = 0; k < 4; ++k) {
        size_t i4 = base + threadIdx.x + k * 256;
        int j = ((int)(i4 & 31)) * 4;
        float4 v = ((const float4*)g_tmp)[i4];
        v.x = (v.x - mean_s[j + 0]) * rstd_s[j + 0];
        v.y = (v.y - mean_s[j + 1]) * rstd_s[j + 1];
        v.z = (v.z - mean_s[j + 2]) * rstd_s[j + 2];
        v.w = (v.w - mean_s[j + 3]) * rstd_s[j + 3];
        ((float4*)g_f)[i4] = v;
    }
}

// ---------------- output head: out = u + DT * (swish(f@W1+b1)@W2 + b2) ------
__global__ __launch_bounds__(256, 2) void k_out(
    const float* __restrict__ inp, const float* __restrict__ W1,
    const float* __restrict__ b1, const float* __restrict__ W2,
    const float* __restrict__ b2, float* __restrict__ out) {
    extern __shared__ float sm[];
    float* f_s = sm;                   // 128*132
    float* W1_s = f_s + 128 * 132;     // 128*64
    float* b1_s = W1_s + 128 * 64;     // 64
    float* W2_s = b1_s + 64;           // 64
    float* red_s = W2_s + 64;          // 128*8

    int tid = threadIdx.x;
    int n0 = blockIdx.x * 128;
    int b = n0 / HW;

    for (int i = tid; i < 128 * 32; i += 256) {
        int c = i >> 5, q = i & 31;
        ((float4*)(f_s + c * 132))[q] =
            ((const float4*)(g_f + (size_t)(n0 + c) * 128))[q];
    }
    for (int i = tid; i < 128 * 16; i += 256)
        ((float4*)W1_s)[i] = ((const float4*)W1)[i];
    if (tid < 64) { b1_s[tid] = b1[tid]; W2_s[tid] = W2[tid]; }
    __syncthreads();

    int tc = tid & 7, tr = tid >> 3;  // tr in [0,32)
    float acc[4][8];
    ACC_ZERO(acc);
    gemm128<32>(f_s, 132, W1_s, 64, acc, tr, tc);
#pragma unroll
    for (int i = 0; i < 4; ++i) {
        float p = 0.0f;
#pragma unroll
        for (int j = 0; j < 8; ++j)
            p += swishf(acc[i][j] + b1_s[tc * 8 + j]) * W2_s[tc * 8 + j];
        red_s[(tr + 32 * i) * 8 + tc] = p;
    }
    __syncthreads();
    if (tid < 128) {
        float d = b2[0];
#pragma unroll
        for (int t = 0; t < 8; ++t) d += red_s[tid * 8 + t];
        int n = n0 + tid;
        out[n] = inp[b * NCH * HW + (n - b * HW)] + DTV * d;
    }
}

// ---------------- host launcher ----------------
extern "C" void kernel_launch(void* const* d_in, const int* in_sizes, int n_in,
                              void* d_out, int out_size) {
    const float* inp   = (const float*)d_in[0];
    const float* cp    = (const float*)d_in[1];
    // d_in[2] = edge_index (unused; graph is a structured 8-neighborhood stencil)
    const float* embW1 = (const float*)d_in[3];
    const float* embb1 = (const float*)d_in[4];
    const float* embW2 = (const float*)d_in[5];
    const float* embb2 = (const float*)d_in[6];
    const float* msg1W = (const float*)d_in[7];
    const float* msg1b = (const float*)d_in[8];
    const float* msg2W = (const float*)d_in[9];
    const float* msg2b = (const float*)d_in[10];
    const float* upd1W = (const float*)d_in[11];
    const float* upd1b = (const float*)d_in[12];
    const float* upd2W = (const float*)d_in[13];
    const float* upd2b = (const float*)d_in[14];
    const float* outW1 = (const float*)d_in[15];
    const float* outb1 = (const float*)d_in[16];
    const float* outW2 = (const float*)d_in[17];
    const float* outb2 = (const float*)d_in[18];
    float* out = (float*)d_out;

    const size_t smE = (size_t)(64 * 8 + 8 * 128 + 128 + 64 * 132 + 128 * 128 + 128) * 4;
    const size_t smA = (size_t)(64 * 132 + 128 * 128 + 128) * 4;
    const size_t smEdge = (size_t)(2 * 128 * 132 + 128 * 128 + 8 * 128 + 5 * 128 + 8) * 4;
    const size_t smO = (size_t)(128 * 132 + 128 * 64 + 64 + 64 + 128 * 8) * 4;

    cudaFuncSetAttribute(k_embed, cudaFuncAttributeMaxDynamicSharedMemorySize, (int)smE);
    cudaFuncSetAttribute(k_msgA, cudaFuncAttributeMaxDynamicSharedMemorySize, (int)smA);
    cudaFuncSetAttribute(k_edge, cudaFuncAttributeMaxDynamicSharedMemorySize, (int)smEdge);
    cudaFuncSetAttribute(k_out, cudaFuncAttributeMaxDynamicSharedMemorySize, (int)smO);

    k_embed<<<NN / 64, 256, smE>>>(inp, cp, embW1, embb1, embW2, embb2);
    for (int l = 0; l < NL; ++l) {
        k_msgA<<<NN / 64, 256, smA>>>(cp, msg1W, msg1b, l);
        k_edge<<<NN / 128, 512, smEdge>>>(inp, cp, msg1W, msg2W, msg2b,
                                          upd1W, upd1b, upd2W, upd2b, l);
        k_norm<<<2048, 256>>>();
    }
    k_out<<<NN / 128, 256, smO>>>(inp, outW1, outb1, outW2, outb2, out);
}

// round 5
// speedup vs baseline: 1.5684x; 1.5684x over previous
#include <cuda_runtime.h>
#include <cuda_bf16.h>
#include <cstdint>

#define HH 128
#define WW 128
#define HW 16384
#define NN 65536
#define HID 128
#define NL 6
#define NPRM 5
#define EPSV 1e-5f
#define DTV 0.1f
#define NCH 3
#define NBATCH 4

__device__ float g_f[(size_t)NN * HID];
__device__ float g_A[(size_t)NN * HID];
__device__ float g_Bm[(size_t)NN * HID];
__device__ float g_tmp[(size_t)NN * HID];
__device__ float g_stats[NBATCH * 2 * HID];

__device__ __forceinline__ float swishf(float x) {
    return __fdividef(x, 1.0f + __expf(-x));
}
// single-MUFU swish: x*sigmoid(x) = h + h*tanh(h), h = x/2
__device__ __forceinline__ float tsw(float x) {
    float h = 0.5f * x, th;
    asm("tanh.approx.f32 %0, %1;" : "=f"(th) : "f"(h));
    return h + h * th;
}

// ---------------- tf32 split helpers ----------------
__device__ __forceinline__ uint32_t f2tf32(float x) {
    uint32_t r;
    asm("cvt.rna.tf32.f32 %0, %1;" : "=r"(r) : "f"(x));
    return r;
}
// pack (lo0 -> low half, lo1 -> high half)
__device__ __forceinline__ uint32_t pack_bf2(float lo0, float lo1) {
    uint32_t r;
    asm("cvt.rn.bf16x2.f32 %0, %1, %2;" : "=r"(r) : "f"(lo1), "f"(lo0));
    return r;
}
// store 4 elems (row, k0..k0+3) as tf32-hi (fp32) + bf16-lo
__device__ __forceinline__ void store_hl4(float* H, uint16_t* L, int row, int k0, float4 v) {
    uint32_t h0 = f2tf32(v.x), h1 = f2tf32(v.y), h2 = f2tf32(v.z), h3 = f2tf32(v.w);
    float f0 = __uint_as_float(h0), f1 = __uint_as_float(h1);
    float f2v = __uint_as_float(h2), f3 = __uint_as_float(h3);
    *(float4*)(H + row * 132 + k0) = make_float4(f0, f1, f2v, f3);
    *(uint2*)(L + row * 132 + k0) =
        make_uint2(pack_bf2(v.x - f0, v.y - f1), pack_bf2(v.z - f2v, v.w - f3));
}
__device__ __forceinline__ void store_hl2(float* H, uint16_t* L, int row, int col,
                                          float x, float y) {
    uint32_t h0 = f2tf32(x), h1 = f2tf32(y);
    float f0 = __uint_as_float(h0), f1 = __uint_as_float(h1);
    *(float2*)(H + row * 132 + col) = make_float2(f0, f1);
    *(uint32_t*)(L + row * 132 + col) = pack_bf2(x - f0, y - f1);
}
// load weight W[k][n] (row-major 128x128) TRANSPOSED into Wt[n][k], hi/lo split
__device__ void load_wt_hl(float* H, uint16_t* L, const float* __restrict__ W, int tid) {
    for (int i = tid; i < 16384; i += 256) {
        int n = i & 127, k = i >> 7;
        float x = W[k * 128 + n];
        uint32_t h = f2tf32(x);
        float fh = __uint_as_float(h);
        H[n * 132 + k] = fh;
        __nv_bfloat16 bb = __float2bfloat16(x - fh);
        L[n * 132 + k] = *reinterpret_cast<uint16_t*>(&bb);
    }
}

// ---------------- warp-tile 3xTF32 GEMM ----------------
__device__ __forceinline__ void mma8(float* a_, uint32_t a0, uint32_t a1, uint32_t a2,
                                     uint32_t a3, uint32_t b0, uint32_t b1) {
    asm volatile(
        "mma.sync.aligned.m16n8k8.row.col.f32.tf32.tf32.f32 "
        "{%0,%1,%2,%3},{%4,%5,%6,%7},{%8,%9},{%0,%1,%2,%3};"
        : "+f"(a_[0]), "+f"(a_[1]), "+f"(a_[2]), "+f"(a_[3])
        : "r"(a0), "r"(a1), "r"(a2), "r"(a3), "r"(b0), "r"(b1));
}
#define ZERO444(a)                                                     \
    _Pragma("unroll") for (int _i = 0; _i < 4; ++_i)                   \
        _Pragma("unroll") for (int _j = 0; _j < 4; ++_j)               \
            _Pragma("unroll") for (int _q = 0; _q < 4; ++_q) a[_i][_j][_q] = 0.0f;

// D[64x32] warp tile: rows m0+, cols n0+. A: [row][k] hi/lo; B: Wt [n][k] hi/lo.
__device__ __forceinline__ void gemm3x(const float* __restrict__ Ah,
                                       const uint16_t* __restrict__ Al,
                                       const float* __restrict__ Bh,
                                       const uint16_t* __restrict__ Bl,
                                       float acc[4][4][4], int m0, int n0, int g, int t) {
#pragma unroll 1
    for (int k0 = 0; k0 < 128; k0 += 8) {
        uint32_t ah[4][4], al[4][4], bh[4][2], bl[4][2];
#pragma unroll
        for (int mi = 0; mi < 4; ++mi) {
            const float* p = Ah + (m0 + 16 * mi + g) * 132 + k0 + t;
            ah[mi][0] = __float_as_uint(p[0]);
            ah[mi][1] = __float_as_uint(p[1056]);
            ah[mi][2] = __float_as_uint(p[4]);
            ah[mi][3] = __float_as_uint(p[1060]);
            const uint16_t* q = Al + (m0 + 16 * mi + g) * 132 + k0 + t;
            al[mi][0] = (uint32_t)q[0] << 16;
            al[mi][1] = (uint32_t)q[1056] << 16;
            al[mi][2] = (uint32_t)q[4] << 16;
            al[mi][3] = (uint32_t)q[1060] << 16;
        }
#pragma unroll
        for (int nj = 0; nj < 4; ++nj) {
            const float* p = Bh + (n0 + 8 * nj + g) * 132 + k0 + t;
            bh[nj][0] = __float_as_uint(p[0]);
            bh[nj][1] = __float_as_uint(p[4]);
            const uint16_t* q = Bl + (n0 + 8 * nj + g) * 132 + k0 + t;
            bl[nj][0] = (uint32_t)q[0] << 16;
            bl[nj][1] = (uint32_t)q[4] << 16;
        }
#pragma unroll
        for (int mi = 0; mi < 4; ++mi)
#pragma unroll
            for (int nj = 0; nj < 4; ++nj) {
                mma8(acc[mi][nj], ah[mi][0], ah[mi][1], ah[mi][2], ah[mi][3],
                     bh[nj][0], bh[nj][1]);
                mma8(acc[mi][nj], ah[mi][0], ah[mi][1], ah[mi][2], ah[mi][3],
                     bl[nj][0], bl[nj][1]);
                mma8(acc[mi][nj], al[mi][0], al[mi][1], al[mi][2], al[mi][3],
                     bh[nj][0], bh[nj][1]);
            }
    }
}

// ------------- k_msgA_mm: A = f@W_t + pc, Bm = f@W_s -------------
__global__ __launch_bounds__(256, 1) void k_msgA_mm(
    const float* __restrict__ cp, const float* __restrict__ msg1W,
    const float* __restrict__ msg1b, int l) {
    extern __shared__ char smem[];
    float* Fh = (float*)smem;                   // 67584
    float* Wh = (float*)(smem + 67584);         // 67584
    uint16_t* Fl = (uint16_t*)(smem + 135168);  // 33792
    uint16_t* Wl = (uint16_t*)(smem + 168960);  // 33792
    float* pc_s = (float*)(smem + 202752);      // 512

    const int tid = threadIdx.x, warp = tid >> 5, lane = tid & 31;
    const int g = lane >> 2, t = lane & 3;
    const int m0 = (warp >> 2) * 64, n0c = (warp & 3) * 32;
    const int nb0 = blockIdx.x << 7, b = nb0 >> 14;
    const float* Wl1 = msg1W + (size_t)l * 264 * 128;

    if (blockIdx.x == 0)
        for (int i = tid; i < NBATCH * 2 * HID; i += 256) g_stats[i] = 0.0f;
    if (tid < 128) {
        float s = msg1b[l * 128 + tid];
#pragma unroll
        for (int p = 0; p < NPRM; ++p)
            s = fmaf(cp[b * NPRM + p], Wl1[(259 + p) * 128 + tid], s);
        pc_s[tid] = s;
    }
    for (int i = tid; i < 4096; i += 256) {
        int c = i >> 5, k0 = (i & 31) * 4;
        store_hl4(Fh, Fl, c, k0, *(const float4*)(g_f + (size_t)(nb0 + c) * 128 + k0));
    }
    load_wt_hl(Wh, Wl, Wl1, tid);  // W_t rows 0..127
    __syncthreads();

    float acc[4][4][4];
    ZERO444(acc);
    gemm3x(Fh, Fl, Wh, Wl, acc, m0, n0c, g, t);
#pragma unroll
    for (int mi = 0; mi < 4; ++mi) {
        int c0 = m0 + 16 * mi + g;
#pragma unroll
        for (int nj = 0; nj < 4; ++nj) {
            int col = n0c + 8 * nj + 2 * t;
            *(float2*)(g_A + (size_t)(nb0 + c0) * 128 + col) =
                make_float2(acc[mi][nj][0] + pc_s[col], acc[mi][nj][1] + pc_s[col + 1]);
            *(float2*)(g_A + (size_t)(nb0 + c0 + 8) * 128 + col) =
                make_float2(acc[mi][nj][2] + pc_s[col], acc[mi][nj][3] + pc_s[col + 1]);
        }
    }
    __syncthreads();
    load_wt_hl(Wh, Wl, Wl1 + 128 * 128, tid);  // W_s rows 128..255
    __syncthreads();
    ZERO444(acc);
    gemm3x(Fh, Fl, Wh, Wl, acc, m0, n0c, g, t);
#pragma unroll
    for (int mi = 0; mi < 4; ++mi) {
        int c0 = m0 + 16 * mi + g;
#pragma unroll
        for (int nj = 0; nj < 4; ++nj) {
            int col = n0c + 8 * nj + 2 * t;
            *(float2*)(g_Bm + (size_t)(nb0 + c0) * 128 + col) =
                make_float2(acc[mi][nj][0], acc[mi][nj][1]);
            *(float2*)(g_Bm + (size_t)(nb0 + c0 + 8) * 128 + col) =
                make_float2(acc[mi][nj][2], acc[mi][nj][3]);
        }
    }
}

// ------------- k_edge_mm: messages + agg + update MLP -------------
__global__ __launch_bounds__(256, 1) void k_edge_mm(
    const float* __restrict__ inp, const float* __restrict__ cp,
    const float* __restrict__ msg1W, const float* __restrict__ msg2W,
    const float* __restrict__ msg2b, const float* __restrict__ upd1W,
    const float* __restrict__ upd1b, const float* __restrict__ upd2W,
    const float* __restrict__ upd2b, int l) {
    extern __shared__ char smem[];
    float* Mh = (float*)smem;                   // 67584
    float* Wh = (float*)(smem + 67584);         // 67584
    uint16_t* Ml = (uint16_t*)(smem + 135168);  // 33792
    uint16_t* Wl = (uint16_t*)(smem + 168960);  // 33792
    float* posW = (float*)(smem + 202752);      // 4096
    float* wu_s = (float*)(smem + 206848);
    float* b2m_s = (float*)(smem + 207360);
    float* pcu_s = (float*)(smem + 207872);
    float* b2u_s = (float*)(smem + 208384);
    float* du_s = (float*)(smem + 208896);
    float* cp_s = (float*)(smem + 209408);

    const int tid = threadIdx.x, warp = tid >> 5, lane = tid & 31;
    const int g = lane >> 2, t = lane & 3;
    const int m0 = (warp >> 2) * 64, n0c = (warp & 3) * 32;
    const int gr = blockIdx.x, b = gr >> 7, r = gr & 127, nb0 = gr << 7;
    const float* W1l = msg1W + (size_t)l * 264 * 128;
    const int DR[8] = {-1, -1, -1, 0, 0, 1, 1, 1};
    const int DC[8] = {-1, 0, 1, -1, 1, -1, 0, 1};

    if (tid < 8) cp_s[tid] = (tid < NPRM) ? cp[b * NPRM + tid] : 0.0f;
    if (tid < 128) {
        wu_s[tid] = W1l[256 * 128 + tid];
        b2m_s[tid] = msg2b[l * 128 + tid];
    }
    __syncthreads();
    for (int i = tid; i < 1024; i += 256) {
        int d = i >> 7, j = i & 127;
        posW[i] = (float)(-DR[d]) * (1.0f / 127.0f) * cp_s[1] * W1l[257 * 128 + j] +
                  (float)(-DC[d]) * (1.0f / 127.0f) * cp_s[0] * W1l[258 * 128 + j];
    }
    load_wt_hl(Wh, Wl, msg2W + (size_t)l * 16384, tid);

    float agg[4][4][4];
    ZERO444(agg);

#pragma unroll 1
    for (int d = 0; d < 8; ++d) {
        const int dr = DR[d], dc = DC[d];
        if ((unsigned)(r + dr) >= (unsigned)HH) continue;
        __syncthreads();  // prior gemm reads done (first iter: W/posW writes done)
        if (tid < 128) {
            int n = nb0 + tid, nb = n + dr * WW + dc;
            nb = min(max(nb, 0), NN - 1);
            int bb = nb >> 14;
            du_s[tid] = inp[b * NCH * HW + (n - b * HW)] -
                        inp[bb * NCH * HW + (nb - bb * HW)];
        }
        __syncthreads();
        for (int i = tid; i < 4096; i += 256) {
            int c = i >> 5, k0 = (i & 31) * 4;
            int nb = nb0 + c + dr * WW + dc;
            nb = min(max(nb, 0), NN - 1);
            float4 bm = *(const float4*)(g_Bm + (size_t)nb * 128 + k0);
            float4 aa = *(const float4*)(g_A + (size_t)(nb0 + c) * 128 + k0);
            float du = du_s[c];
            float4 v;
            v.x = tsw(aa.x + bm.x + du * wu_s[k0 + 0] + posW[d * 128 + k0 + 0]);
            v.y = tsw(aa.y + bm.y + du * wu_s[k0 + 1] + posW[d * 128 + k0 + 1]);
            v.z = tsw(aa.z + bm.z + du * wu_s[k0 + 2] + posW[d * 128 + k0 + 2]);
            v.w = tsw(aa.w + bm.w + du * wu_s[k0 + 3] + posW[d * 128 + k0 + 3]);
            store_hl4(Mh, Ml, c, k0, v);
        }
        __syncthreads();
        float acc[4][4][4];
        ZERO444(acc);
        gemm3x(Mh, Ml, Wh, Wl, acc, m0, n0c, g, t);
#pragma unroll
        for (int mi = 0; mi < 4; ++mi) {
            int c0 = m0 + 16 * mi + g;
            bool ok0 = (unsigned)(c0 + dc) < (unsigned)WW;
            bool ok1 = (unsigned)(c0 + 8 + dc) < (unsigned)WW;
#pragma unroll
            for (int nj = 0; nj < 4; ++nj) {
                int col = n0c + 8 * nj + 2 * t;
                float bb0 = b2m_s[col], bb1 = b2m_s[col + 1];
                if (ok0) {
                    agg[mi][nj][0] += tsw(acc[mi][nj][0] + bb0);
                    agg[mi][nj][1] += tsw(acc[mi][nj][1] + bb1);
                }
                if (ok1) {
                    agg[mi][nj][2] += tsw(acc[mi][nj][2] + bb0);
                    agg[mi][nj][3] += tsw(acc[mi][nj][3] + bb1);
                }
            }
        }
    }
    __syncthreads();  // last gemm done; M/W reusable

    // -------- update MLP --------
    const float* U1 = upd1W + (size_t)l * 261 * 128;
    {
        int crn = 1 + (r > 0) + (r < HH - 1);
#pragma unroll
        for (int mi = 0; mi < 4; ++mi) {
            int c0 = m0 + 16 * mi + g;
            float inv0 = 1.0f / (float)(crn * (1 + (c0 > 0) + (c0 < WW - 1)) - 1);
            float inv1 = 1.0f / (float)(crn * (2 + (c0 + 8 < WW - 1)) - 1);
#pragma unroll
            for (int nj = 0; nj < 4; ++nj) {
                int col = n0c + 8 * nj + 2 * t;
                store_hl2(Mh, Ml, c0, col, agg[mi][nj][0] * inv0, agg[mi][nj][1] * inv0);
                store_hl2(Mh, Ml, c0 + 8, col, agg[mi][nj][2] * inv1, agg[mi][nj][3] * inv1);
            }
        }
    }
    load_wt_hl(Wh, Wl, U1 + 128 * 128, tid);  // U1 agg rows
    if (tid < 128) {
        float s = upd1b[l * 128 + tid];
#pragma unroll
        for (int p = 0; p < NPRM; ++p)
            s = fmaf(cp_s[p], U1[(256 + p) * 128 + tid], s);
        pcu_s[tid] = s;
        b2u_s[tid] = upd2b[l * 128 + tid];
    }
    __syncthreads();
    float acc2[4][4][4];
    ZERO444(acc2);
    gemm3x(Mh, Ml, Wh, Wl, acc2, m0, n0c, g, t);
    __syncthreads();
    for (int i = tid; i < 4096; i += 256) {  // f -> M
        int c = i >> 5, k0 = (i & 31) * 4;
        store_hl4(Mh, Ml, c, k0, *(const float4*)(g_f + (size_t)(nb0 + c) * 128 + k0));
    }
    load_wt_hl(Wh, Wl, U1, tid);  // U1 f rows
    __syncthreads();
    gemm3x(Mh, Ml, Wh, Wl, acc2, m0, n0c, g, t);  // accumulate
    __syncthreads();
#pragma unroll
    for (int mi = 0; mi < 4; ++mi) {  // h1 = swish(acc2 + pcu) -> M
        int c0 = m0 + 16 * mi + g;
#pragma unroll
        for (int nj = 0; nj < 4; ++nj) {
            int col = n0c + 8 * nj + 2 * t;
            store_hl2(Mh, Ml, c0, col, tsw(acc2[mi][nj][0] + pcu_s[col]),
                      tsw(acc2[mi][nj][1] + pcu_s[col + 1]));
            store_hl2(Mh, Ml, c0 + 8, col, tsw(acc2[mi][nj][2] + pcu_s[col]),
                      tsw(acc2[mi][nj][3] + pcu_s[col + 1]));
        }
    }
    load_wt_hl(Wh, Wl, upd2W + (size_t)l * 16384, tid);  // U2
    __syncthreads();
    float acc3[4][4][4];
    ZERO444(acc3);
    gemm3x(Mh, Ml, Wh, Wl, acc3, m0, n0c, g, t);
    __syncthreads();

    // -------- residual + stores + layernorm stats --------
    float* stage = Mh;  // reuse as fp32 [128][132]
#pragma unroll
    for (int mi = 0; mi < 4; ++mi) {
#pragma unroll
        for (int half = 0; half < 2; ++half) {
            int c0 = m0 + 16 * mi + g + 8 * half;
#pragma unroll
            for (int nj = 0; nj < 4; ++nj) {
                int col = n0c + 8 * nj + 2 * t;
                float2 f2 = *(const float2*)(g_f + (size_t)(nb0 + c0) * 128 + col);
                float v0 = f2.x + tsw(acc3[mi][nj][2 * half + 0] + b2u_s[col]);
                float v1 = f2.y + tsw(acc3[mi][nj][2 * half + 1] + b2u_s[col + 1]);
                *(float2*)(g_tmp + (size_t)(nb0 + c0) * 128 + col) = make_float2(v0, v1);
                *(float2*)(stage + c0 * 132 + col) = make_float2(v0, v1);
            }
        }
    }
    __syncthreads();
    if (tid < 128) {
        float S = 0.0f, S2 = 0.0f;
#pragma unroll 4
        for (int gg = 0; gg < 128; ++gg) {
            float v = stage[gg * 132 + tid];
            S += v;
            S2 += v * v;
        }
        atomicAdd(&g_stats[b * 2 * HID + tid], S);
        atomicAdd(&g_stats[b * 2 * HID + HID + tid], S2);
    }
}

// ================= fp32 kernels (unchanged, passing) =================
#define ACC_ZERO(acc)                                                  \
    _Pragma("unroll") for (int _i = 0; _i < 4; ++_i)                   \
        _Pragma("unroll") for (int _j = 0; _j < 8; ++_j) acc[_i][_j] = 0.0f;

template <int RSTEP>
__device__ __forceinline__ void gemm128(const float* __restrict__ As, int lda,
                                        const float* __restrict__ Ws, int ldw,
                                        float acc[4][8], int tr, int tc) {
#pragma unroll 4
    for (int k4 = 0; k4 < 32; ++k4) {
        float4 a[4];
#pragma unroll
        for (int i = 0; i < 4; ++i)
            a[i] = *(const float4*)(As + (tr + i * RSTEP) * lda + k4 * 4);
        const float* wp = Ws + (k4 * 4) * ldw + tc * 8;
#pragma unroll
        for (int kk = 0; kk < 4; ++kk) {
            float4 b0 = *(const float4*)(wp + kk * ldw);
            float4 b1 = *(const float4*)(wp + kk * ldw + 4);
#pragma unroll
            for (int i = 0; i < 4; ++i) {
                float av = ((const float*)(a + i))[kk];
                acc[i][0] = fmaf(av, b0.x, acc[i][0]);
                acc[i][1] = fmaf(av, b0.y, acc[i][1]);
                acc[i][2] = fmaf(av, b0.z, acc[i][2]);
                acc[i][3] = fmaf(av, b0.w, acc[i][3]);
                acc[i][4] = fmaf(av, b1.x, acc[i][4]);
                acc[i][5] = fmaf(av, b1.y, acc[i][5]);
                acc[i][6] = fmaf(av, b1.z, acc[i][6]);
                acc[i][7] = fmaf(av, b1.w, acc[i][7]);
            }
        }
    }
}

__global__ __launch_bounds__(256, 2) void k_embed(
    const float* __restrict__ inp, const float* __restrict__ cp,
    const float* __restrict__ W1, const float* __restrict__ b1,
    const float* __restrict__ W2, const float* __restrict__ b2) {
    extern __shared__ float sm[];
    float* e_s = sm;
    float* W1_s = e_s + 64 * 8;
    float* b1_s = W1_s + 8 * 128;
    float* h1_s = b1_s + 128;
    float* W2_s = h1_s + 64 * 132;
    float* b2_s = W2_s + 128 * 128;
    int tid = threadIdx.x;
    int n0 = blockIdx.x * 64, b = n0 / HW;
    for (int i = tid; i < 8 * 128; i += 256) W1_s[i] = W1[i];
    if (tid < 128) { b1_s[tid] = b1[tid]; b2_s[tid] = b2[tid]; }
    for (int i = tid; i < 128 * 32; i += 256)
        ((float4*)W2_s)[i] = ((const float4*)W2)[i];
    if (tid < 64) {
        int n = n0 + tid, rc = n - b * HW;
        int r = rc >> 7, c = rc & 127;
        e_s[tid * 8 + 0] = inp[b * NCH * HW + rc];
        e_s[tid * 8 + 1] = (float)r * (1.0f / 127.0f) * cp[b * NPRM + 1];
        e_s[tid * 8 + 2] = (float)c * (1.0f / 127.0f) * cp[b * NPRM + 0];
#pragma unroll
        for (int p = 0; p < NPRM; ++p) e_s[tid * 8 + 3 + p] = cp[b * NPRM + p];
    }
    __syncthreads();
    int tc = tid & 15, tr = tid >> 4;
#pragma unroll
    for (int i = 0; i < 4; ++i) {
        int row = tr + 16 * i;
#pragma unroll
        for (int j = 0; j < 8; ++j) {
            float s = b1_s[tc * 8 + j];
#pragma unroll
            for (int k = 0; k < 8; ++k)
                s = fmaf(e_s[row * 8 + k], W1_s[k * 128 + tc * 8 + j], s);
            h1_s[row * 132 + tc * 8 + j] = swishf(s);
        }
    }
    __syncthreads();
    float acc[4][8];
    ACC_ZERO(acc);
    gemm128<16>(h1_s, 132, W2_s, 128, acc, tr, tc);
#pragma unroll
    for (int i = 0; i < 4; ++i) {
        int row = tr + 16 * i;
#pragma unroll
        for (int j = 0; j < 8; ++j)
            g_f[(size_t)(n0 + row) * 128 + tc * 8 + j] =
                swishf(acc[i][j] + b2_s[tc * 8 + j]);
    }
}

__global__ __launch_bounds__(256) void k_norm() {
    __shared__ float mean_s[HID], rstd_s[HID];
    int b = blockIdx.x >> 9;
    if (threadIdx.x < 128) {
        float m = g_stats[b * 2 * HID + threadIdx.x] * (1.0f / (float)HW);
        float v = g_stats[b * 2 * HID + HID + threadIdx.x] * (1.0f / (float)HW) - m * m;
        mean_s[threadIdx.x] = m;
        rstd_s[threadIdx.x] = rsqrtf(v + EPSV);
    }
    __syncthreads();
    size_t base = (size_t)blockIdx.x * 1024;
#pragma unroll
    for (int k = 0; k < 4; ++k) {
        size_t i4 = base + threadIdx.x + k * 256;
        int j = ((int)(i4 & 31)) * 4;
        float4 v = ((const float4*)g_tmp)[i4];
        v.x = (v.x - mean_s[j + 0]) * rstd_s[j + 0];
        v.y = (v.y - mean_s[j + 1]) * rstd_s[j + 1];
        v.z = (v.z - mean_s[j + 2]) * rstd_s[j + 2];
        v.w = (v.w - mean_s[j + 3]) * rstd_s[j + 3];
        ((float4*)g_f)[i4] = v;
    }
}

__global__ __launch_bounds__(256, 2) void k_out(
    const float* __restrict__ inp, const float* __restrict__ W1,
    const float* __restrict__ b1, const float* __restrict__ W2,
    const float* __restrict__ b2, float* __restrict__ out) {
    extern __shared__ float sm[];
    float* f_s = sm;
    float* W1_s = f_s + 128 * 132;
    float* b1_s = W1_s + 128 * 64;
    float* W2_s = b1_s + 64;
    float* red_s = W2_s + 64;
    int tid = threadIdx.x;
    int n0 = blockIdx.x * 128, b = n0 / HW;
    for (int i = tid; i < 128 * 32; i += 256) {
        int c = i >> 5, q = i & 31;
        ((float4*)(f_s + c * 132))[q] = ((const float4*)(g_f + (size_t)(n0 + c) * 128))[q];
    }
    for (int i = tid; i < 128 * 16; i += 256)
        ((float4*)W1_s)[i] = ((const float4*)W1)[i];
    if (tid < 64) { b1_s[tid] = b1[tid]; W2_s[tid] = W2[tid]; }
    __syncthreads();
    int tc = tid & 7, tr = tid >> 3;
    float acc[4][8];
    ACC_ZERO(acc);
    gemm128<32>(f_s, 132, W1_s, 64, acc, tr, tc);
#pragma unroll
    for (int i = 0; i < 4; ++i) {
        float p = 0.0f;
#pragma unroll
        for (int j = 0; j < 8; ++j)
            p += swishf(acc[i][j] + b1_s[tc * 8 + j]) * W2_s[tc * 8 + j];
        red_s[(tr + 32 * i) * 8 + tc] = p;
    }
    __syncthreads();
    if (tid < 128) {
        float d = b2[0];
#pragma unroll
        for (int t = 0; t < 8; ++t) d += red_s[tid * 8 + t];
        int n = n0 + tid;
        out[n] = inp[b * NCH * HW + (n - b * HW)] + DTV * d;
    }
}

// ---------------- host launcher ----------------
extern "C" void kernel_launch(void* const* d_in, const int* in_sizes, int n_in,
                              void* d_out, int out_size) {
    const float* inp   = (const float*)d_in[0];
    const float* cp    = (const float*)d_in[1];
    const float* embW1 = (const float*)d_in[3];
    const float* embb1 = (const float*)d_in[4];
    const float* embW2 = (const float*)d_in[5];
    const float* embb2 = (const float*)d_in[6];
    const float* msg1W = (const float*)d_in[7];
    const float* msg1b = (const float*)d_in[8];
    const float* msg2W = (const float*)d_in[9];
    const float* msg2b = (const float*)d_in[10];
    const float* upd1W = (const float*)d_in[11];
    const float* upd1b = (const float*)d_in[12];
    const float* upd2W = (const float*)d_in[13];
    const float* upd2b = (const float*)d_in[14];
    const float* outW1 = (const float*)d_in[15];
    const float* outb1 = (const float*)d_in[16];
    const float* outW2 = (const float*)d_in[17];
    const float* outb2 = (const float*)d_in[18];
    float* out = (float*)d_out;

    const size_t smE = (size_t)(64 * 8 + 8 * 128 + 128 + 64 * 132 + 128 * 128 + 128) * 4;
    const size_t smO = (size_t)(128 * 132 + 128 * 64 + 64 + 64 + 128 * 8) * 4;
    const size_t smMA = 203264;
    const size_t smEG = 209440;

    cudaFuncSetAttribute(k_embed, cudaFuncAttributeMaxDynamicSharedMemorySize, (int)smE);
    cudaFuncSetAttribute(k_out, cudaFuncAttributeMaxDynamicSharedMemorySize, (int)smO);
    cudaFuncSetAttribute(k_msgA_mm, cudaFuncAttributeMaxDynamicSharedMemorySize, (int)smMA);
    cudaFuncSetAttribute(k_edge_mm, cudaFuncAttributeMaxDynamicSharedMemorySize, (int)smEG);

    k_embed<<<NN / 64, 256, smE>>>(inp, cp, embW1, embb1, embW2, embb2);
    for (int l = 0; l < NL; ++l) {
        k_msgA_mm<<<NN / 128, 256, smMA>>>(cp, msg1W, msg1b, l);
        k_edge_mm<<<NN / 128, 256, smEG>>>(inp, cp, msg1W, msg2W, msg2b,
                                           upd1W, upd1b, upd2W, upd2b, l);
        k_norm<<<2048, 256>>>();
    }
    k_out<<<NN / 128, 256, smO>>>(inp, outW1, outb1, outW2, outb2, out);
}

// round 6
// speedup vs baseline: 2.1548x; 1.3739x over previous
#include <cuda_runtime.h>
#include <cuda_fp16.h>
#include <cstdint>

#define HH 128
#define WW 128
#define HW 16384
#define NN 65536
#define HID 128
#define NL 6
#define NPRM 5
#define EPSV 1e-5f
#define DTV 0.1f
#define NCH 3
#define NBATCH 4
#define PSTRIDE 68  // half2-words per row of an operand plane (conflict-free)

__device__ float g_f[(size_t)NN * HID];
__device__ float g_A[(size_t)NN * HID];
__device__ float g_Bm[(size_t)NN * HID];
__device__ float g_tmp[(size_t)NN * HID];
__device__ float g_stats[NBATCH * 2 * HID];

__device__ __forceinline__ float swishf(float x) {
    return __fdividef(x, 1.0f + __expf(-x));
}
// single-MUFU swish: x*sigmoid(x) = h + h*tanh(h), h = x/2
__device__ __forceinline__ float tsw(float x) {
    float h = 0.5f * x, th;
    asm("tanh.approx.f32 %0, %1;" : "=f"(th) : "f"(h));
    return h + h * th;
}
__device__ __forceinline__ uint32_t h2u(__half2 h) {
    return *reinterpret_cast<uint32_t*>(&h);
}

// store 4 elems (row, k0..k0+3), k0 % 4 == 0, into hi/lo fp16 planes
__device__ __forceinline__ void store_hl4(uint32_t* H, uint32_t* L, int row, int k0,
                                          float4 v) {
    __half2 h01 = __floats2half2_rn(v.x, v.y);
    __half2 h23 = __floats2half2_rn(v.z, v.w);
    __half2 l01 = __floats2half2_rn(v.x - __low2float(h01), v.y - __high2float(h01));
    __half2 l23 = __floats2half2_rn(v.z - __low2float(h23), v.w - __high2float(h23));
    int idx = row * PSTRIDE + (k0 >> 1);
    *(uint2*)(H + idx) = make_uint2(h2u(h01), h2u(h23));
    *(uint2*)(L + idx) = make_uint2(h2u(l01), h2u(l23));
}
// store 2 elems at even col
__device__ __forceinline__ void store_hl2(uint32_t* H, uint32_t* L, int row, int col,
                                          float x, float y) {
    __half2 hh = __floats2half2_rn(x, y);
    __half2 ll = __floats2half2_rn(x - __low2float(hh), y - __high2float(hh));
    int idx = row * PSTRIDE + (col >> 1);
    H[idx] = h2u(hh);
    L[idx] = h2u(ll);
}
// load weight W[k][n] (row-major 128x128) TRANSPOSED into planes Wt[n][k]
__device__ void load_wt_hl(uint32_t* Hw, uint32_t* Lw, const float* __restrict__ W,
                           int tid) {
    __half* H = (__half*)Hw;
    __half* L = (__half*)Lw;
    for (int i = tid; i < 16384; i += 256) {
        int n = i & 127, k = i >> 7;
        float x = W[k * 128 + n];
        __half h = __float2half_rn(x);
        H[n * (2 * PSTRIDE) + k] = h;
        L[n * (2 * PSTRIDE) + k] = __float2half_rn(x - __half2float(h));
    }
}

// ---------------- fp16-split warp-tile GEMM (m16n8k16) ----------------
__device__ __forceinline__ void hmma(float* a_, uint32_t a0, uint32_t a1, uint32_t a2,
                                     uint32_t a3, uint32_t b0, uint32_t b1) {
    asm volatile(
        "mma.sync.aligned.m16n8k16.row.col.f32.f16.f16.f32 "
        "{%0,%1,%2,%3},{%4,%5,%6,%7},{%8,%9},{%0,%1,%2,%3};"
        : "+f"(a_[0]), "+f"(a_[1]), "+f"(a_[2]), "+f"(a_[3])
        : "r"(a0), "r"(a1), "r"(a2), "r"(a3), "r"(b0), "r"(b1));
}
#define ZERO444(a)                                                     \
    _Pragma("unroll") for (int _i = 0; _i < 4; ++_i)                   \
        _Pragma("unroll") for (int _j = 0; _j < 4; ++_j)               \
            _Pragma("unroll") for (int _q = 0; _q < 4; ++_q) a[_i][_j][_q] = 0.0f;

// D[64x32] per warp: rows m0+, cols n0c+. A planes [row][k], B planes Wt[n][k].
__device__ __forceinline__ void gemmh(const uint32_t* __restrict__ Ah,
                                      const uint32_t* __restrict__ Al,
                                      const uint32_t* __restrict__ Bh,
                                      const uint32_t* __restrict__ Bl,
                                      float acc[4][4][4], int m0, int n0c, int g, int t) {
#pragma unroll 1
    for (int s = 0; s < 8; ++s) {
        const int kb = s * 8 + t;
        uint32_t bh[4][2], bl[4][2];
#pragma unroll
        for (int nj = 0; nj < 4; ++nj) {
            const uint32_t* p = Bh + (n0c + 8 * nj + g) * PSTRIDE + kb;
            bh[nj][0] = p[0];
            bh[nj][1] = p[4];
            const uint32_t* q = Bl + (n0c + 8 * nj + g) * PSTRIDE + kb;
            bl[nj][0] = q[0];
            bl[nj][1] = q[4];
        }
#pragma unroll
        for (int mi = 0; mi < 4; ++mi) {
            const uint32_t* p = Ah + (m0 + 16 * mi + g) * PSTRIDE + kb;
            uint32_t a0 = p[0], a1 = p[8 * PSTRIDE], a2 = p[4], a3 = p[8 * PSTRIDE + 4];
            const uint32_t* q = Al + (m0 + 16 * mi + g) * PSTRIDE + kb;
            uint32_t c0 = q[0], c1 = q[8 * PSTRIDE], c2 = q[4], c3 = q[8 * PSTRIDE + 4];
#pragma unroll
            for (int nj = 0; nj < 4; ++nj) {
                hmma(acc[mi][nj], a0, a1, a2, a3, bh[nj][0], bh[nj][1]);
                hmma(acc[mi][nj], a0, a1, a2, a3, bl[nj][0], bl[nj][1]);
                hmma(acc[mi][nj], c0, c1, c2, c3, bh[nj][0], bh[nj][1]);
            }
        }
    }
}

// ------------- k_msgA_mm: A = f@W_t + pc, Bm = f@W_s -------------
__global__ __launch_bounds__(256, 1) void k_msgA_mm(
    const float* __restrict__ cp, const float* __restrict__ msg1W,
    const float* __restrict__ msg1b, int l) {
    extern __shared__ char smem[];
    uint32_t* Fh = (uint32_t*)smem;               // 34816
    uint32_t* Fl = (uint32_t*)(smem + 34816);     // 34816
    uint32_t* Wh = (uint32_t*)(smem + 69632);     // 34816
    uint32_t* Wl = (uint32_t*)(smem + 104448);    // 34816
    float* pc_s = (float*)(smem + 139264);        // 512

    const int tid = threadIdx.x, warp = tid >> 5, lane = tid & 31;
    const int g = lane >> 2, t = lane & 3;
    const int m0 = (warp >> 2) * 64, n0c = (warp & 3) * 32;
    const int nb0 = blockIdx.x << 7, b = nb0 >> 14;
    const float* Wl1 = msg1W + (size_t)l * 264 * 128;

    if (blockIdx.x == 0)
        for (int i = tid; i < NBATCH * 2 * HID; i += 256) g_stats[i] = 0.0f;
    if (tid < 128) {
        float s = msg1b[l * 128 + tid];
#pragma unroll
        for (int p = 0; p < NPRM; ++p)
            s = fmaf(cp[b * NPRM + p], Wl1[(259 + p) * 128 + tid], s);
        pc_s[tid] = s;
    }
    for (int i = tid; i < 4096; i += 256) {
        int c = i >> 5, k0 = (i & 31) * 4;
        store_hl4(Fh, Fl, c, k0, *(const float4*)(g_f + (size_t)(nb0 + c) * 128 + k0));
    }
    load_wt_hl(Wh, Wl, Wl1, tid);  // W_t rows 0..127
    __syncthreads();

    float acc[4][4][4];
    ZERO444(acc);
    gemmh(Fh, Fl, Wh, Wl, acc, m0, n0c, g, t);
#pragma unroll
    for (int mi = 0; mi < 4; ++mi) {
        int c0 = m0 + 16 * mi + g;
#pragma unroll
        for (int nj = 0; nj < 4; ++nj) {
            int col = n0c + 8 * nj + 2 * t;
            *(float2*)(g_A + (size_t)(nb0 + c0) * 128 + col) =
                make_float2(acc[mi][nj][0] + pc_s[col], acc[mi][nj][1] + pc_s[col + 1]);
            *(float2*)(g_A + (size_t)(nb0 + c0 + 8) * 128 + col) =
                make_float2(acc[mi][nj][2] + pc_s[col], acc[mi][nj][3] + pc_s[col + 1]);
        }
    }
    __syncthreads();
    load_wt_hl(Wh, Wl, Wl1 + 128 * 128, tid);  // W_s rows 128..255
    __syncthreads();
    ZERO444(acc);
    gemmh(Fh, Fl, Wh, Wl, acc, m0, n0c, g, t);
#pragma unroll
    for (int mi = 0; mi < 4; ++mi) {
        int c0 = m0 + 16 * mi + g;
#pragma unroll
        for (int nj = 0; nj < 4; ++nj) {
            int col = n0c + 8 * nj + 2 * t;
            *(float2*)(g_Bm + (size_t)(nb0 + c0) * 128 + col) =
                make_float2(acc[mi][nj][0], acc[mi][nj][1]);
            *(float2*)(g_Bm + (size_t)(nb0 + c0 + 8) * 128 + col) =
                make_float2(acc[mi][nj][2], acc[mi][nj][3]);
        }
    }
}

// ------------- k_edge_mm: messages + agg + update MLP -------------
__global__ __launch_bounds__(256, 1) void k_edge_mm(
    const float* __restrict__ inp, const float* __restrict__ cp,
    const float* __restrict__ msg1W, const float* __restrict__ msg2W,
    const float* __restrict__ msg2b, const float* __restrict__ upd1W,
    const float* __restrict__ upd1b, const float* __restrict__ upd2W,
    const float* __restrict__ upd2b, int l) {
    extern __shared__ char smem[];
    uint32_t* Mh = (uint32_t*)smem;               // 34816
    uint32_t* Ml = (uint32_t*)(smem + 34816);     // 34816
    uint32_t* Wh = (uint32_t*)(smem + 69632);     // 34816
    uint32_t* Wl = (uint32_t*)(smem + 104448);    // 34816
    float* Ac = (float*)(smem + 139264);          // 128*132*4 = 67584 (also stage)
    float* posW = (float*)(smem + 206848);        // 4096
    float* wu_s = (float*)(smem + 210944);
    float* b2m_s = (float*)(smem + 211456);
    float* pcu_s = (float*)(smem + 211968);
    float* b2u_s = (float*)(smem + 212480);
    float* du_s = (float*)(smem + 212992);
    float* cp_s = (float*)(smem + 213504);        // 32  -> total 213536

    const int tid = threadIdx.x, warp = tid >> 5, lane = tid & 31;
    const int g = lane >> 2, t = lane & 3;
    const int m0 = (warp >> 2) * 64, n0c = (warp & 3) * 32;
    const int gr = blockIdx.x, b = gr >> 7, r = gr & 127, nb0 = gr << 7;
    const float* W1l = msg1W + (size_t)l * 264 * 128;
    const int DR[8] = {-1, -1, -1, 0, 0, 1, 1, 1};
    const int DC[8] = {-1, 0, 1, -1, 1, -1, 0, 1};

    if (tid < 8) cp_s[tid] = (tid < NPRM) ? cp[b * NPRM + tid] : 0.0f;
    if (tid < 128) {
        wu_s[tid] = W1l[256 * 128 + tid];
        b2m_s[tid] = msg2b[l * 128 + tid];
    }
    __syncthreads();
    for (int i = tid; i < 1024; i += 256) {
        int d = i >> 7, j = i & 127;
        posW[i] = (float)(-DR[d]) * (1.0f / 127.0f) * cp_s[1] * W1l[257 * 128 + j] +
                  (float)(-DC[d]) * (1.0f / 127.0f) * cp_s[0] * W1l[258 * 128 + j];
    }
    for (int i = tid; i < 4096; i += 256) {  // cache A tile (fp32)
        int c = i >> 5, q = i & 31;
        ((float4*)(Ac + c * 132))[q] = ((const float4*)(g_A + (size_t)(nb0 + c) * 128))[q];
    }
    load_wt_hl(Wh, Wl, msg2W + (size_t)l * 16384, tid);

    float agg[4][4][4];
    ZERO444(agg);

#pragma unroll 1
    for (int d = 0; d < 8; ++d) {
        const int dr = DR[d], dc = DC[d];
        if ((unsigned)(r + dr) >= (unsigned)HH) continue;
        __syncthreads();  // prior gemm reads done (first iter: W/posW/Ac writes done)
        if (tid < 128) {
            int n = nb0 + tid, nb = n + dr * WW + dc;
            nb = min(max(nb, 0), NN - 1);
            int bb = nb >> 14;
            du_s[tid] = inp[b * NCH * HW + (n - b * HW)] -
                        inp[bb * NCH * HW + (nb - bb * HW)];
        }
        __syncthreads();
        for (int i = tid; i < 4096; i += 256) {
            int c = i >> 5, k0 = (i & 31) * 4;
            int nb = nb0 + c + dr * WW + dc;
            nb = min(max(nb, 0), NN - 1);
            float4 bm = *(const float4*)(g_Bm + (size_t)nb * 128 + k0);
            const float* ap = Ac + c * 132 + k0;
            float du = du_s[c];
            float4 v;
            v.x = tsw(ap[0] + bm.x + du * wu_s[k0 + 0] + posW[d * 128 + k0 + 0]);
            v.y = tsw(ap[1] + bm.y + du * wu_s[k0 + 1] + posW[d * 128 + k0 + 1]);
            v.z = tsw(ap[2] + bm.z + du * wu_s[k0 + 2] + posW[d * 128 + k0 + 2]);
            v.w = tsw(ap[3] + bm.w + du * wu_s[k0 + 3] + posW[d * 128 + k0 + 3]);
            store_hl4(Mh, Ml, c, k0, v);
        }
        __syncthreads();
        float acc[4][4][4];
        ZERO444(acc);
        gemmh(Mh, Ml, Wh, Wl, acc, m0, n0c, g, t);
#pragma unroll
        for (int mi = 0; mi < 4; ++mi) {
            int c0 = m0 + 16 * mi + g;
            bool ok0 = (unsigned)(c0 + dc) < (unsigned)WW;
            bool ok1 = (unsigned)(c0 + 8 + dc) < (unsigned)WW;
#pragma unroll
            for (int nj = 0; nj < 4; ++nj) {
                int col = n0c + 8 * nj + 2 * t;
                float bb0 = b2m_s[col], bb1 = b2m_s[col + 1];
                if (ok0) {
                    agg[mi][nj][0] += tsw(acc[mi][nj][0] + bb0);
                    agg[mi][nj][1] += tsw(acc[mi][nj][1] + bb1);
                }
                if (ok1) {
                    agg[mi][nj][2] += tsw(acc[mi][nj][2] + bb0);
                    agg[mi][nj][3] += tsw(acc[mi][nj][3] + bb1);
                }
            }
        }
    }
    __syncthreads();  // last gemm done; M/W reusable

    // -------- update MLP --------
    const float* U1 = upd1W + (size_t)l * 261 * 128;
    {
        int crn = 1 + (r > 0) + (r < HH - 1);
#pragma unroll
        for (int mi = 0; mi < 4; ++mi) {
            int c0 = m0 + 16 * mi + g;
            float inv0 = 1.0f / (float)(crn * (1 + (c0 > 0) + (c0 < WW - 1)) - 1);
            float inv1 = 1.0f / (float)(crn * (2 + (c0 + 8 < WW - 1)) - 1);
#pragma unroll
            for (int nj = 0; nj < 4; ++nj) {
                int col = n0c + 8 * nj + 2 * t;
                store_hl2(Mh, Ml, c0, col, agg[mi][nj][0] * inv0, agg[mi][nj][1] * inv0);
                store_hl2(Mh, Ml, c0 + 8, col, agg[mi][nj][2] * inv1, agg[mi][nj][3] * inv1);
            }
        }
    }
    load_wt_hl(Wh, Wl, U1 + 128 * 128, tid);  // U1 agg rows
    if (tid < 128) {
        float s = upd1b[l * 128 + tid];
#pragma unroll
        for (int p = 0; p < NPRM; ++p)
            s = fmaf(cp_s[p], U1[(256 + p) * 128 + tid], s);
        pcu_s[tid] = s;
        b2u_s[tid] = upd2b[l * 128 + tid];
    }
    __syncthreads();
    float acc2[4][4][4];
    ZERO444(acc2);
    gemmh(Mh, Ml, Wh, Wl, acc2, m0, n0c, g, t);
    __syncthreads();
    for (int i = tid; i < 4096; i += 256) {  // f -> M planes
        int c = i >> 5, k0 = (i & 31) * 4;
        store_hl4(Mh, Ml, c, k0, *(const float4*)(g_f + (size_t)(nb0 + c) * 128 + k0));
    }
    load_wt_hl(Wh, Wl, U1, tid);  // U1 f rows
    __syncthreads();
    gemmh(Mh, Ml, Wh, Wl, acc2, m0, n0c, g, t);  // accumulate
    __syncthreads();
#pragma unroll
    for (int mi = 0; mi < 4; ++mi) {  // h1 = swish(acc2 + pcu) -> M planes
        int c0 = m0 + 16 * mi + g;
#pragma unroll
        for (int nj = 0; nj < 4; ++nj) {
            int col = n0c + 8 * nj + 2 * t;
            store_hl2(Mh, Ml, c0, col, tsw(acc2[mi][nj][0] + pcu_s[col]),
                      tsw(acc2[mi][nj][1] + pcu_s[col + 1]));
            store_hl2(Mh, Ml, c0 + 8, col, tsw(acc2[mi][nj][2] + pcu_s[col]),
                      tsw(acc2[mi][nj][3] + pcu_s[col + 1]));
        }
    }
    load_wt_hl(Wh, Wl, upd2W + (size_t)l * 16384, tid);  // U2
    __syncthreads();
    float acc3[4][4][4];
    ZERO444(acc3);
    gemmh(Mh, Ml, Wh, Wl, acc3, m0, n0c, g, t);

    // -------- residual + stores + layernorm stats --------
    float* stage = Ac;  // Ac free after message loop
#pragma unroll
    for (int mi = 0; mi < 4; ++mi) {
#pragma unroll
        for (int half = 0; half < 2; ++half) {
            int c0 = m0 + 16 * mi + g + 8 * half;
#pragma unroll
            for (int nj = 0; nj < 4; ++nj) {
                int col = n0c + 8 * nj + 2 * t;
                float2 f2 = *(const float2*)(g_f + (size_t)(nb0 + c0) * 128 + col);
                float v0 = f2.x + tsw(acc3[mi][nj][2 * half + 0] + b2u_s[col]);
                float v1 = f2.y + tsw(acc3[mi][nj][2 * half + 1] + b2u_s[col + 1]);
                *(float2*)(g_tmp + (size_t)(nb0 + c0) * 128 + col) = make_float2(v0, v1);
                *(float2*)(stage + c0 * 132 + col) = make_float2(v0, v1);
            }
        }
    }
    __syncthreads();
    if (tid < 128) {
        float S = 0.0f, S2 = 0.0f;
#pragma unroll 4
        for (int gg = 0; gg < 128; ++gg) {
            float v = stage[gg * 132 + tid];
            S += v;
            S2 += v * v;
        }
        atomicAdd(&g_stats[b * 2 * HID + tid], S);
        atomicAdd(&g_stats[b * 2 * HID + HID + tid], S2);
    }
}

// ================= fp32 kernels (unchanged) =================
#define ACC_ZERO(acc)                                                  \
    _Pragma("unroll") for (int _i = 0; _i < 4; ++_i)                   \
        _Pragma("unroll") for (int _j = 0; _j < 8; ++_j) acc[_i][_j] = 0.0f;

template <int RSTEP>
__device__ __forceinline__ void gemm128(const float* __restrict__ As, int lda,
                                        const float* __restrict__ Ws, int ldw,
                                        float acc[4][8], int tr, int tc) {
#pragma unroll 4
    for (int k4 = 0; k4 < 32; ++k4) {
        float4 a[4];
#pragma unroll
        for (int i = 0; i < 4; ++i)
            a[i] = *(const float4*)(As + (tr + i * RSTEP) * lda + k4 * 4);
        const float* wp = Ws + (k4 * 4) * ldw + tc * 8;
#pragma unroll
        for (int kk = 0; kk < 4; ++kk) {
            float4 b0 = *(const float4*)(wp + kk * ldw);
            float4 b1 = *(const float4*)(wp + kk * ldw + 4);
#pragma unroll
            for (int i = 0; i < 4; ++i) {
                float av = ((const float*)(a + i))[kk];
                acc[i][0] = fmaf(av, b0.x, acc[i][0]);
                acc[i][1] = fmaf(av, b0.y, acc[i][1]);
                acc[i][2] = fmaf(av, b0.z, acc[i][2]);
                acc[i][3] = fmaf(av, b0.w, acc[i][3]);
                acc[i][4] = fmaf(av, b1.x, acc[i][4]);
                acc[i][5] = fmaf(av, b1.y, acc[i][5]);
                acc[i][6] = fmaf(av, b1.z, acc[i][6]);
                acc[i][7] = fmaf(av, b1.w, acc[i][7]);
            }
        }
    }
}

__global__ __launch_bounds__(256, 2) void k_embed(
    const float* __restrict__ inp, const float* __restrict__ cp,
    const float* __restrict__ W1, const float* __restrict__ b1,
    const float* __restrict__ W2, const float* __restrict__ b2) {
    extern __shared__ float sm[];
    float* e_s = sm;
    float* W1_s = e_s + 64 * 8;
    float* b1_s = W1_s + 8 * 128;
    float* h1_s = b1_s + 128;
    float* W2_s = h1_s + 64 * 132;
    float* b2_s = W2_s + 128 * 128;
    int tid = threadIdx.x;
    int n0 = blockIdx.x * 64, b = n0 / HW;
    for (int i = tid; i < 8 * 128; i += 256) W1_s[i] = W1[i];
    if (tid < 128) { b1_s[tid] = b1[tid]; b2_s[tid] = b2[tid]; }
    for (int i = tid; i < 128 * 32; i += 256)
        ((float4*)W2_s)[i] = ((const float4*)W2)[i];
    if (tid < 64) {
        int n = n0 + tid, rc = n - b * HW;
        int r = rc >> 7, c = rc & 127;
        e_s[tid * 8 + 0] = inp[b * NCH * HW + rc];
        e_s[tid * 8 + 1] = (float)r * (1.0f / 127.0f) * cp[b * NPRM + 1];
        e_s[tid * 8 + 2] = (float)c * (1.0f / 127.0f) * cp[b * NPRM + 0];
#pragma unroll
        for (int p = 0; p < NPRM; ++p) e_s[tid * 8 + 3 + p] = cp[b * NPRM + p];
    }
    __syncthreads();
    int tc = tid & 15, tr = tid >> 4;
#pragma unroll
    for (int i = 0; i < 4; ++i) {
        int row = tr + 16 * i;
#pragma unroll
        for (int j = 0; j < 8; ++j) {
            float s = b1_s[tc * 8 + j];
#pragma unroll
            for (int k = 0; k < 8; ++k)
                s = fmaf(e_s[row * 8 + k], W1_s[k * 128 + tc * 8 + j], s);
            h1_s[row * 132 + tc * 8 + j] = swishf(s);
        }
    }
    __syncthreads();
    float acc[4][8];
    ACC_ZERO(acc);
    gemm128<16>(h1_s, 132, W2_s, 128, acc, tr, tc);
#pragma unroll
    for (int i = 0; i < 4; ++i) {
        int row = tr + 16 * i;
#pragma unroll
        for (int j = 0; j < 8; ++j)
            g_f[(size_t)(n0 + row) * 128 + tc * 8 + j] =
                swishf(acc[i][j] + b2_s[tc * 8 + j]);
    }
}

__global__ __launch_bounds__(256) void k_norm() {
    __shared__ float mean_s[HID], rstd_s[HID];
    int b = blockIdx.x >> 9;
    if (threadIdx.x < 128) {
        float m = g_stats[b * 2 * HID + threadIdx.x] * (1.0f / (float)HW);
        float v = g_stats[b * 2 * HID + HID + threadIdx.x] * (1.0f / (float)HW) - m * m;
        mean_s[threadIdx.x] = m;
        rstd_s[threadIdx.x] = rsqrtf(v + EPSV);
    }
    __syncthreads();
    size_t base = (size_t)blockIdx.x * 1024;
#pragma unroll
    for (int k = 0; k < 4; ++k) {
        size_t i4 = base + threadIdx.x + k * 256;
        int j = ((int)(i4 & 31)) * 4;
        float4 v = ((const float4*)g_tmp)[i4];
        v.x = (v.x - mean_s[j + 0]) * rstd_s[j + 0];
        v.y = (v.y - mean_s[j + 1]) * rstd_s[j + 1];
        v.z = (v.z - mean_s[j + 2]) * rstd_s[j + 2];
        v.w = (v.w - mean_s[j + 3]) * rstd_s[j + 3];
        ((float4*)g_f)[i4] = v;
    }
}

__global__ __launch_bounds__(256, 2) void k_out(
    const float* __restrict__ inp, const float* __restrict__ W1,
    const float* __restrict__ b1, const float* __restrict__ W2,
    const float* __restrict__ b2, float* __restrict__ out) {
    extern __shared__ float sm[];
    float* f_s = sm;
    float* W1_s = f_s + 128 * 132;
    float* b1_s = W1_s + 128 * 64;
    float* W2_s = b1_s + 64;
    float* red_s = W2_s + 64;
    int tid = threadIdx.x;
    int n0 = blockIdx.x * 128, b = n0 / HW;
    for (int i = tid; i < 128 * 32; i += 256) {
        int c = i >> 5, q = i & 31;
        ((float4*)(f_s + c * 132))[q] = ((const float4*)(g_f + (size_t)(n0 + c) * 128))[q];
    }
    for (int i = tid; i < 128 * 16; i += 256)
        ((float4*)W1_s)[i] = ((const float4*)W1)[i];
    if (tid < 64) { b1_s[tid] = b1[tid]; W2_s[tid] = W2[tid]; }
    __syncthreads();
    int tc = tid & 7, tr = tid >> 3;
    float acc[4][8];
    ACC_ZERO(acc);
    gemm128<32>(f_s, 132, W1_s, 64, acc, tr, tc);
#pragma unroll
    for (int i = 0; i < 4; ++i) {
        float p = 0.0f;
#pragma unroll
        for (int j = 0; j < 8; ++j)
            p += swishf(acc[i][j] + b1_s[tc * 8 + j]) * W2_s[tc * 8 + j];
        red_s[(tr + 32 * i) * 8 + tc] = p;
    }
    __syncthreads();
    if (tid < 128) {
        float d = b2[0];
#pragma unroll
        for (int t = 0; t < 8; ++t) d += red_s[tid * 8 + t];
        int n = n0 + tid;
        out[n] = inp[b * NCH * HW + (n - b * HW)] + DTV * d;
    }
}

// ---------------- host launcher ----------------
extern "C" void kernel_launch(void* const* d_in, const int* in_sizes, int n_in,
                              void* d_out, int out_size) {
    const float* inp   = (const float*)d_in[0];
    const float* cp    = (const float*)d_in[1];
    const float* embW1 = (const float*)d_in[3];
    const float* embb1 = (const float*)d_in[4];
    const float* embW2 = (const float*)d_in[5];
    const float* embb2 = (const float*)d_in[6];
    const float* msg1W = (const float*)d_in[7];
    const float* msg1b = (const float*)d_in[8];
    const float* msg2W = (const float*)d_in[9];
    const float* msg2b = (const float*)d_in[10];
    const float* upd1W = (const float*)d_in[11];
    const float* upd1b = (const float*)d_in[12];
    const float* upd2W = (const float*)d_in[13];
    const float* upd2b = (const float*)d_in[14];
    const float* outW1 = (const float*)d_in[15];
    const float* outb1 = (const float*)d_in[16];
    const float* outW2 = (const float*)d_in[17];
    const float* outb2 = (const float*)d_in[18];
    float* out = (float*)d_out;

    const size_t smE = (size_t)(64 * 8 + 8 * 128 + 128 + 64 * 132 + 128 * 128 + 128) * 4;
    const size_t smO = (size_t)(128 * 132 + 128 * 64 + 64 + 64 + 128 * 8) * 4;
    const size_t smMA = 139776;
    const size_t smEG = 213536;

    cudaFuncSetAttribute(k_embed, cudaFuncAttributeMaxDynamicSharedMemorySize, (int)smE);
    cudaFuncSetAttribute(k_out, cudaFuncAttributeMaxDynamicSharedMemorySize, (int)smO);
    cudaFuncSetAttribute(k_msgA_mm, cudaFuncAttributeMaxDynamicSharedMemorySize, (int)smMA);
    cudaFuncSetAttribute(k_edge_mm, cudaFuncAttributeMaxDynamicSharedMemorySize, (int)smEG);

    k_embed<<<NN / 64, 256, smE>>>(inp, cp, embW1, embb1, embW2, embb2);
    for (int l = 0; l < NL; ++l) {
        k_msgA_mm<<<NN / 128, 256, smMA>>>(cp, msg1W, msg1b, l);
        k_edge_mm<<<NN / 128, 256, smEG>>>(inp, cp, msg1W, msg2W, msg2b,
                                           upd1W, upd1b, upd2W, upd2b, l);
        k_norm<<<2048, 256>>>();
    }
    k_out<<<NN / 128, 256, smO>>>(inp, outW1, outb1, outW2, outb2, out);
}

// round 7
// speedup vs baseline: 2.8464x; 1.3209x over previous
#include <cuda_runtime.h>
#include <cuda_fp16.h>
#include <cstdint>

#define HH 128
#define WW 128
#define HW 16384
#define NN 65536
#define HID 128
#define NL 6
#define NPRM 5
#define EPSV 1e-5f
#define DTV 0.1f
#define NCH 3
#define NBATCH 4
#define PS 68  // uint32 (half2) words per plane row

__device__ float g_f[(size_t)NN * HID];
__device__ __half g_Ah[(size_t)NN * HID];
__device__ __half g_Bh[(size_t)NN * HID];
__device__ float g_tmp[(size_t)NN * HID];
__device__ float g_stats[NBATCH * 2 * HID];

__device__ __forceinline__ float swishf(float x) {
    return __fdividef(x, 1.0f + __expf(-x));
}
__device__ __forceinline__ float tsw(float x) {
    float h = 0.5f * x, th;
    asm("tanh.approx.f32 %0, %1;" : "=f"(th) : "f"(h));
    return h + h * th;
}
__device__ __forceinline__ __half2 u2h(uint32_t u) {
    return *reinterpret_cast<__half2*>(&u);
}
__device__ __forceinline__ uint32_t h2u(__half2 h) {
    return *reinterpret_cast<uint32_t*>(&h);
}
__device__ __forceinline__ __half2 tanh2(__half2 x) {
    uint32_t r;
    asm("tanh.approx.f16x2 %0, %1;" : "=r"(r) : "r"(h2u(x)));
    return u2h(r);
}
// packed swish of fp32 pair: m = h + h*tanh(h), h = (x)/2 ; returns half2
__device__ __forceinline__ __half2 psw(float x0, float x1) {
    __half2 h = __floats2half2_rn(0.5f * x0, 0.5f * x1);
    __half2 t = tanh2(h);
    return __hfma2(h, t, h);
}

// load weight W[k][n] (row-major 128x128) TRANSPOSED into planes Wt[n][k] hi+lo
__device__ void load_wt_hl(uint32_t* Hw, uint32_t* Lw, const float* __restrict__ W,
                           int tid) {
    __half* H = (__half*)Hw;
    __half* L = (__half*)Lw;
    for (int i = tid; i < 16384; i += 256) {
        int n = i & 127, k = i >> 7;
        float x = W[k * 128 + n];
        __half h = __float2half_rn(x);
        H[n * (2 * PS) + k] = h;
        L[n * (2 * PS) + k] = __float2half_rn(x - __half2float(h));
    }
}

// ---------------- hi-activation fp16 GEMM (m16n8k16), weights hi+lo --------
__device__ __forceinline__ void hmma(float* a_, uint32_t a0, uint32_t a1, uint32_t a2,
                                     uint32_t a3, uint32_t b0, uint32_t b1) {
    asm volatile(
        "mma.sync.aligned.m16n8k16.row.col.f32.f16.f16.f32 "
        "{%0,%1,%2,%3},{%4,%5,%6,%7},{%8,%9},{%0,%1,%2,%3};"
        : "+f"(a_[0]), "+f"(a_[1]), "+f"(a_[2]), "+f"(a_[3])
        : "r"(a0), "r"(a1), "r"(a2), "r"(a3), "r"(b0), "r"(b1));
}
#define ZERO444(a)                                                     \
    _Pragma("unroll") for (int _i = 0; _i < 4; ++_i)                   \
        _Pragma("unroll") for (int _j = 0; _j < 4; ++_j)               \
            _Pragma("unroll") for (int _q = 0; _q < 4; ++_q) a[_i][_j][_q] = 0.0f;

__device__ __forceinline__ void gemmh(const uint32_t* __restrict__ Ah,
                                      const uint32_t* __restrict__ Bh,
                                      const uint32_t* __restrict__ Bl,
                                      float acc[4][4][4], int m0, int n0c, int g, int t) {
#pragma unroll 1
    for (int s = 0; s < 8; ++s) {
        const int kb = s * 8 + t;
        uint32_t bh[4][2], bl[4][2];
#pragma unroll
        for (int nj = 0; nj < 4; ++nj) {
            const uint32_t* p = Bh + (n0c + 8 * nj + g) * PS + kb;
            bh[nj][0] = p[0];
            bh[nj][1] = p[4];
            const uint32_t* q = Bl + (n0c + 8 * nj + g) * PS + kb;
            bl[nj][0] = q[0];
            bl[nj][1] = q[4];
        }
#pragma unroll
        for (int mi = 0; mi < 4; ++mi) {
            const uint32_t* p = Ah + (m0 + 16 * mi + g) * PS + kb;
            uint32_t a0 = p[0], a1 = p[8 * PS], a2 = p[4], a3 = p[8 * PS + 4];
#pragma unroll
            for (int nj = 0; nj < 4; ++nj) {
                hmma(acc[mi][nj], a0, a1, a2, a3, bh[nj][0], bh[nj][1]);
                hmma(acc[mi][nj], a0, a1, a2, a3, bl[nj][0], bl[nj][1]);
            }
        }
    }
}

// ------------- k_msgA_mm: A = f@W_t + pc, Bm = f@W_s (fp16 out) -------------
__global__ __launch_bounds__(256, 2) void k_msgA_mm(
    const float* __restrict__ cp, const float* __restrict__ msg1W,
    const float* __restrict__ msg1b, int l) {
    extern __shared__ char smem[];
    uint32_t* Fh = (uint32_t*)smem;             // 34816
    uint32_t* Wh = (uint32_t*)(smem + 34816);   // 34816
    uint32_t* Wl = (uint32_t*)(smem + 69632);   // 34816
    float* pc_s = (float*)(smem + 104448);      // 512 -> 104960

    const int tid = threadIdx.x, warp = tid >> 5, lane = tid & 31;
    const int g = lane >> 2, t = lane & 3;
    const int m0 = (warp >> 2) * 64, n0c = (warp & 3) * 32;
    const int nb0 = blockIdx.x << 7, b = nb0 >> 14;
    const float* Wl1 = msg1W + (size_t)l * 264 * 128;

    if (blockIdx.x == 0)
        for (int i = tid; i < NBATCH * 2 * HID; i += 256) g_stats[i] = 0.0f;
    if (tid < 128) {
        float s = msg1b[l * 128 + tid];
#pragma unroll
        for (int p = 0; p < NPRM; ++p)
            s = fmaf(cp[b * NPRM + p], Wl1[(259 + p) * 128 + tid], s);
        pc_s[tid] = s;
    }
    for (int i = tid; i < 4096; i += 256) {
        int c = i >> 5, q = i & 31;
        float4 fv = *(const float4*)(g_f + (size_t)(nb0 + c) * 128 + q * 4);
        *(uint2*)(Fh + c * PS + 2 * q) = make_uint2(
            h2u(__floats2half2_rn(fv.x, fv.y)), h2u(__floats2half2_rn(fv.z, fv.w)));
    }
    load_wt_hl(Wh, Wl, Wl1, tid);  // W_t rows 0..127
    __syncthreads();

    float acc[4][4][4];
    ZERO444(acc);
    gemmh(Fh, Wh, Wl, acc, m0, n0c, g, t);
#pragma unroll
    for (int mi = 0; mi < 4; ++mi) {
        int c0 = m0 + 16 * mi + g;
#pragma unroll
        for (int nj = 0; nj < 4; ++nj) {
            int col = n0c + 8 * nj + 2 * t;
            *(uint32_t*)(g_Ah + (size_t)(nb0 + c0) * 128 + col) =
                h2u(__floats2half2_rn(acc[mi][nj][0] + pc_s[col],
                                      acc[mi][nj][1] + pc_s[col + 1]));
            *(uint32_t*)(g_Ah + (size_t)(nb0 + c0 + 8) * 128 + col) =
                h2u(__floats2half2_rn(acc[mi][nj][2] + pc_s[col],
                                      acc[mi][nj][3] + pc_s[col + 1]));
        }
    }
    __syncthreads();
    load_wt_hl(Wh, Wl, Wl1 + 128 * 128, tid);  // W_s rows 128..255
    __syncthreads();
    ZERO444(acc);
    gemmh(Fh, Wh, Wl, acc, m0, n0c, g, t);
#pragma unroll
    for (int mi = 0; mi < 4; ++mi) {
        int c0 = m0 + 16 * mi + g;
#pragma unroll
        for (int nj = 0; nj < 4; ++nj) {
            int col = n0c + 8 * nj + 2 * t;
            *(uint32_t*)(g_Bh + (size_t)(nb0 + c0) * 128 + col) =
                h2u(__floats2half2_rn(acc[mi][nj][0], acc[mi][nj][1]));
            *(uint32_t*)(g_Bh + (size_t)(nb0 + c0 + 8) * 128 + col) =
                h2u(__floats2half2_rn(acc[mi][nj][2], acc[mi][nj][3]));
        }
    }
}

// ------------- k_edge_mm: messages + agg + update MLP -------------
__global__ __launch_bounds__(256, 1) void k_edge_mm(
    const float* __restrict__ inp, const float* __restrict__ cp,
    const float* __restrict__ msg1W, const float* __restrict__ msg2W,
    const float* __restrict__ msg2b, const float* __restrict__ upd1W,
    const float* __restrict__ upd1b, const float* __restrict__ upd2W,
    const float* __restrict__ upd2b, int l) {
    extern __shared__ char smem[];
    uint32_t* Mh = (uint32_t*)smem;               // 34816
    uint32_t* Wh = (uint32_t*)(smem + 34816);     // 34816
    uint32_t* Wl = (uint32_t*)(smem + 69632);     // 34816
    uint32_t* Ac = (uint32_t*)(smem + 104448);    // 34816 (A tile, half2)
    uint32_t* posW2 = (uint32_t*)(smem + 139264); // 8*64*4 = 2048
    uint32_t* wu2 = (uint32_t*)(smem + 141312);   // 256
    float* b2m_s = (float*)(smem + 141568);       // 512
    float* pcu_s = (float*)(smem + 142080);       // 512
    float* b2u_s = (float*)(smem + 142592);       // 512
    uint32_t* du2_s = (uint32_t*)(smem + 143104); // 512
    float* cp_s = (float*)(smem + 143616);        // 32 -> total 143648
    float* stage = (float*)smem;                  // 128*132*4 = 67584 (late reuse)

    const int tid = threadIdx.x, warp = tid >> 5, lane = tid & 31;
    const int g = lane >> 2, t = lane & 3;
    const int m0 = (warp >> 2) * 64, n0c = (warp & 3) * 32;
    const int gr = blockIdx.x, b = gr >> 7, r = gr & 127, nb0 = gr << 7;
    const float* W1l = msg1W + (size_t)l * 264 * 128;
    const int DR[8] = {-1, -1, -1, 0, 0, 1, 1, 1};
    const int DC[8] = {-1, 0, 1, -1, 1, -1, 0, 1};

    if (tid < 8) cp_s[tid] = (tid < NPRM) ? cp[b * NPRM + tid] : 0.0f;
    if (tid < 128) b2m_s[tid] = msg2b[l * 128 + tid];
    if (tid < 64)  // wu as half2 pairs
        wu2[tid] = h2u(__floats2half2_rn(W1l[256 * 128 + 2 * tid],
                                         W1l[256 * 128 + 2 * tid + 1]));
    __syncthreads();
    for (int i = tid; i < 512; i += 256) {  // posW half2: [d][64]
        int d = i >> 6, j = i & 63;
        float pdx = (float)(-DR[d]) * (1.0f / 127.0f) * cp_s[1];
        float pdy = (float)(-DC[d]) * (1.0f / 127.0f) * cp_s[0];
        float v0 = pdx * W1l[257 * 128 + 2 * j] + pdy * W1l[258 * 128 + 2 * j];
        float v1 = pdx * W1l[257 * 128 + 2 * j + 1] + pdy * W1l[258 * 128 + 2 * j + 1];
        posW2[i] = h2u(__floats2half2_rn(v0, v1));
    }
    for (int i = tid; i < 4096; i += 256) {  // cache A tile (half2)
        int c = i >> 5, q = i & 31;
        *(uint2*)(Ac + c * PS + 2 * q) =
            *(const uint2*)(g_Ah + (size_t)(nb0 + c) * 128 + q * 4);
    }
    load_wt_hl(Wh, Wl, msg2W + (size_t)l * 16384, tid);

    __half2 agg[4][4][2];
#pragma unroll
    for (int i = 0; i < 4; ++i)
#pragma unroll
        for (int j = 0; j < 4; ++j) {
            agg[i][j][0] = __float2half2_rn(0.0f);
            agg[i][j][1] = __float2half2_rn(0.0f);
        }

#pragma unroll 1
    for (int d = 0; d < 8; ++d) {
        const int dr = DR[d], dc = DC[d];
        if ((unsigned)(r + dr) >= (unsigned)HH) continue;
        __syncthreads();  // prior gemm reads done (first iter: smem fills done)
        if (tid < 128) {
            int n = nb0 + tid, nb = n + dr * WW + dc;
            nb = min(max(nb, 0), NN - 1);
            int bb = nb >> 14;
            float du = inp[b * NCH * HW + (n - b * HW)] -
                       inp[bb * NCH * HW + (nb - bb * HW)];
            du2_s[tid] = h2u(__half2half2(__float2half_rn(du)));
        }
        __syncthreads();
        for (int i = tid; i < 4096; i += 256) {  // M build, all half2
            int c = i >> 5, q = i & 31;
            int nb = nb0 + c + dr * WW + dc;
            nb = min(max(nb, 0), NN - 1);
            uint2 bm = *(const uint2*)(g_Bh + (size_t)nb * 128 + q * 4);
            uint2 av = *(const uint2*)(Ac + c * PS + 2 * q);
            __half2 hd = u2h(du2_s[c]);
            __half2 half_c = __float2half2_rn(0.5f);
            __half2 s0 = __hadd2(__hadd2(u2h(av.x), u2h(bm.x)),
                                 __hfma2(hd, u2h(wu2[2 * q]), u2h(posW2[d * 64 + 2 * q])));
            __half2 s1 = __hadd2(__hadd2(u2h(av.y), u2h(bm.y)),
                                 __hfma2(hd, u2h(wu2[2 * q + 1]),
                                         u2h(posW2[d * 64 + 2 * q + 1])));
            __half2 h0 = __hmul2(s0, half_c), h1 = __hmul2(s1, half_c);
            __half2 t0 = tanh2(h0), t1 = tanh2(h1);
            *(uint2*)(Mh + c * PS + 2 * q) =
                make_uint2(h2u(__hfma2(h0, t0, h0)), h2u(__hfma2(h1, t1, h1)));
        }
        __syncthreads();
        float acc[4][4][4];
        ZERO444(acc);
        gemmh(Mh, Wh, Wl, acc, m0, n0c, g, t);
#pragma unroll
        for (int mi = 0; mi < 4; ++mi) {
            int c0 = m0 + 16 * mi + g;
            bool ok0 = (unsigned)(c0 + dc) < (unsigned)WW;
            bool ok1 = (unsigned)(c0 + 8 + dc) < (unsigned)WW;
#pragma unroll
            for (int nj = 0; nj < 4; ++nj) {
                int col = n0c + 8 * nj + 2 * t;
                if (ok0)
                    agg[mi][nj][0] = __hadd2(
                        agg[mi][nj][0],
                        psw(acc[mi][nj][0] + b2m_s[col], acc[mi][nj][1] + b2m_s[col + 1]));
                if (ok1)
                    agg[mi][nj][1] = __hadd2(
                        agg[mi][nj][1],
                        psw(acc[mi][nj][2] + b2m_s[col], acc[mi][nj][3] + b2m_s[col + 1]));
            }
        }
    }
    __syncthreads();  // last gemm done; Mh reusable

    // -------- update MLP --------
    const float* U1 = upd1W + (size_t)l * 261 * 128;
    {
        int crn = 1 + (r > 0) + (r < HH - 1);
#pragma unroll
        for (int mi = 0; mi < 4; ++mi) {
#pragma unroll
            for (int hh = 0; hh < 2; ++hh) {
                int c0 = m0 + 16 * mi + g + 8 * hh;
                float inv = 1.0f / (float)(crn * (1 + (c0 > 0) + (c0 < WW - 1)) - 1);
                __half2 inv2 = __float2half2_rn(inv);
#pragma unroll
                for (int nj = 0; nj < 4; ++nj)
                    Mh[c0 * PS + (n0c >> 1) + 4 * nj + t] =
                        h2u(__hmul2(agg[mi][nj][hh], inv2));
            }
        }
    }
    load_wt_hl(Wh, Wl, U1 + 128 * 128, tid);  // U1 agg rows
    if (tid < 128) {
        float s = upd1b[l * 128 + tid];
#pragma unroll
        for (int p = 0; p < NPRM; ++p)
            s = fmaf(cp_s[p], U1[(256 + p) * 128 + tid], s);
        pcu_s[tid] = s;
        b2u_s[tid] = upd2b[l * 128 + tid];
    }
    __syncthreads();
    float acc2[4][4][4];
    ZERO444(acc2);
    gemmh(Mh, Wh, Wl, acc2, m0, n0c, g, t);
    __syncthreads();
    for (int i = tid; i < 4096; i += 256) {  // f -> Mh (fp16 hi)
        int c = i >> 5, q = i & 31;
        float4 fv = *(const float4*)(g_f + (size_t)(nb0 + c) * 128 + q * 4);
        *(uint2*)(Mh + c * PS + 2 * q) = make_uint2(
            h2u(__floats2half2_rn(fv.x, fv.y)), h2u(__floats2half2_rn(fv.z, fv.w)));
    }
    load_wt_hl(Wh, Wl, U1, tid);  // U1 f rows
    __syncthreads();
    gemmh(Mh, Wh, Wl, acc2, m0, n0c, g, t);  // accumulate
    __syncthreads();
#pragma unroll
    for (int mi = 0; mi < 4; ++mi) {  // h1 = swish(acc2 + pcu) -> Mh
#pragma unroll
        for (int nj = 0; nj < 4; ++nj) {
            int col = n0c + 8 * nj + 2 * t;
            int c0 = m0 + 16 * mi + g;
            Mh[c0 * PS + (col >> 1)] =
                h2u(psw(acc2[mi][nj][0] + pcu_s[col], acc2[mi][nj][1] + pcu_s[col + 1]));
            Mh[(c0 + 8) * PS + (col >> 1)] =
                h2u(psw(acc2[mi][nj][2] + pcu_s[col], acc2[mi][nj][3] + pcu_s[col + 1]));
        }
    }
    load_wt_hl(Wh, Wl, upd2W + (size_t)l * 16384, tid);  // U2
    __syncthreads();
    float acc3[4][4][4];
    ZERO444(acc3);
    gemmh(Mh, Wh, Wl, acc3, m0, n0c, g, t);
    __syncthreads();  // gemm done; stage may overwrite Mh/Wh

    // -------- residual + stores + layernorm stats --------
#pragma unroll
    for (int mi = 0; mi < 4; ++mi) {
#pragma unroll
        for (int half = 0; half < 2; ++half) {
            int c0 = m0 + 16 * mi + g + 8 * half;
#pragma unroll
            for (int nj = 0; nj < 4; ++nj) {
                int col = n0c + 8 * nj + 2 * t;
                float2 f2 = *(const float2*)(g_f + (size_t)(nb0 + c0) * 128 + col);
                float v0 = f2.x + tsw(acc3[mi][nj][2 * half + 0] + b2u_s[col]);
                float v1 = f2.y + tsw(acc3[mi][nj][2 * half + 1] + b2u_s[col + 1]);
                *(float2*)(g_tmp + (size_t)(nb0 + c0) * 128 + col) = make_float2(v0, v1);
                *(float2*)(stage + c0 * 132 + col) = make_float2(v0, v1);
            }
        }
    }
    __syncthreads();
    if (tid < 128) {
        float S = 0.0f, S2 = 0.0f;
#pragma unroll 4
        for (int gg = 0; gg < 128; ++gg) {
            float v = stage[gg * 132 + tid];
            S += v;
            S2 += v * v;
        }
        atomicAdd(&g_stats[b * 2 * HID + tid], S);
        atomicAdd(&g_stats[b * 2 * HID + HID + tid], S2);
    }
}

// ================= fp32 kernels (unchanged) =================
#define ACC_ZERO(acc)                                                  \
    _Pragma("unroll") for (int _i = 0; _i < 4; ++_i)                   \
        _Pragma("unroll") for (int _j = 0; _j < 8; ++_j) acc[_i][_j] = 0.0f;

template <int RSTEP>
__device__ __forceinline__ void gemm128(const float* __restrict__ As, int lda,
                                        const float* __restrict__ Ws, int ldw,
                                        float acc[4][8], int tr, int tc) {
#pragma unroll 4
    for (int k4 = 0; k4 < 32; ++k4) {
        float4 a[4];
#pragma unroll
        for (int i = 0; i < 4; ++i)
            a[i] = *(const float4*)(As + (tr + i * RSTEP) * lda + k4 * 4);
        const float* wp = Ws + (k4 * 4) * ldw + tc * 8;
#pragma unroll
        for (int kk = 0; kk < 4; ++kk) {
            float4 b0 = *(const float4*)(wp + kk * ldw);
            float4 b1 = *(const float4*)(wp + kk * ldw + 4);
#pragma unroll
            for (int i = 0; i < 4; ++i) {
                float av = ((const float*)(a + i))[kk];
                acc[i][0] = fmaf(av, b0.x, acc[i][0]);
                acc[i][1] = fmaf(av, b0.y, acc[i][1]);
                acc[i][2] = fmaf(av, b0.z, acc[i][2]);
                acc[i][3] = fmaf(av, b0.w, acc[i][3]);
                acc[i][4] = fmaf(av, b1.x, acc[i][4]);
                acc[i][5] = fmaf(av, b1.y, acc[i][5]);
                acc[i][6] = fmaf(av, b1.z, acc[i][6]);
                acc[i][7] = fmaf(av, b1.w, acc[i][7]);
            }
        }
    }
}

__global__ __launch_bounds__(256, 2) void k_embed(
    const float* __restrict__ inp, const float* __restrict__ cp,
    const float* __restrict__ W1, const float* __restrict__ b1,
    const float* __restrict__ W2, const float* __restrict__ b2) {
    extern __shared__ float sm[];
    float* e_s = sm;
    float* W1_s = e_s + 64 * 8;
    float* b1_s = W1_s + 8 * 128;
    float* h1_s = b1_s + 128;
    float* W2_s = h1_s + 64 * 132;
    float* b2_s = W2_s + 128 * 128;
    int tid = threadIdx.x;
    int n0 = blockIdx.x * 64, b = n0 / HW;
    for (int i = tid; i < 8 * 128; i += 256) W1_s[i] = W1[i];
    if (tid < 128) { b1_s[tid] = b1[tid]; b2_s[tid] = b2[tid]; }
    for (int i = tid; i < 128 * 32; i += 256)
        ((float4*)W2_s)[i] = ((const float4*)W2)[i];
    if (tid < 64) {
        int n = n0 + tid, rc = n - b * HW;
        int r = rc >> 7, c = rc & 127;
        e_s[tid * 8 + 0] = inp[b * NCH * HW + rc];
        e_s[tid * 8 + 1] = (float)r * (1.0f / 127.0f) * cp[b * NPRM + 1];
        e_s[tid * 8 + 2] = (float)c * (1.0f / 127.0f) * cp[b * NPRM + 0];
#pragma unroll
        for (int p = 0; p < NPRM; ++p) e_s[tid * 8 + 3 + p] = cp[b * NPRM + p];
    }
    __syncthreads();
    int tc = tid & 15, tr = tid >> 4;
#pragma unroll
    for (int i = 0; i < 4; ++i) {
        int row = tr + 16 * i;
#pragma unroll
        for (int j = 0; j < 8; ++j) {
            float s = b1_s[tc * 8 + j];
#pragma unroll
            for (int k = 0; k < 8; ++k)
                s = fmaf(e_s[row * 8 + k], W1_s[k * 128 + tc * 8 + j], s);
            h1_s[row * 132 + tc * 8 + j] = swishf(s);
        }
    }
    __syncthreads();
    float acc[4][8];
    ACC_ZERO(acc);
    gemm128<16>(h1_s, 132, W2_s, 128, acc, tr, tc);
#pragma unroll
    for (int i = 0; i < 4; ++i) {
        int row = tr + 16 * i;
#pragma unroll
        for (int j = 0; j < 8; ++j)
            g_f[(size_t)(n0 + row) * 128 + tc * 8 + j] =
                swishf(acc[i][j] + b2_s[tc * 8 + j]);
    }
}

__global__ __launch_bounds__(256) void k_norm() {
    __shared__ float mean_s[HID], rstd_s[HID];
    int b = blockIdx.x >> 9;
    if (threadIdx.x < 128) {
        float m = g_stats[b * 2 * HID + threadIdx.x] * (1.0f / (float)HW);
        float v = g_stats[b * 2 * HID + HID + threadIdx.x] * (1.0f / (float)HW) - m * m;
        mean_s[threadIdx.x] = m;
        rstd_s[threadIdx.x] = rsqrtf(v + EPSV);
    }
    __syncthreads();
    size_t base = (size_t)blockIdx.x * 1024;
#pragma unroll
    for (int k = 0; k < 4; ++k) {
        size_t i4 = base + threadIdx.x + k * 256;
        int j = ((int)(i4 & 31)) * 4;
        float4 v = ((const float4*)g_tmp)[i4];
        v.x = (v.x - mean_s[j + 0]) * rstd_s[j + 0];
        v.y = (v.y - mean_s[j + 1]) * rstd_s[j + 1];
        v.z = (v.z - mean_s[j + 2]) * rstd_s[j + 2];
        v.w = (v.w - mean_s[j + 3]) * rstd_s[j + 3];
        ((float4*)g_f)[i4] = v;
    }
}

__global__ __launch_bounds__(256, 2) void k_out(
    const float* __restrict__ inp, const float* __restrict__ W1,
    const float* __restrict__ b1, const float* __restrict__ W2,
    const float* __restrict__ b2, float* __restrict__ out) {
    extern __shared__ float sm[];
    float* f_s = sm;
    float* W1_s = f_s + 128 * 132;
    float* b1_s = W1_s + 128 * 64;
    float* W2_s = b1_s + 64;
    float* red_s = W2_s + 64;
    int tid = threadIdx.x;
    int n0 = blockIdx.x * 128, b = n0 / HW;
    for (int i = tid; i < 128 * 32; i += 256) {
        int c = i >> 5, q = i & 31;
        ((float4*)(f_s + c * 132))[q] = ((const float4*)(g_f + (size_t)(n0 + c) * 128))[q];
    }
    for (int i = tid; i < 128 * 16; i += 256)
        ((float4*)W1_s)[i] = ((const float4*)W1)[i];
    if (tid < 64) { b1_s[tid] = b1[tid]; W2_s[tid] = W2[tid]; }
    __syncthreads();
    int tc = tid & 7, tr = tid >> 3;
    float acc[4][8];
    ACC_ZERO(acc);
    gemm128<32>(f_s, 132, W1_s, 64, acc, tr, tc);
#pragma unroll
    for (int i = 0; i < 4; ++i) {
        float p = 0.0f;
#pragma unroll
        for (int j = 0; j < 8; ++j)
            p += swishf(acc[i][j] + b1_s[tc * 8 + j]) * W2_s[tc * 8 + j];
        red_s[(tr + 32 * i) * 8 + tc] = p;
    }
    __syncthreads();
    if (tid < 128) {
        float d = b2[0];
#pragma unroll
        for (int t = 0; t < 8; ++t) d += red_s[tid * 8 + t];
        int n = n0 + tid;
        out[n] = inp[b * NCH * HW + (n - b * HW)] + DTV * d;
    }
}

// ---------------- host launcher ----------------
extern "C" void kernel_launch(void* const* d_in, const int* in_sizes, int n_in,
                              void* d_out, int out_size) {
    const float* inp   = (const float*)d_in[0];
    const float* cp    = (const float*)d_in[1];
    const float* embW1 = (const float*)d_in[3];
    const float* embb1 = (const float*)d_in[4];
    const float* embW2 = (const float*)d_in[5];
    const float* embb2 = (const float*)d_in[6];
    const float* msg1W = (const float*)d_in[7];
    const float* msg1b = (const float*)d_in[8];
    const float* msg2W = (const float*)d_in[9];
    const float* msg2b = (const float*)d_in[10];
    const float* upd1W = (const float*)d_in[11];
    const float* upd1b = (const float*)d_in[12];
    const float* upd2W = (const float*)d_in[13];
    const float* upd2b = (const float*)d_in[14];
    const float* outW1 = (const float*)d_in[15];
    const float* outb1 = (const float*)d_in[16];
    const float* outW2 = (const float*)d_in[17];
    const float* outb2 = (const float*)d_in[18];
    float* out = (float*)d_out;

    const size_t smE = (size_t)(64 * 8 + 8 * 128 + 128 + 64 * 132 + 128 * 128 + 128) * 4;
    const size_t smO = (size_t)(128 * 132 + 128 * 64 + 64 + 64 + 128 * 8) * 4;
    const size_t smMA = 104960;
    const size_t smEG = 143648;

    cudaFuncSetAttribute(k_embed, cudaFuncAttributeMaxDynamicSharedMemorySize, (int)smE);
    cudaFuncSetAttribute(k_out, cudaFuncAttributeMaxDynamicSharedMemorySize, (int)smO);
    cudaFuncSetAttribute(k_msgA_mm, cudaFuncAttributeMaxDynamicSharedMemorySize, (int)smMA);
    cudaFuncSetAttribute(k_edge_mm, cudaFuncAttributeMaxDynamicSharedMemorySize, (int)smEG);

    k_embed<<<NN / 64, 256, smE>>>(inp, cp, embW1, embb1, embW2, embb2);
    for (int l = 0; l < NL; ++l) {
        k_msgA_mm<<<NN / 128, 256, smMA>>>(cp, msg1W, msg1b, l);
        k_edge_mm<<<NN / 128, 256, smEG>>>(inp, cp, msg1W, msg2W, msg2b,
                                           upd1W, upd1b, upd2W, upd2b, l);
        k_norm<<<2048, 256>>>();
    }
    k_out<<<NN / 128, 256, smO>>>(inp, outW1, outb1, outW2, outb2, out);
}

// round 8
// speedup vs baseline: 4.7319x; 1.6624x over previous
#include <cuda_runtime.h>
#include <cuda_fp16.h>
#include <cstdint>

#define HH 128
#define WW 128
#define HW 16384
#define NN 65536
#define HID 128
#define NL 6
#define NPRM 5
#define EPSV 1e-5f
#define DTV 0.1f
#define NCH 3
#define NBATCH 4
#define PS 68  // uint32 (half2) words per plane row

__device__ float g_f[(size_t)NN * HID];
__device__ __half g_Ah[(size_t)NN * HID];
__device__ __half g_Bh[(size_t)NN * HID];
__device__ float g_tmp[(size_t)NN * HID];
__device__ float g_stats[NBATCH * 2 * HID];

__device__ __forceinline__ float swishf(float x) {
    return __fdividef(x, 1.0f + __expf(-x));
}
__device__ __forceinline__ float tsw(float x) {
    float h = 0.5f * x, th;
    asm("tanh.approx.f32 %0, %1;" : "=f"(th) : "f"(h));
    return h + h * th;
}
__device__ __forceinline__ __half2 u2h(uint32_t u) {
    return *reinterpret_cast<__half2*>(&u);
}
__device__ __forceinline__ uint32_t h2u(__half2 h) {
    return *reinterpret_cast<uint32_t*>(&h);
}
__device__ __forceinline__ __half2 tanh2(__half2 x) {
    uint32_t r;
    asm("tanh.approx.f16x2 %0, %1;" : "=r"(r) : "r"(h2u(x)));
    return u2h(r);
}
// packed swish of fp32 pair: m = h + h*tanh(h), h = x/2 ; returns half2
__device__ __forceinline__ __half2 psw(float x0, float x1) {
    __half2 h = __floats2half2_rn(0.5f * x0, 0.5f * x1);
    __half2 t = tanh2(h);
    return __hfma2(h, t, h);
}

// load weight W[k][n] (row-major 128x128) TRANSPOSED into plane Wt[n][k] (fp16 hi)
__device__ void load_wt_h(uint32_t* Hw, const float* __restrict__ W, int tid) {
    __half* H = (__half*)Hw;
    for (int i = tid; i < 16384; i += 256) {
        int n = i & 127, k = i >> 7;
        H[n * (2 * PS) + k] = __float2half_rn(W[k * 128 + n]);
    }
}

// ---------------- fp16 GEMM (m16n8k16), hi-only operands ----------------
__device__ __forceinline__ void hmma(float* a_, uint32_t a0, uint32_t a1, uint32_t a2,
                                     uint32_t a3, uint32_t b0, uint32_t b1) {
    asm volatile(
        "mma.sync.aligned.m16n8k16.row.col.f32.f16.f16.f32 "
        "{%0,%1,%2,%3},{%4,%5,%6,%7},{%8,%9},{%0,%1,%2,%3};"
        : "+f"(a_[0]), "+f"(a_[1]), "+f"(a_[2]), "+f"(a_[3])
        : "r"(a0), "r"(a1), "r"(a2), "r"(a3), "r"(b0), "r"(b1));
}
#define ZERO444(a)                                                     \
    _Pragma("unroll") for (int _i = 0; _i < 4; ++_i)                   \
        _Pragma("unroll") for (int _j = 0; _j < 4; ++_j)               \
            _Pragma("unroll") for (int _q = 0; _q < 4; ++_q) a[_i][_j][_q] = 0.0f;

__device__ __forceinline__ void gemmh(const uint32_t* __restrict__ Ah,
                                      const uint32_t* __restrict__ Bh,
                                      float acc[4][4][4], int m0, int n0c, int g, int t) {
#pragma unroll 1
    for (int s = 0; s < 8; ++s) {
        const int kb = s * 8 + t;
        uint32_t bh[4][2];
#pragma unroll
        for (int nj = 0; nj < 4; ++nj) {
            const uint32_t* p = Bh + (n0c + 8 * nj + g) * PS + kb;
            bh[nj][0] = p[0];
            bh[nj][1] = p[4];
        }
#pragma unroll
        for (int mi = 0; mi < 4; ++mi) {
            const uint32_t* p = Ah + (m0 + 16 * mi + g) * PS + kb;
            uint32_t a0 = p[0], a1 = p[8 * PS], a2 = p[4], a3 = p[8 * PS + 4];
#pragma unroll
            for (int nj = 0; nj < 4; ++nj)
                hmma(acc[mi][nj], a0, a1, a2, a3, bh[nj][0], bh[nj][1]);
        }
    }
}

// ------------- k_msgA_mm: A = f@W_t + pc, Bm = f@W_s (fp16 out) -------------
__global__ __launch_bounds__(256, 3) void k_msgA_mm(
    const float* __restrict__ cp, const float* __restrict__ msg1W,
    const float* __restrict__ msg1b, int l) {
    extern __shared__ char smem[];
    uint32_t* Fh = (uint32_t*)smem;             // 34816
    uint32_t* Wh = (uint32_t*)(smem + 34816);   // 34816
    float* pc_s = (float*)(smem + 69632);       // 512 -> 70144

    const int tid = threadIdx.x, warp = tid >> 5, lane = tid & 31;
    const int g = lane >> 2, t = lane & 3;
    const int m0 = (warp >> 2) * 64, n0c = (warp & 3) * 32;
    const int nb0 = blockIdx.x << 7, b = nb0 >> 14;
    const float* Wl1 = msg1W + (size_t)l * 264 * 128;

    if (blockIdx.x == 0)
        for (int i = tid; i < NBATCH * 2 * HID; i += 256) g_stats[i] = 0.0f;
    if (tid < 128) {
        float s = msg1b[l * 128 + tid];
#pragma unroll
        for (int p = 0; p < NPRM; ++p)
            s = fmaf(cp[b * NPRM + p], Wl1[(259 + p) * 128 + tid], s);
        pc_s[tid] = s;
    }
    for (int i = tid; i < 4096; i += 256) {
        int c = i >> 5, q = i & 31;
        float4 fv = *(const float4*)(g_f + (size_t)(nb0 + c) * 128 + q * 4);
        *(uint2*)(Fh + c * PS + 2 * q) = make_uint2(
            h2u(__floats2half2_rn(fv.x, fv.y)), h2u(__floats2half2_rn(fv.z, fv.w)));
    }
    load_wt_h(Wh, Wl1, tid);  // W_t rows 0..127
    __syncthreads();

    float acc[4][4][4];
    ZERO444(acc);
    gemmh(Fh, Wh, acc, m0, n0c, g, t);
#pragma unroll
    for (int mi = 0; mi < 4; ++mi) {
        int c0 = m0 + 16 * mi + g;
#pragma unroll
        for (int nj = 0; nj < 4; ++nj) {
            int col = n0c + 8 * nj + 2 * t;
            *(uint32_t*)(g_Ah + (size_t)(nb0 + c0) * 128 + col) =
                h2u(__floats2half2_rn(acc[mi][nj][0] + pc_s[col],
                                      acc[mi][nj][1] + pc_s[col + 1]));
            *(uint32_t*)(g_Ah + (size_t)(nb0 + c0 + 8) * 128 + col) =
                h2u(__floats2half2_rn(acc[mi][nj][2] + pc_s[col],
                                      acc[mi][nj][3] + pc_s[col + 1]));
        }
    }
    __syncthreads();
    load_wt_h(Wh, Wl1 + 128 * 128, tid);  // W_s rows 128..255
    __syncthreads();
    ZERO444(acc);
    gemmh(Fh, Wh, acc, m0, n0c, g, t);
#pragma unroll
    for (int mi = 0; mi < 4; ++mi) {
        int c0 = m0 + 16 * mi + g;
#pragma unroll
        for (int nj = 0; nj < 4; ++nj) {
            int col = n0c + 8 * nj + 2 * t;
            *(uint32_t*)(g_Bh + (size_t)(nb0 + c0) * 128 + col) =
                h2u(__floats2half2_rn(acc[mi][nj][0], acc[mi][nj][1]));
            *(uint32_t*)(g_Bh + (size_t)(nb0 + c0 + 8) * 128 + col) =
                h2u(__floats2half2_rn(acc[mi][nj][2], acc[mi][nj][3]));
        }
    }
}

// ------------- k_edge_mm: messages + agg + update MLP -------------
__global__ __launch_bounds__(256, 2) void k_edge_mm(
    const float* __restrict__ inp, const float* __restrict__ cp,
    const float* __restrict__ msg1W, const float* __restrict__ msg2W,
    const float* __restrict__ msg2b, const float* __restrict__ upd1W,
    const float* __restrict__ upd1b, const float* __restrict__ upd2W,
    const float* __restrict__ upd2b, int l) {
    extern __shared__ char smem[];
    uint32_t* Mh = (uint32_t*)smem;               // 34816
    uint32_t* Wh = (uint32_t*)(smem + 34816);     // 34816
    uint32_t* Ac = (uint32_t*)(smem + 69632);     // 34816 (A tile, half2)
    uint32_t* posW2 = (uint32_t*)(smem + 104448); // 2048
    uint32_t* wu2 = (uint32_t*)(smem + 106496);   // 256
    float* b2m_s = (float*)(smem + 106752);       // 512
    float* pcu_s = (float*)(smem + 107264);       // 512
    float* b2u_s = (float*)(smem + 107776);       // 512
    uint32_t* du2_s = (uint32_t*)(smem + 108288); // 512
    float* cp_s = (float*)(smem + 108800);        // 32 -> total 108832
    float* stage = (float*)smem;                  // 128*132*4 = 67584 (late reuse of Mh+Wh)

    const int tid = threadIdx.x, warp = tid >> 5, lane = tid & 31;
    const int g = lane >> 2, t = lane & 3;
    const int m0 = (warp >> 2) * 64, n0c = (warp & 3) * 32;
    const int gr = blockIdx.x, b = gr >> 7, r = gr & 127, nb0 = gr << 7;
    const float* W1l = msg1W + (size_t)l * 264 * 128;
    const int DR[8] = {-1, -1, -1, 0, 0, 1, 1, 1};
    const int DC[8] = {-1, 0, 1, -1, 1, -1, 0, 1};

    if (tid < 8) cp_s[tid] = (tid < NPRM) ? cp[b * NPRM + tid] : 0.0f;
    if (tid < 128) b2m_s[tid] = msg2b[l * 128 + tid];
    if (tid < 64)
        wu2[tid] = h2u(__floats2half2_rn(W1l[256 * 128 + 2 * tid],
                                         W1l[256 * 128 + 2 * tid + 1]));
    __syncthreads();
    for (int i = tid; i < 512; i += 256) {  // posW half2: [d][64]
        int d = i >> 6, j = i & 63;
        float pdx = (float)(-DR[d]) * (1.0f / 127.0f) * cp_s[1];
        float pdy = (float)(-DC[d]) * (1.0f / 127.0f) * cp_s[0];
        float v0 = pdx * W1l[257 * 128 + 2 * j] + pdy * W1l[258 * 128 + 2 * j];
        float v1 = pdx * W1l[257 * 128 + 2 * j + 1] + pdy * W1l[258 * 128 + 2 * j + 1];
        posW2[i] = h2u(__floats2half2_rn(v0, v1));
    }
    for (int i = tid; i < 4096; i += 256) {  // cache A tile (half2)
        int c = i >> 5, q = i & 31;
        *(uint2*)(Ac + c * PS + 2 * q) =
            *(const uint2*)(g_Ah + (size_t)(nb0 + c) * 128 + q * 4);
    }
    load_wt_h(Wh, msg2W + (size_t)l * 16384, tid);

    __half2 agg[4][4][2];
#pragma unroll
    for (int i = 0; i < 4; ++i)
#pragma unroll
        for (int j = 0; j < 4; ++j) {
            agg[i][j][0] = __float2half2_rn(0.0f);
            agg[i][j][1] = __float2half2_rn(0.0f);
        }

#pragma unroll 1
    for (int d = 0; d < 8; ++d) {
        const int dr = DR[d], dc = DC[d];
        if ((unsigned)(r + dr) >= (unsigned)HH) continue;
        __syncthreads();  // prior gemm reads done (first iter: smem fills done)
        if (tid < 128) {
            int n = nb0 + tid, nb = n + dr * WW + dc;
            nb = min(max(nb, 0), NN - 1);
            int bb = nb >> 14;
            float du = inp[b * NCH * HW + (n - b * HW)] -
                       inp[bb * NCH * HW + (nb - bb * HW)];
            du2_s[tid] = h2u(__half2half2(__float2half_rn(du)));
        }
        __syncthreads();
        for (int i = tid; i < 4096; i += 256) {  // M build, all half2
            int c = i >> 5, q = i & 31;
            int nb = nb0 + c + dr * WW + dc;
            nb = min(max(nb, 0), NN - 1);
            uint2 bm = *(const uint2*)(g_Bh + (size_t)nb * 128 + q * 4);
            uint2 av = *(const uint2*)(Ac + c * PS + 2 * q);
            __half2 hd = u2h(du2_s[c]);
            __half2 half_c = __float2half2_rn(0.5f);
            __half2 s0 = __hadd2(__hadd2(u2h(av.x), u2h(bm.x)),
                                 __hfma2(hd, u2h(wu2[2 * q]), u2h(posW2[d * 64 + 2 * q])));
            __half2 s1 = __hadd2(__hadd2(u2h(av.y), u2h(bm.y)),
                                 __hfma2(hd, u2h(wu2[2 * q + 1]),
                                         u2h(posW2[d * 64 + 2 * q + 1])));
            __half2 h0 = __hmul2(s0, half_c), h1 = __hmul2(s1, half_c);
            __half2 t0 = tanh2(h0), t1 = tanh2(h1);
            *(uint2*)(Mh + c * PS + 2 * q) =
                make_uint2(h2u(__hfma2(h0, t0, h0)), h2u(__hfma2(h1, t1, h1)));
        }
        __syncthreads();
        float acc[4][4][4];
        ZERO444(acc);
        gemmh(Mh, Wh, acc, m0, n0c, g, t);
#pragma unroll
        for (int mi = 0; mi < 4; ++mi) {
            int c0 = m0 + 16 * mi + g;
            bool ok0 = (unsigned)(c0 + dc) < (unsigned)WW;
            bool ok1 = (unsigned)(c0 + 8 + dc) < (unsigned)WW;
#pragma unroll
            for (int nj = 0; nj < 4; ++nj) {
                int col = n0c + 8 * nj + 2 * t;
                if (ok0)
                    agg[mi][nj][0] = __hadd2(
                        agg[mi][nj][0],
                        psw(acc[mi][nj][0] + b2m_s[col], acc[mi][nj][1] + b2m_s[col + 1]));
                if (ok1)
                    agg[mi][nj][1] = __hadd2(
                        agg[mi][nj][1],
                        psw(acc[mi][nj][2] + b2m_s[col], acc[mi][nj][3] + b2m_s[col + 1]));
            }
        }
    }
    __syncthreads();  // last gemm done; Mh reusable

    // -------- update MLP --------
    const float* U1 = upd1W + (size_t)l * 261 * 128;
    {
        int crn = 1 + (r > 0) + (r < HH - 1);
#pragma unroll
        for (int mi = 0; mi < 4; ++mi) {
#pragma unroll
            for (int hh = 0; hh < 2; ++hh) {
                int c0 = m0 + 16 * mi + g + 8 * hh;
                float inv = 1.0f / (float)(crn * (1 + (c0 > 0) + (c0 < WW - 1)) - 1);
                __half2 inv2 = __float2half2_rn(inv);
#pragma unroll
                for (int nj = 0; nj < 4; ++nj)
                    Mh[c0 * PS + (n0c >> 1) + 4 * nj + t] =
                        h2u(__hmul2(agg[mi][nj][hh], inv2));
            }
        }
    }
    load_wt_h(Wh, U1 + 128 * 128, tid);  // U1 agg rows
    if (tid < 128) {
        float s = upd1b[l * 128 + tid];
#pragma unroll
        for (int p = 0; p < NPRM; ++p)
            s = fmaf(cp_s[p], U1[(256 + p) * 128 + tid], s);
        pcu_s[tid] = s;
        b2u_s[tid] = upd2b[l * 128 + tid];
    }
    __syncthreads();
    float acc2[4][4][4];
    ZERO444(acc2);
    gemmh(Mh, Wh, acc2, m0, n0c, g, t);
    __syncthreads();
    for (int i = tid; i < 4096; i += 256) {  // f -> Mh (fp16 hi)
        int c = i >> 5, q = i & 31;
        float4 fv = *(const float4*)(g_f + (size_t)(nb0 + c) * 128 + q * 4);
        *(uint2*)(Mh + c * PS + 2 * q) = make_uint2(
            h2u(__floats2half2_rn(fv.x, fv.y)), h2u(__floats2half2_rn(fv.z, fv.w)));
    }
    load_wt_h(Wh, U1, tid);  // U1 f rows
    __syncthreads();
    gemmh(Mh, Wh, acc2, m0, n0c, g, t);  // accumulate
    __syncthreads();
#pragma unroll
    for (int mi = 0; mi < 4; ++mi) {  // h1 = swish(acc2 + pcu) -> Mh
#pragma unroll
        for (int nj = 0; nj < 4; ++nj) {
            int col = n0c + 8 * nj + 2 * t;
            int c0 = m0 + 16 * mi + g;
            Mh[c0 * PS + (col >> 1)] =
                h2u(psw(acc2[mi][nj][0] + pcu_s[col], acc2[mi][nj][1] + pcu_s[col + 1]));
            Mh[(c0 + 8) * PS + (col >> 1)] =
                h2u(psw(acc2[mi][nj][2] + pcu_s[col], acc2[mi][nj][3] + pcu_s[col + 1]));
        }
    }
    load_wt_h(Wh, upd2W + (size_t)l * 16384, tid);  // U2
    __syncthreads();
    float acc3[4][4][4];
    ZERO444(acc3);
    gemmh(Mh, Wh, acc3, m0, n0c, g, t);
    __syncthreads();  // gemm done; stage may overwrite Mh/Wh

    // -------- residual + stores + layernorm stats --------
#pragma unroll
    for (int mi = 0; mi < 4; ++mi) {
#pragma unroll
        for (int half = 0; half < 2; ++half) {
            int c0 = m0 + 16 * mi + g + 8 * half;
#pragma unroll
            for (int nj = 0; nj < 4; ++nj) {
                int col = n0c + 8 * nj + 2 * t;
                float2 f2 = *(const float2*)(g_f + (size_t)(nb0 + c0) * 128 + col);
                float v0 = f2.x + tsw(acc3[mi][nj][2 * half + 0] + b2u_s[col]);
                float v1 = f2.y + tsw(acc3[mi][nj][2 * half + 1] + b2u_s[col + 1]);
                *(float2*)(g_tmp + (size_t)(nb0 + c0) * 128 + col) = make_float2(v0, v1);
                *(float2*)(stage + c0 * 132 + col) = make_float2(v0, v1);
            }
        }
    }
    __syncthreads();
    if (tid < 128) {
        float S = 0.0f, S2 = 0.0f;
#pragma unroll 4
        for (int gg = 0; gg < 128; ++gg) {
            float v = stage[gg * 132 + tid];
            S += v;
            S2 += v * v;
        }
        atomicAdd(&g_stats[b * 2 * HID + tid], S);
        atomicAdd(&g_stats[b * 2 * HID + HID + tid], S2);
    }
}

// ================= fp32 kernels (unchanged) =================
#define ACC_ZERO(acc)                                                  \
    _Pragma("unroll") for (int _i = 0; _i < 4; ++_i)                   \
        _Pragma("unroll") for (int _j = 0; _j < 8; ++_j) acc[_i][_j] = 0.0f;

template <int RSTEP>
__device__ __forceinline__ void gemm128(const float* __restrict__ As, int lda,
                                        const float* __restrict__ Ws, int ldw,
                                        float acc[4][8], int tr, int tc) {
#pragma unroll 4
    for (int k4 = 0; k4 < 32; ++k4) {
        float4 a[4];
#pragma unroll
        for (int i = 0; i < 4; ++i)
            a[i] = *(const float4*)(As + (tr + i * RSTEP) * lda + k4 * 4);
        const float* wp = Ws + (k4 * 4) * ldw + tc * 8;
#pragma unroll
        for (int kk = 0; kk < 4; ++kk) {
            float4 b0 = *(const float4*)(wp + kk * ldw);
            float4 b1 = *(const float4*)(wp + kk * ldw + 4);
#pragma unroll
            for (int i = 0; i < 4; ++i) {
                float av = ((const float*)(a + i))[kk];
                acc[i][0] = fmaf(av, b0.x, acc[i][0]);
                acc[i][1] = fmaf(av, b0.y, acc[i][1]);
                acc[i][2] = fmaf(av, b0.z, acc[i][2]);
                acc[i][3] = fmaf(av, b0.w, acc[i][3]);
                acc[i][4] = fmaf(av, b1.x, acc[i][4]);
                acc[i][5] = fmaf(av, b1.y, acc[i][5]);
                acc[i][6] = fmaf(av, b1.z, acc[i][6]);
                acc[i][7] = fmaf(av, b1.w, acc[i][7]);
            }
        }
    }
}

__global__ __launch_bounds__(256, 2) void k_embed(
    const float* __restrict__ inp, const float* __restrict__ cp,
    const float* __restrict__ W1, const float* __restrict__ b1,
    const float* __restrict__ W2, const float* __restrict__ b2) {
    extern __shared__ float sm[];
    float* e_s = sm;
    float* W1_s = e_s + 64 * 8;
    float* b1_s = W1_s + 8 * 128;
    float* h1_s = b1_s + 128;
    float* W2_s = h1_s + 64 * 132;
    float* b2_s = W2_s + 128 * 128;
    int tid = threadIdx.x;
    int n0 = blockIdx.x * 64, b = n0 / HW;
    for (int i = tid; i < 8 * 128; i += 256) W1_s[i] = W1[i];
    if (tid < 128) { b1_s[tid] = b1[tid]; b2_s[tid] = b2[tid]; }
    for (int i = tid; i < 128 * 32; i += 256)
        ((float4*)W2_s)[i] = ((const float4*)W2)[i];
    if (tid < 64) {
        int n = n0 + tid, rc = n - b * HW;
        int r = rc >> 7, c = rc & 127;
        e_s[tid * 8 + 0] = inp[b * NCH * HW + rc];
        e_s[tid * 8 + 1] = (float)r * (1.0f / 127.0f) * cp[b * NPRM + 1];
        e_s[tid * 8 + 2] = (float)c * (1.0f / 127.0f) * cp[b * NPRM + 0];
#pragma unroll
        for (int p = 0; p < NPRM; ++p) e_s[tid * 8 + 3 + p] = cp[b * NPRM + p];
    }
    __syncthreads();
    int tc = tid & 15, tr = tid >> 4;
#pragma unroll
    for (int i = 0; i < 4; ++i) {
        int row = tr + 16 * i;
#pragma unroll
        for (int j = 0; j < 8; ++j) {
            float s = b1_s[tc * 8 + j];
#pragma unroll
            for (int k = 0; k < 8; ++k)
                s = fmaf(e_s[row * 8 + k], W1_s[k * 128 + tc * 8 + j], s);
            h1_s[row * 132 + tc * 8 + j] = swishf(s);
        }
    }
    __syncthreads();
    float acc[4][8];
    ACC_ZERO(acc);
    gemm128<16>(h1_s, 132, W2_s, 128, acc, tr, tc);
#pragma unroll
    for (int i = 0; i < 4; ++i) {
        int row = tr + 16 * i;
#pragma unroll
        for (int j = 0; j < 8; ++j)
            g_f[(size_t)(n0 + row) * 128 + tc * 8 + j] =
                swishf(acc[i][j] + b2_s[tc * 8 + j]);
    }
}

__global__ __launch_bounds__(256) void k_norm() {
    __shared__ float mean_s[HID], rstd_s[HID];
    int b = blockIdx.x >> 9;
    if (threadIdx.x < 128) {
        float m = g_stats[b * 2 * HID + threadIdx.x] * (1.0f / (float)HW);
        float v = g_stats[b * 2 * HID + HID + threadIdx.x] * (1.0f / (float)HW) - m * m;
        mean_s[threadIdx.x] = m;
        rstd_s[threadIdx.x] = rsqrtf(v + EPSV);
    }
    __syncthreads();
    size_t base = (size_t)blockIdx.x * 1024;
#pragma unroll
    for (int k = 0; k < 4; ++k) {
        size_t i4 = base + threadIdx.x + k * 256;
        int j = ((int)(i4 & 31)) * 4;
        float4 v = ((const float4*)g_tmp)[i4];
        v.x = (v.x - mean_s[j + 0]) * rstd_s[j + 0];
        v.y = (v.y - mean_s[j + 1]) * rstd_s[j + 1];
        v.z = (v.z - mean_s[j + 2]) * rstd_s[j + 2];
        v.w = (v.w - mean_s[j + 3]) * rstd_s[j + 3];
        ((float4*)g_f)[i4] = v;
    }
}

__global__ __launch_bounds__(256, 2) void k_out(
    const float* __restrict__ inp, const float* __restrict__ W1,
    const float* __restrict__ b1, const float* __restrict__ W2,
    const float* __restrict__ b2, float* __restrict__ out) {
    extern __shared__ float sm[];
    float* f_s = sm;
    float* W1_s = f_s + 128 * 132;
    float* b1_s = W1_s + 128 * 64;
    float* W2_s = b1_s + 64;
    float* red_s = W2_s + 64;
    int tid = threadIdx.x;
    int n0 = blockIdx.x * 128, b = n0 / HW;
    for (int i = tid; i < 128 * 32; i += 256) {
        int c = i >> 5, q = i & 31;
        ((float4*)(f_s + c * 132))[q] = ((const float4*)(g_f + (size_t)(n0 + c) * 128))[q];
    }
    for (int i = tid; i < 128 * 16; i += 256)
        ((float4*)W1_s)[i] = ((const float4*)W1)[i];
    if (tid < 64) { b1_s[tid] = b1[tid]; W2_s[tid] = W2[tid]; }
    __syncthreads();
    int tc = tid & 7, tr = tid >> 3;
    float acc[4][8];
    ACC_ZERO(acc);
    gemm128<32>(f_s, 132, W1_s, 64, acc, tr, tc);
#pragma unroll
    for (int i = 0; i < 4; ++i) {
        float p = 0.0f;
#pragma unroll
        for (int j = 0; j < 8; ++j)
            p += swishf(acc[i][j] + b1_s[tc * 8 + j]) * W2_s[tc * 8 + j];
        red_s[(tr + 32 * i) * 8 + tc] = p;
    }
    __syncthreads();
    if (tid < 128) {
        float d = b2[0];
#pragma unroll
        for (int t = 0; t < 8; ++t) d += red_s[tid * 8 + t];
        int n = n0 + tid;
        out[n] = inp[b * NCH * HW + (n - b * HW)] + DTV * d;
    }
}

// ---------------- host launcher ----------------
extern "C" void kernel_launch(void* const* d_in, const int* in_sizes, int n_in,
                              void* d_out, int out_size) {
    const float* inp   = (const float*)d_in[0];
    const float* cp    = (const float*)d_in[1];
    const float* embW1 = (const float*)d_in[3];
    const float* embb1 = (const float*)d_in[4];
    const float* embW2 = (const float*)d_in[5];
    const float* embb2 = (const float*)d_in[6];
    const float* msg1W = (const float*)d_in[7];
    const float* msg1b = (const float*)d_in[8];
    const float* msg2W = (const float*)d_in[9];
    const float* msg2b = (const float*)d_in[10];
    const float* upd1W = (const float*)d_in[11];
    const float* upd1b = (const float*)d_in[12];
    const float* upd2W = (const float*)d_in[13];
    const float* upd2b = (const float*)d_in[14];
    const float* outW1 = (const float*)d_in[15];
    const float* outb1 = (const float*)d_in[16];
    const float* outW2 = (const float*)d_in[17];
    const float* outb2 = (const float*)d_in[18];
    float* out = (float*)d_out;

    const size_t smE = (size_t)(64 * 8 + 8 * 128 + 128 + 64 * 132 + 128 * 128 + 128) * 4;
    const size_t smO = (size_t)(128 * 132 + 128 * 64 + 64 + 64 + 128 * 8) * 4;
    const size_t smMA = 70144;
    const size_t smEG = 108832;

    cudaFuncSetAttribute(k_embed, cudaFuncAttributeMaxDynamicSharedMemorySize, (int)smE);
    cudaFuncSetAttribute(k_out, cudaFuncAttributeMaxDynamicSharedMemorySize, (int)smO);
    cudaFuncSetAttribute(k_msgA_mm, cudaFuncAttributeMaxDynamicSharedMemorySize, (int)smMA);
    cudaFuncSetAttribute(k_edge_mm, cudaFuncAttributeMaxDynamicSharedMemorySize, (int)smEG);

    k_embed<<<NN / 64, 256, smE>>>(inp, cp, embW1, embb1, embW2, embb2);
    for (int l = 0; l < NL; ++l) {
        k_msgA_mm<<<NN / 128, 256, smMA>>>(cp, msg1W, msg1b, l);
        k_edge_mm<<<NN / 128, 256, smEG>>>(inp, cp, msg1W, msg2W, msg2b,
                                           upd1W, upd1b, upd2W, upd2b, l);
        k_norm<<<2048, 256>>>();
    }
    k_out<<<NN / 128, 256, smO>>>(inp, outW1, outb1, outW2, outb2, out);
}

// round 9
// speedup vs baseline: 4.8459x; 1.0241x over previous
#include <cuda_runtime.h>
#include <cuda_fp16.h>
#include <cstdint>

#define HH 128
#define WW 128
#define HW 16384
#define NN 65536
#define HID 128
#define NL 6
#define NPRM 5
#define EPSV 1e-5f
#define DTV 0.1f
#define NCH 3
#define NBATCH 4
#define PS 68  // uint32 (half2) words per plane row
#define SBUF 1024  // floats per stats buffer

__device__ float g_f[(size_t)NN * HID];
__device__ __half g_Ah[(size_t)NN * HID];
__device__ __half g_Bh[(size_t)NN * HID];
__device__ float g_tmp[(size_t)NN * HID];
__device__ float g_stats[2 * SBUF];

__constant__ int c_dr[8] = {-1, -1, -1, 0, 0, 1, 1, 1};
__constant__ int c_dc[8] = {-1, 0, 1, -1, 1, -1, 0, 1};

__device__ __forceinline__ float swishf(float x) {
    return __fdividef(x, 1.0f + __expf(-x));
}
__device__ __forceinline__ float tsw(float x) {
    float h = 0.5f * x, th;
    asm("tanh.approx.f32 %0, %1;" : "=f"(th) : "f"(h));
    return h + h * th;
}
__device__ __forceinline__ __half2 u2h(uint32_t u) {
    return *reinterpret_cast<__half2*>(&u);
}
__device__ __forceinline__ uint32_t h2u(__half2 h) {
    return *reinterpret_cast<uint32_t*>(&h);
}
__device__ __forceinline__ __half2 tanh2(__half2 x) {
    uint32_t r;
    asm("tanh.approx.f16x2 %0, %1;" : "=r"(r) : "r"(h2u(x)));
    return u2h(r);
}
// packed swish of fp32 pair: m = h + h*tanh(h), h = x/2 ; returns half2
__device__ __forceinline__ __half2 psw(float x0, float x1) {
    __half2 h = __floats2half2_rn(0.5f * x0, 0.5f * x1);
    __half2 t = tanh2(h);
    return __hfma2(h, t, h);
}

// load weight W[k][n] (row-major 128x128) TRANSPOSED into plane Wt[n][k] (fp16)
__device__ void load_wt_h(uint32_t* Hw, const float* __restrict__ W, int tid) {
    __half* H = (__half*)Hw;
    for (int i = tid; i < 16384; i += 256) {
        int n = i & 127, k = i >> 7;
        H[n * (2 * PS) + k] = __float2half_rn(W[k * 128 + n]);
    }
}

// ---------------- fp16 GEMM (m16n8k16) ----------------
__device__ __forceinline__ void hmma(float* a_, uint32_t a0, uint32_t a1, uint32_t a2,
                                     uint32_t a3, uint32_t b0, uint32_t b1) {
    asm volatile(
        "mma.sync.aligned.m16n8k16.row.col.f32.f16.f16.f32 "
        "{%0,%1,%2,%3},{%4,%5,%6,%7},{%8,%9},{%0,%1,%2,%3};"
        : "+f"(a_[0]), "+f"(a_[1]), "+f"(a_[2]), "+f"(a_[3])
        : "r"(a0), "r"(a1), "r"(a2), "r"(a3), "r"(b0), "r"(b1));
}
#define ZERO444(a)                                                     \
    _Pragma("unroll") for (int _i = 0; _i < 4; ++_i)                   \
        _Pragma("unroll") for (int _j = 0; _j < 4; ++_j)               \
            _Pragma("unroll") for (int _q = 0; _q < 4; ++_q) a[_i][_j][_q] = 0.0f;

__device__ __forceinline__ void gemmh(const uint32_t* __restrict__ Ah,
                                      const uint32_t* __restrict__ Bh,
                                      float acc[4][4][4], int m0, int n0c, int g, int t) {
#pragma unroll 1
    for (int s = 0; s < 8; ++s) {
        const int kb = s * 8 + t;
        uint32_t bh[4][2];
#pragma unroll
        for (int nj = 0; nj < 4; ++nj) {
            const uint32_t* p = Bh + (n0c + 8 * nj + g) * PS + kb;
            bh[nj][0] = p[0];
            bh[nj][1] = p[4];
        }
#pragma unroll
        for (int mi = 0; mi < 4; ++mi) {
            const uint32_t* p = Ah + (m0 + 16 * mi + g) * PS + kb;
            uint32_t a0 = p[0], a1 = p[8 * PS], a2 = p[4], a3 = p[8 * PS + 4];
#pragma unroll
            for (int nj = 0; nj < 4; ++nj)
                hmma(acc[mi][nj], a0, a1, a2, a3, bh[nj][0], bh[nj][1]);
        }
    }
}

// ------ k_msgA_mm: (fused prev-layer norm) + A = f@W_t + pc, Bm = f@W_s ------
__global__ __launch_bounds__(256, 3) void k_msgA_mm(
    const float* __restrict__ cp, const float* __restrict__ msg1W,
    const float* __restrict__ msg1b, int l) {
    extern __shared__ char smem[];
    uint32_t* Fh = (uint32_t*)smem;             // 34816
    uint32_t* Wh = (uint32_t*)(smem + 34816);   // 34816
    float* pc_s = (float*)(smem + 69632);       // 512
    float* mean_s = (float*)(smem + 70144);     // 512
    float* rstd_s = (float*)(smem + 70656);     // 512 -> 71168

    const int tid = threadIdx.x, warp = tid >> 5, lane = tid & 31;
    const int g = lane >> 2, t = lane & 3;
    const int m0 = (warp >> 2) * 64, n0c = (warp & 3) * 32;
    const int nb0 = blockIdx.x << 7, b = nb0 >> 14;
    const float* Wl1 = msg1W + (size_t)l * 264 * 128;

    if (blockIdx.x == 0)  // zero THIS layer's stats buffer (edge will accumulate)
        for (int i = tid; i < SBUF; i += 256) g_stats[(l & 1) * SBUF + i] = 0.0f;
    if (tid < 128) {
        float s = msg1b[l * 128 + tid];
#pragma unroll
        for (int p = 0; p < NPRM; ++p)
            s = fmaf(cp[b * NPRM + p], Wl1[(259 + p) * 128 + tid], s);
        pc_s[tid] = s;
    }
    if (l > 0) {  // fused layernorm of previous layer's g_tmp
        if (tid < 128) {
            const float* st = g_stats + ((l - 1) & 1) * SBUF + b * 256;
            float m = st[tid] * (1.0f / (float)HW);
            float v = st[128 + tid] * (1.0f / (float)HW) - m * m;
            mean_s[tid] = m;
            rstd_s[tid] = rsqrtf(v + EPSV);
        }
        __syncthreads();
        for (int i = tid; i < 4096; i += 256) {
            int c = i >> 5, q = i & 31, j = q * 4;
            float4 v = *(const float4*)(g_tmp + (size_t)(nb0 + c) * 128 + j);
            v.x = (v.x - mean_s[j + 0]) * rstd_s[j + 0];
            v.y = (v.y - mean_s[j + 1]) * rstd_s[j + 1];
            v.z = (v.z - mean_s[j + 2]) * rstd_s[j + 2];
            v.w = (v.w - mean_s[j + 3]) * rstd_s[j + 3];
            *(float4*)(g_f + (size_t)(nb0 + c) * 128 + j) = v;  // edge reads this
            *(uint2*)(Fh + c * PS + 2 * q) = make_uint2(
                h2u(__floats2half2_rn(v.x, v.y)), h2u(__floats2half2_rn(v.z, v.w)));
        }
    } else {
        for (int i = tid; i < 4096; i += 256) {
            int c = i >> 5, q = i & 31;
            float4 fv = *(const float4*)(g_f + (size_t)(nb0 + c) * 128 + q * 4);
            *(uint2*)(Fh + c * PS + 2 * q) = make_uint2(
                h2u(__floats2half2_rn(fv.x, fv.y)), h2u(__floats2half2_rn(fv.z, fv.w)));
        }
    }
    load_wt_h(Wh, Wl1, tid);  // W_t rows 0..127
    __syncthreads();

    float acc[4][4][4];
    ZERO444(acc);
    gemmh(Fh, Wh, acc, m0, n0c, g, t);
#pragma unroll
    for (int mi = 0; mi < 4; ++mi) {
        int c0 = m0 + 16 * mi + g;
#pragma unroll
        for (int nj = 0; nj < 4; ++nj) {
            int col = n0c + 8 * nj + 2 * t;
            *(uint32_t*)(g_Ah + (size_t)(nb0 + c0) * 128 + col) =
                h2u(__floats2half2_rn(acc[mi][nj][0] + pc_s[col],
                                      acc[mi][nj][1] + pc_s[col + 1]));
            *(uint32_t*)(g_Ah + (size_t)(nb0 + c0 + 8) * 128 + col) =
                h2u(__floats2half2_rn(acc[mi][nj][2] + pc_s[col],
                                      acc[mi][nj][3] + pc_s[col + 1]));
        }
    }
    __syncthreads();
    load_wt_h(Wh, Wl1 + 128 * 128, tid);  // W_s rows 128..255
    __syncthreads();
    ZERO444(acc);
    gemmh(Fh, Wh, acc, m0, n0c, g, t);
#pragma unroll
    for (int mi = 0; mi < 4; ++mi) {
        int c0 = m0 + 16 * mi + g;
#pragma unroll
        for (int nj = 0; nj < 4; ++nj) {
            int col = n0c + 8 * nj + 2 * t;
            *(uint32_t*)(g_Bh + (size_t)(nb0 + c0) * 128 + col) =
                h2u(__floats2half2_rn(acc[mi][nj][0], acc[mi][nj][1]));
            *(uint32_t*)(g_Bh + (size_t)(nb0 + c0 + 8) * 128 + col) =
                h2u(__floats2half2_rn(acc[mi][nj][2], acc[mi][nj][3]));
        }
    }
}

// ------------- k_edge_mm: messages + agg + update MLP -------------
__global__ __launch_bounds__(256, 2) void k_edge_mm(
    const float* __restrict__ inp, const float* __restrict__ cp,
    const float* __restrict__ msg1W, const float* __restrict__ msg2W,
    const float* __restrict__ msg2b, const float* __restrict__ upd1W,
    const float* __restrict__ upd1b, const float* __restrict__ upd2W,
    const float* __restrict__ upd2b, int l) {
    extern __shared__ char smem[];
    uint32_t* Mh = (uint32_t*)smem;               // 34816
    uint32_t* Wh = (uint32_t*)(smem + 34816);     // 34816
    uint32_t* Ac = (uint32_t*)(smem + 69632);     // 34816 (A tile, half2)
    uint32_t* posW2 = (uint32_t*)(smem + 104448); // 2048
    uint32_t* wu2 = (uint32_t*)(smem + 106496);   // 256
    float* b2m_s = (float*)(smem + 106752);       // 512
    float* pcu_s = (float*)(smem + 107264);       // 512
    float* b2u_s = (float*)(smem + 107776);       // 512
    uint32_t* du2a = (uint32_t*)(smem + 108288);  // 8*128*4 = 4096
    float* cp_s = (float*)(smem + 112384);        // 32 -> total 112416
    float* stage = (float*)smem;                  // 128*132*4 = 67584 (late reuse)

    const int tid = threadIdx.x, warp = tid >> 5, lane = tid & 31;
    const int g = lane >> 2, t = lane & 3;
    const int m0 = (warp >> 2) * 64, n0c = (warp & 3) * 32;
    const int gr = blockIdx.x, b = gr >> 7, r = gr & 127, nb0 = gr << 7;
    const float* W1l = msg1W + (size_t)l * 264 * 128;

    if (tid < 8) cp_s[tid] = (tid < NPRM) ? cp[b * NPRM + tid] : 0.0f;
    if (tid < 128) b2m_s[tid] = msg2b[l * 128 + tid];
    if (tid < 64)
        wu2[tid] = h2u(__floats2half2_rn(W1l[256 * 128 + 2 * tid],
                                         W1l[256 * 128 + 2 * tid + 1]));
    __syncthreads();
    for (int i = tid; i < 512; i += 256) {  // posW half2: [d][64]
        int d = i >> 6, j = i & 63;
        float pdx = (float)(-c_dr[d]) * (1.0f / 127.0f) * cp_s[1];
        float pdy = (float)(-c_dc[d]) * (1.0f / 127.0f) * cp_s[0];
        float v0 = pdx * W1l[257 * 128 + 2 * j] + pdy * W1l[258 * 128 + 2 * j];
        float v1 = pdx * W1l[257 * 128 + 2 * j + 1] + pdy * W1l[258 * 128 + 2 * j + 1];
        posW2[i] = h2u(__floats2half2_rn(v0, v1));
    }
    for (int i = tid; i < 1024; i += 256) {  // du for ALL 8 directions upfront
        int d = i >> 7, c = i & 127;
        int n = nb0 + c, nb = n + c_dr[d] * WW + c_dc[d];
        nb = min(max(nb, 0), NN - 1);
        int bb = nb >> 14;
        float du = inp[b * NCH * HW + (n - b * HW)] -
                   inp[bb * NCH * HW + (nb - bb * HW)];
        du2a[i] = h2u(__half2half2(__float2half_rn(du)));
    }
    for (int i = tid; i < 4096; i += 256) {  // cache A tile (half2)
        int c = i >> 5, q = i & 31;
        *(uint2*)(Ac + c * PS + 2 * q) =
            *(const uint2*)(g_Ah + (size_t)(nb0 + c) * 128 + q * 4);
    }
    load_wt_h(Wh, msg2W + (size_t)l * 16384, tid);

    __half2 agg[4][4][2];
#pragma unroll
    for (int i = 0; i < 4; ++i)
#pragma unroll
        for (int j = 0; j < 4; ++j) {
            agg[i][j][0] = __float2half2_rn(0.0f);
            agg[i][j][1] = __float2half2_rn(0.0f);
        }

#pragma unroll 1
    for (int d = 0; d < 8; ++d) {
        const int dr = c_dr[d], dc = c_dc[d];
        if ((unsigned)(r + dr) >= (unsigned)HH) continue;
        __syncthreads();  // prior gemm reads done (first iter: smem fills done)
        for (int i = tid; i < 4096; i += 256) {  // M build, all half2
            int c = i >> 5, q = i & 31;
            int nb = nb0 + c + dr * WW + dc;
            nb = min(max(nb, 0), NN - 1);
            uint2 bm = *(const uint2*)(g_Bh + (size_t)nb * 128 + q * 4);
            uint2 av = *(const uint2*)(Ac + c * PS + 2 * q);
            __half2 hd = u2h(du2a[d * 128 + c]);
            __half2 half_c = __float2half2_rn(0.5f);
            __half2 s0 = __hadd2(__hadd2(u2h(av.x), u2h(bm.x)),
                                 __hfma2(hd, u2h(wu2[2 * q]), u2h(posW2[d * 64 + 2 * q])));
            __half2 s1 = __hadd2(__hadd2(u2h(av.y), u2h(bm.y)),
                                 __hfma2(hd, u2h(wu2[2 * q + 1]),
                                         u2h(posW2[d * 64 + 2 * q + 1])));
            __half2 h0 = __hmul2(s0, half_c), h1 = __hmul2(s1, half_c);
            __half2 t0 = tanh2(h0), t1 = tanh2(h1);
            *(uint2*)(Mh + c * PS + 2 * q) =
                make_uint2(h2u(__hfma2(h0, t0, h0)), h2u(__hfma2(h1, t1, h1)));
        }
        __syncthreads();
        float acc[4][4][4];
        ZERO444(acc);
        gemmh(Mh, Wh, acc, m0, n0c, g, t);
#pragma unroll
        for (int mi = 0; mi < 4; ++mi) {
            int c0 = m0 + 16 * mi + g;
            bool ok0 = (unsigned)(c0 + dc) < (unsigned)WW;
            bool ok1 = (unsigned)(c0 + 8 + dc) < (unsigned)WW;
#pragma unroll
            for (int nj = 0; nj < 4; ++nj) {
                int col = n0c + 8 * nj + 2 * t;
                if (ok0)
                    agg[mi][nj][0] = __hadd2(
                        agg[mi][nj][0],
                        psw(acc[mi][nj][0] + b2m_s[col], acc[mi][nj][1] + b2m_s[col + 1]));
                if (ok1)
                    agg[mi][nj][1] = __hadd2(
                        agg[mi][nj][1],
                        psw(acc[mi][nj][2] + b2m_s[col], acc[mi][nj][3] + b2m_s[col + 1]));
            }
        }
    }
    __syncthreads();  // last gemm done; Mh reusable

    // -------- update MLP --------
    const float* U1 = upd1W + (size_t)l * 261 * 128;
    {
        int crn = 1 + (r > 0) + (r < HH - 1);
#pragma unroll
        for (int mi = 0; mi < 4; ++mi) {
#pragma unroll
            for (int hh = 0; hh < 2; ++hh) {
                int c0 = m0 + 16 * mi + g + 8 * hh;
                float inv = 1.0f / (float)(crn * (1 + (c0 > 0) + (c0 < WW - 1)) - 1);
                __half2 inv2 = __float2half2_rn(inv);
#pragma unroll
                for (int nj = 0; nj < 4; ++nj)
                    Mh[c0 * PS + (n0c >> 1) + 4 * nj + t] =
                        h2u(__hmul2(agg[mi][nj][hh], inv2));
            }
        }
    }
    load_wt_h(Wh, U1 + 128 * 128, tid);  // U1 agg rows
    if (tid < 128) {
        float s = upd1b[l * 128 + tid];
#pragma unroll
        for (int p = 0; p < NPRM; ++p)
            s = fmaf(cp_s[p], U1[(256 + p) * 128 + tid], s);
        pcu_s[tid] = s;
        b2u_s[tid] = upd2b[l * 128 + tid];
    }
    __syncthreads();
    float acc2[4][4][4];
    ZERO444(acc2);
    gemmh(Mh, Wh, acc2, m0, n0c, g, t);
    __syncthreads();
    for (int i = tid; i < 4096; i += 256) {  // f -> Mh (fp16 hi)
        int c = i >> 5, q = i & 31;
        float4 fv = *(const float4*)(g_f + (size_t)(nb0 + c) * 128 + q * 4);
        *(uint2*)(Mh + c * PS + 2 * q) = make_uint2(
            h2u(__floats2half2_rn(fv.x, fv.y)), h2u(__floats2half2_rn(fv.z, fv.w)));
    }
    load_wt_h(Wh, U1, tid);  // U1 f rows
    __syncthreads();
    gemmh(Mh, Wh, acc2, m0, n0c, g, t);  // accumulate
    __syncthreads();
#pragma unroll
    for (int mi = 0; mi < 4; ++mi) {  // h1 = swish(acc2 + pcu) -> Mh
#pragma unroll
        for (int nj = 0; nj < 4; ++nj) {
            int col = n0c + 8 * nj + 2 * t;
            int c0 = m0 + 16 * mi + g;
            Mh[c0 * PS + (col >> 1)] =
                h2u(psw(acc2[mi][nj][0] + pcu_s[col], acc2[mi][nj][1] + pcu_s[col + 1]));
            Mh[(c0 + 8) * PS + (col >> 1)] =
                h2u(psw(acc2[mi][nj][2] + pcu_s[col], acc2[mi][nj][3] + pcu_s[col + 1]));
        }
    }
    load_wt_h(Wh, upd2W + (size_t)l * 16384, tid);  // U2
    __syncthreads();
    float acc3[4][4][4];
    ZERO444(acc3);
    gemmh(Mh, Wh, acc3, m0, n0c, g, t);
    __syncthreads();  // gemm done; stage may overwrite Mh/Wh

    // -------- residual + stores + layernorm stats --------
#pragma unroll
    for (int mi = 0; mi < 4; ++mi) {
#pragma unroll
        for (int half = 0; half < 2; ++half) {
            int c0 = m0 + 16 * mi + g + 8 * half;
#pragma unroll
            for (int nj = 0; nj < 4; ++nj) {
                int col = n0c + 8 * nj + 2 * t;
                float2 f2 = *(const float2*)(g_f + (size_t)(nb0 + c0) * 128 + col);
                float v0 = f2.x + tsw(acc3[mi][nj][2 * half + 0] + b2u_s[col]);
                float v1 = f2.y + tsw(acc3[mi][nj][2 * half + 1] + b2u_s[col + 1]);
                *(float2*)(g_tmp + (size_t)(nb0 + c0) * 128 + col) = make_float2(v0, v1);
                *(float2*)(stage + c0 * 132 + col) = make_float2(v0, v1);
            }
        }
    }
    __syncthreads();
    if (tid < 128) {
        float S = 0.0f, S2 = 0.0f;
#pragma unroll 4
        for (int gg = 0; gg < 128; ++gg) {
            float v = stage[gg * 132 + tid];
            S += v;
            S2 += v * v;
        }
        atomicAdd(&g_stats[(l & 1) * SBUF + b * 256 + tid], S);
        atomicAdd(&g_stats[(l & 1) * SBUF + b * 256 + 128 + tid], S2);
    }
}

// ================= fp32 kernels =================
#define ACC_ZERO(acc)                                                  \
    _Pragma("unroll") for (int _i = 0; _i < 4; ++_i)                   \
        _Pragma("unroll") for (int _j = 0; _j < 8; ++_j) acc[_i][_j] = 0.0f;

template <int RSTEP>
__device__ __forceinline__ void gemm128(const float* __restrict__ As, int lda,
                                        const float* __restrict__ Ws, int ldw,
                                        float acc[4][8], int tr, int tc) {
#pragma unroll 4
    for (int k4 = 0; k4 < 32; ++k4) {
        float4 a[4];
#pragma unroll
        for (int i = 0; i < 4; ++i)
            a[i] = *(const float4*)(As + (tr + i * RSTEP) * lda + k4 * 4);
        const float* wp = Ws + (k4 * 4) * ldw + tc * 8;
#pragma unroll
        for (int kk = 0; kk < 4; ++kk) {
            float4 b0 = *(const float4*)(wp + kk * ldw);
            float4 b1 = *(const float4*)(wp + kk * ldw + 4);
#pragma unroll
            for (int i = 0; i < 4; ++i) {
                float av = ((const float*)(a + i))[kk];
                acc[i][0] = fmaf(av, b0.x, acc[i][0]);
                acc[i][1] = fmaf(av, b0.y, acc[i][1]);
                acc[i][2] = fmaf(av, b0.z, acc[i][2]);
                acc[i][3] = fmaf(av, b0.w, acc[i][3]);
                acc[i][4] = fmaf(av, b1.x, acc[i][4]);
                acc[i][5] = fmaf(av, b1.y, acc[i][5]);
                acc[i][6] = fmaf(av, b1.z, acc[i][6]);
                acc[i][7] = fmaf(av, b1.w, acc[i][7]);
            }
        }
    }
}

__global__ __launch_bounds__(256, 2) void k_embed(
    const float* __restrict__ inp, const float* __restrict__ cp,
    const float* __restrict__ W1, const float* __restrict__ b1,
    const float* __restrict__ W2, const float* __restrict__ b2) {
    extern __shared__ float sm[];
    float* e_s = sm;
    float* W1_s = e_s + 64 * 8;
    float* b1_s = W1_s + 8 * 128;
    float* h1_s = b1_s + 128;
    float* W2_s = h1_s + 64 * 132;
    float* b2_s = W2_s + 128 * 128;
    int tid = threadIdx.x;
    int n0 = blockIdx.x * 64, b = n0 / HW;
    for (int i = tid; i < 8 * 128; i += 256) W1_s[i] = W1[i];
    if (tid < 128) { b1_s[tid] = b1[tid]; b2_s[tid] = b2[tid]; }
    for (int i = tid; i < 128 * 32; i += 256)
        ((float4*)W2_s)[i] = ((const float4*)W2)[i];
    if (tid < 64) {
        int n = n0 + tid, rc = n - b * HW;
        int r = rc >> 7, c = rc & 127;
        e_s[tid * 8 + 0] = inp[b * NCH * HW + rc];
        e_s[tid * 8 + 1] = (float)r * (1.0f / 127.0f) * cp[b * NPRM + 1];
        e_s[tid * 8 + 2] = (float)c * (1.0f / 127.0f) * cp[b * NPRM + 0];
#pragma unroll
        for (int p = 0; p < NPRM; ++p) e_s[tid * 8 + 3 + p] = cp[b * NPRM + p];
    }
    __syncthreads();
    int tc = tid & 15, tr = tid >> 4;
#pragma unroll
    for (int i = 0; i < 4; ++i) {
        int row = tr + 16 * i;
#pragma unroll
        for (int j = 0; j < 8; ++j) {
            float s = b1_s[tc * 8 + j];
#pragma unroll
            for (int k = 0; k < 8; ++k)
                s = fmaf(e_s[row * 8 + k], W1_s[k * 128 + tc * 8 + j], s);
            h1_s[row * 132 + tc * 8 + j] = swishf(s);
        }
    }
    __syncthreads();
    float acc[4][8];
    ACC_ZERO(acc);
    gemm128<16>(h1_s, 132, W2_s, 128, acc, tr, tc);
#pragma unroll
    for (int i = 0; i < 4; ++i) {
        int row = tr + 16 * i;
#pragma unroll
        for (int j = 0; j < 8; ++j)
            g_f[(size_t)(n0 + row) * 128 + tc * 8 + j] =
                swishf(acc[i][j] + b2_s[tc * 8 + j]);
    }
}

// k_out with fused final layernorm (stats buffer (NL-1)&1 = 1)
__global__ __launch_bounds__(256, 2) void k_out(
    const float* __restrict__ inp, const float* __restrict__ W1,
    const float* __restrict__ b1, const float* __restrict__ W2,
    const float* __restrict__ b2, float* __restrict__ out) {
    extern __shared__ float sm[];
    float* f_s = sm;                    // 16896
    float* W1_s = f_s + 128 * 132;      // 8192
    float* b1_s = W1_s + 128 * 64;      // 64
    float* W2_s = b1_s + 64;            // 64
    float* red_s = W2_s + 64;           // 1024
    float* mean_s = red_s + 128 * 8;    // 128
    float* rstd_s = mean_s + 128;       // 128
    int tid = threadIdx.x;
    int n0 = blockIdx.x * 128, b = n0 / HW;
    if (tid < 128) {
        const float* st = g_stats + ((NL - 1) & 1) * SBUF + b * 256;
        float m = st[tid] * (1.0f / (float)HW);
        float v = st[128 + tid] * (1.0f / (float)HW) - m * m;
        mean_s[tid] = m;
        rstd_s[tid] = rsqrtf(v + EPSV);
    }
    __syncthreads();
    for (int i = tid; i < 128 * 32; i += 256) {
        int c = i >> 5, q = i & 31, j = q * 4;
        float4 v = *(const float4*)(g_tmp + (size_t)(n0 + c) * 128 + j);
        v.x = (v.x - mean_s[j + 0]) * rstd_s[j + 0];
        v.y = (v.y - mean_s[j + 1]) * rstd_s[j + 1];
        v.z = (v.z - mean_s[j + 2]) * rstd_s[j + 2];
        v.w = (v.w - mean_s[j + 3]) * rstd_s[j + 3];
        ((float4*)(f_s + c * 132))[q] = v;
    }
    for (int i = tid; i < 128 * 16; i += 256)
        ((float4*)W1_s)[i] = ((const float4*)W1)[i];
    if (tid < 64) { b1_s[tid] = b1[tid]; W2_s[tid] = W2[tid]; }
    __syncthreads();
    int tc = tid & 7, tr = tid >> 3;
    float acc[4][8];
    ACC_ZERO(acc);
    gemm128<32>(f_s, 132, W1_s, 64, acc, tr, tc);
#pragma unroll
    for (int i = 0; i < 4; ++i) {
        float p = 0.0f;
#pragma unroll
        for (int j = 0; j < 8; ++j)
            p += swishf(acc[i][j] + b1_s[tc * 8 + j]) * W2_s[tc * 8 + j];
        red_s[(tr + 32 * i) * 8 + tc] = p;
    }
    __syncthreads();
    if (tid < 128) {
        float d = b2[0];
#pragma unroll
        for (int t = 0; t < 8; ++t) d += red_s[tid * 8 + t];
        int n = n0 + tid;
        out[n] = inp[b * NCH * HW + (n - b * HW)] + DTV * d;
    }
}

// ---------------- host launcher ----------------
extern "C" void kernel_launch(void* const* d_in, const int* in_sizes, int n_in,
                              void* d_out, int out_size) {
    const float* inp   = (const float*)d_in[0];
    const float* cp    = (const float*)d_in[1];
    const float* embW1 = (const float*)d_in[3];
    const float* embb1 = (const float*)d_in[4];
    const float* embW2 = (const float*)d_in[5];
    const float* embb2 = (const float*)d_in[6];
    const float* msg1W = (const float*)d_in[7];
    const float* msg1b = (const float*)d_in[8];
    const float* msg2W = (const float*)d_in[9];
    const float* msg2b = (const float*)d_in[10];
    const float* upd1W = (const float*)d_in[11];
    const float* upd1b = (const float*)d_in[12];
    const float* upd2W = (const float*)d_in[13];
    const float* upd2b = (const float*)d_in[14];
    const float* outW1 = (const float*)d_in[15];
    const float* outb1 = (const float*)d_in[16];
    const float* outW2 = (const float*)d_in[17];
    const float* outb2 = (const float*)d_in[18];
    float* out = (float*)d_out;

    const size_t smE = (size_t)(64 * 8 + 8 * 128 + 128 + 64 * 132 + 128 * 128 + 128) * 4;
    const size_t smO = (size_t)(128 * 132 + 128 * 64 + 64 + 64 + 128 * 8 + 256) * 4;
    const size_t smMA = 71168;
    const size_t smEG = 112416;

    cudaFuncSetAttribute(k_embed, cudaFuncAttributeMaxDynamicSharedMemorySize, (int)smE);
    cudaFuncSetAttribute(k_out, cudaFuncAttributeMaxDynamicSharedMemorySize, (int)smO);
    cudaFuncSetAttribute(k_msgA_mm, cudaFuncAttributeMaxDynamicSharedMemorySize, (int)smMA);
    cudaFuncSetAttribute(k_edge_mm, cudaFuncAttributeMaxDynamicSharedMemorySize, (int)smEG);

    k_embed<<<NN / 64, 256, smE>>>(inp, cp, embW1, embb1, embW2, embb2);
    for (int l = 0; l < NL; ++l) {
        k_msgA_mm<<<NN / 128, 256, smMA>>>(cp, msg1W, msg1b, l);
        k_edge_mm<<<NN / 128, 256, smEG>>>(inp, cp, msg1W, msg2W, msg2b,
                                           upd1W, upd1b, upd2W, upd2b, l);
    }
    k_out<<<NN / 128, 256, smO>>>(inp, outW1, outb1, outW2, outb2, out);
}

// round 10
// speedup vs baseline: 4.9038x; 1.0120x over previous
#include <cuda_runtime.h>
#include <cuda_fp16.h>
#include <cstdint>

#define HH 128
#define WW 128
#define HW 16384
#define NN 65536
#define HID 128
#define NL 6
#define NPRM 5
#define EPSV 1e-5f
#define DTV 0.1f
#define NCH 3
#define NBATCH 4
#define PS 68  // uint32 (half2) words per plane row (row stride 272B)
#define SBUF 1024

__device__ float g_f[(size_t)NN * HID];
__device__ __half g_Ah[(size_t)NN * HID];
__device__ __half g_Bh[(size_t)NN * HID];
__device__ float g_tmp[(size_t)NN * HID];
__device__ float g_stats[2 * SBUF];

__constant__ int c_dr[8] = {-1, -1, -1, 0, 0, 1, 1, 1};
__constant__ int c_dc[8] = {-1, 0, 1, -1, 1, -1, 0, 1};

__device__ __forceinline__ float swishf(float x) {
    return __fdividef(x, 1.0f + __expf(-x));
}
__device__ __forceinline__ float tsw(float x) {
    float h = 0.5f * x, th;
    asm("tanh.approx.f32 %0, %1;" : "=f"(th) : "f"(h));
    return h + h * th;
}
__device__ __forceinline__ __half2 u2h(uint32_t u) {
    return *reinterpret_cast<__half2*>(&u);
}
__device__ __forceinline__ uint32_t h2u(__half2 h) {
    return *reinterpret_cast<uint32_t*>(&h);
}
__device__ __forceinline__ __half2 tanh2(__half2 x) {
    uint32_t r;
    asm("tanh.approx.f16x2 %0, %1;" : "=r"(r) : "r"(h2u(x)));
    return u2h(r);
}
__device__ __forceinline__ __half2 psw(float x0, float x1) {
    __half2 h = __floats2half2_rn(0.5f * x0, 0.5f * x1);
    __half2 t = tanh2(h);
    return __hfma2(h, t, h);
}

// load weight W[k][n] (row-major 128x128) TRANSPOSED into plane Wt[n][k] (fp16)
__device__ void load_wt_h(uint32_t* Hw, const float* __restrict__ W, int tid) {
    __half* H = (__half*)Hw;
    for (int i = tid; i < 16384; i += 256) {
        int n = i & 127, k = i >> 7;
        H[n * (2 * PS) + k] = __float2half_rn(W[k * 128 + n]);
    }
}

// ---------------- fp16 GEMM (m16n8k16) with ldmatrix ----------------
__device__ __forceinline__ void hmma(float* a_, uint32_t a0, uint32_t a1, uint32_t a2,
                                     uint32_t a3, uint32_t b0, uint32_t b1) {
    asm volatile(
        "mma.sync.aligned.m16n8k16.row.col.f32.f16.f16.f32 "
        "{%0,%1,%2,%3},{%4,%5,%6,%7},{%8,%9},{%0,%1,%2,%3};"
        : "+f"(a_[0]), "+f"(a_[1]), "+f"(a_[2]), "+f"(a_[3])
        : "r"(a0), "r"(a1), "r"(a2), "r"(a3), "r"(b0), "r"(b1));
}
__device__ __forceinline__ void ldsm4(uint32_t* r, uint32_t addr) {
    asm volatile("ldmatrix.sync.aligned.m8n8.x4.shared.b16 {%0,%1,%2,%3}, [%4];"
                 : "=r"(r[0]), "=r"(r[1]), "=r"(r[2]), "=r"(r[3]) : "r"(addr));
}
__device__ __forceinline__ void ldsm2(uint32_t* r, uint32_t addr) {
    asm volatile("ldmatrix.sync.aligned.m8n8.x2.shared.b16 {%0,%1}, [%2];"
                 : "=r"(r[0]), "=r"(r[1]) : "r"(addr));
}
#define ZERO444(a)                                                     \
    _Pragma("unroll") for (int _i = 0; _i < 4; ++_i)                   \
        _Pragma("unroll") for (int _j = 0; _j < 4; ++_j)               \
            _Pragma("unroll") for (int _q = 0; _q < 4; ++_q) a[_i][_j][_q] = 0.0f;

// D[64x32] per warp. A planes [row][k] (PS stride), B planes Wt[n][k].
__device__ __forceinline__ void gemmh(const uint32_t* __restrict__ Ah,
                                      const uint32_t* __restrict__ Bh,
                                      float acc[4][4][4], int m0, int n0c, int lane) {
    // A x4: lanes 0-7 rows m+0..7 @k0, 8-15 rows m+8..15 @k0, 16-23 @k+8, 24-31 @k+8
    uint32_t abase = (uint32_t)__cvta_generic_to_shared(Ah) +
                     (uint32_t)(m0 + (lane & 15)) * 272 + ((lane >> 4) & 1) * 16;
    // B x2: lanes 0-7 n-rows @k0, lanes 8-15 same rows @k+8 (others ignored)
    uint32_t bbase = (uint32_t)__cvta_generic_to_shared(Bh) +
                     (uint32_t)(n0c + (lane & 7)) * 272 + ((lane >> 3) & 1) * 16;
#pragma unroll 1
    for (int s = 0; s < 8; ++s) {
        uint32_t bh[4][2];
#pragma unroll
        for (int nj = 0; nj < 4; ++nj)
            ldsm2(bh[nj], bbase + nj * (8 * 272) + s * 32);
#pragma unroll
        for (int mi = 0; mi < 4; ++mi) {
            uint32_t a[4];
            ldsm4(a, abase + mi * (16 * 272) + s * 32);
#pragma unroll
            for (int nj = 0; nj < 4; ++nj)
                hmma(acc[mi][nj], a[0], a[1], a[2], a[3], bh[nj][0], bh[nj][1]);
        }
    }
}

// ------ k_msgA_mm: (fused prev-layer norm) + A = f@W_t + pc, Bm = f@W_s ------
__global__ __launch_bounds__(256, 3) void k_msgA_mm(
    const float* __restrict__ cp, const float* __restrict__ msg1W,
    const float* __restrict__ msg1b, int l) {
    extern __shared__ char smem[];
    uint32_t* Fh = (uint32_t*)smem;             // 34816
    uint32_t* Wh = (uint32_t*)(smem + 34816);   // 34816
    float* pc_s = (float*)(smem + 69632);       // 512
    float* mean_s = (float*)(smem + 70144);     // 512
    float* rstd_s = (float*)(smem + 70656);     // 512 -> 71168

    const int tid = threadIdx.x, warp = tid >> 5, lane = tid & 31;
    const int g = lane >> 2, t = lane & 3;
    const int m0 = (warp >> 2) * 64, n0c = (warp & 3) * 32;
    const int nb0 = blockIdx.x << 7, b = nb0 >> 14;
    const float* Wl1 = msg1W + (size_t)l * 264 * 128;

    if (blockIdx.x == 0)
        for (int i = tid; i < SBUF; i += 256) g_stats[(l & 1) * SBUF + i] = 0.0f;
    if (tid < 128) {
        float s = msg1b[l * 128 + tid];
#pragma unroll
        for (int p = 0; p < NPRM; ++p)
            s = fmaf(cp[b * NPRM + p], Wl1[(259 + p) * 128 + tid], s);
        pc_s[tid] = s;
    }
    if (l > 0) {  // fused layernorm of previous layer's g_tmp
        if (tid < 128) {
            const float* st = g_stats + ((l - 1) & 1) * SBUF + b * 256;
            float m = st[tid] * (1.0f / (float)HW);
            float v = st[128 + tid] * (1.0f / (float)HW) - m * m;
            mean_s[tid] = m;
            rstd_s[tid] = rsqrtf(v + EPSV);
        }
        __syncthreads();
        for (int i = tid; i < 4096; i += 256) {
            int c = i >> 5, q = i & 31, j = q * 4;
            float4 v = *(const float4*)(g_tmp + (size_t)(nb0 + c) * 128 + j);
            v.x = (v.x - mean_s[j + 0]) * rstd_s[j + 0];
            v.y = (v.y - mean_s[j + 1]) * rstd_s[j + 1];
            v.z = (v.z - mean_s[j + 2]) * rstd_s[j + 2];
            v.w = (v.w - mean_s[j + 3]) * rstd_s[j + 3];
            *(float4*)(g_f + (size_t)(nb0 + c) * 128 + j) = v;  // edge reads this
            *(uint2*)(Fh + c * PS + 2 * q) = make_uint2(
                h2u(__floats2half2_rn(v.x, v.y)), h2u(__floats2half2_rn(v.z, v.w)));
        }
    } else {
        for (int i = tid; i < 4096; i += 256) {
            int c = i >> 5, q = i & 31;
            float4 fv = *(const float4*)(g_f + (size_t)(nb0 + c) * 128 + q * 4);
            *(uint2*)(Fh + c * PS + 2 * q) = make_uint2(
                h2u(__floats2half2_rn(fv.x, fv.y)), h2u(__floats2half2_rn(fv.z, fv.w)));
        }
    }
    load_wt_h(Wh, Wl1, tid);  // W_t rows 0..127
    __syncthreads();

    float acc[4][4][4];
    ZERO444(acc);
    gemmh(Fh, Wh, acc, m0, n0c, lane);
#pragma unroll
    for (int mi = 0; mi < 4; ++mi) {
        int c0 = m0 + 16 * mi + g;
#pragma unroll
        for (int nj = 0; nj < 4; ++nj) {
            int col = n0c + 8 * nj + 2 * t;
            *(uint32_t*)(g_Ah + (size_t)(nb0 + c0) * 128 + col) =
                h2u(__floats2half2_rn(acc[mi][nj][0] + pc_s[col],
                                      acc[mi][nj][1] + pc_s[col + 1]));
            *(uint32_t*)(g_Ah + (size_t)(nb0 + c0 + 8) * 128 + col) =
                h2u(__floats2half2_rn(acc[mi][nj][2] + pc_s[col],
                                      acc[mi][nj][3] + pc_s[col + 1]));
        }
    }
    __syncthreads();
    load_wt_h(Wh, Wl1 + 128 * 128, tid);  // W_s rows 128..255
    __syncthreads();
    ZERO444(acc);
    gemmh(Fh, Wh, acc, m0, n0c, lane);
#pragma unroll
    for (int mi = 0; mi < 4; ++mi) {
        int c0 = m0 + 16 * mi + g;
#pragma unroll
        for (int nj = 0; nj < 4; ++nj) {
            int col = n0c + 8 * nj + 2 * t;
            *(uint32_t*)(g_Bh + (size_t)(nb0 + c0) * 128 + col) =
                h2u(__floats2half2_rn(acc[mi][nj][0], acc[mi][nj][1]));
            *(uint32_t*)(g_Bh + (size_t)(nb0 + c0 + 8) * 128 + col) =
                h2u(__floats2half2_rn(acc[mi][nj][2], acc[mi][nj][3]));
        }
    }
}

// ------------- k_edge_mm: messages + agg + update MLP -------------
__global__ __launch_bounds__(256, 2) void k_edge_mm(
    const float* __restrict__ inp, const float* __restrict__ cp,
    const float* __restrict__ msg1W, const float* __restrict__ msg2W,
    const float* __restrict__ msg2b, const float* __restrict__ upd1W,
    const float* __restrict__ upd1b, const float* __restrict__ upd2W,
    const float* __restrict__ upd2b, int l) {
    extern __shared__ char smem[];
    uint32_t* Mh = (uint32_t*)smem;               // 34816
    uint32_t* Wh = (uint32_t*)(smem + 34816);     // 34816
    uint32_t* Ac = (uint32_t*)(smem + 69632);     // 34816
    uint32_t* posW2 = (uint32_t*)(smem + 104448); // 2048
    uint32_t* wu2 = (uint32_t*)(smem + 106496);   // 256
    float* b2m_s = (float*)(smem + 106752);       // 512
    float* pcu_s = (float*)(smem + 107264);       // 512
    float* b2u_s = (float*)(smem + 107776);       // 512
    uint32_t* du2a = (uint32_t*)(smem + 108288);  // 4096
    float* cp_s = (float*)(smem + 112384);        // 32 -> 112416
    float* stage = (float*)smem;                  // late reuse

    const int tid = threadIdx.x, warp = tid >> 5, lane = tid & 31;
    const int g = lane >> 2, t = lane & 3;
    const int m0 = (warp >> 2) * 64, n0c = (warp & 3) * 32;
    const int gr = blockIdx.x, b = gr >> 7, r = gr & 127, nb0 = gr << 7;
    const float* W1l = msg1W + (size_t)l * 264 * 128;

    if (tid < 8) cp_s[tid] = (tid < NPRM) ? cp[b * NPRM + tid] : 0.0f;
    if (tid < 128) b2m_s[tid] = msg2b[l * 128 + tid];
    if (tid < 64)
        wu2[tid] = h2u(__floats2half2_rn(W1l[256 * 128 + 2 * tid],
                                         W1l[256 * 128 + 2 * tid + 1]));
    __syncthreads();
    for (int i = tid; i < 512; i += 256) {  // posW half2: [d][64]
        int d = i >> 6, j = i & 63;
        float pdx = (float)(-c_dr[d]) * (1.0f / 127.0f) * cp_s[1];
        float pdy = (float)(-c_dc[d]) * (1.0f / 127.0f) * cp_s[0];
        float v0 = pdx * W1l[257 * 128 + 2 * j] + pdy * W1l[258 * 128 + 2 * j];
        float v1 = pdx * W1l[257 * 128 + 2 * j + 1] + pdy * W1l[258 * 128 + 2 * j + 1];
        posW2[i] = h2u(__floats2half2_rn(v0, v1));
    }
    for (int i = tid; i < 1024; i += 256) {  // du for ALL 8 directions upfront
        int d = i >> 7, c = i & 127;
        int n = nb0 + c, nb = n + c_dr[d] * WW + c_dc[d];
        nb = min(max(nb, 0), NN - 1);
        int bb = nb >> 14;
        float du = inp[b * NCH * HW + (n - b * HW)] -
                   inp[bb * NCH * HW + (nb - bb * HW)];
        du2a[i] = h2u(__half2half2(__float2half_rn(du)));
    }
    for (int i = tid; i < 4096; i += 256) {  // cache A tile (half2)
        int c = i >> 5, q = i & 31;
        *(uint2*)(Ac + c * PS + 2 * q) =
            *(const uint2*)(g_Ah + (size_t)(nb0 + c) * 128 + q * 4);
    }
    load_wt_h(Wh, msg2W + (size_t)l * 16384, tid);

    __half2 agg[4][4][2];
#pragma unroll
    for (int i = 0; i < 4; ++i)
#pragma unroll
        for (int j = 0; j < 4; ++j) {
            agg[i][j][0] = __float2half2_rn(0.0f);
            agg[i][j][1] = __float2half2_rn(0.0f);
        }

#pragma unroll 1
    for (int d = 0; d < 8; ++d) {
        const int dr = c_dr[d], dc = c_dc[d];
        if ((unsigned)(r + dr) >= (unsigned)HH) continue;
        __syncthreads();  // prior gemm reads done (first iter: smem fills done)
        for (int i = tid; i < 4096; i += 256) {  // M build, all half2
            int c = i >> 5, q = i & 31;
            int nb = nb0 + c + dr * WW + dc;
            nb = min(max(nb, 0), NN - 1);
            uint2 bm = *(const uint2*)(g_Bh + (size_t)nb * 128 + q * 4);
            uint2 av = *(const uint2*)(Ac + c * PS + 2 * q);
            __half2 hd = u2h(du2a[d * 128 + c]);
            __half2 half_c = __float2half2_rn(0.5f);
            __half2 s0 = __hadd2(__hadd2(u2h(av.x), u2h(bm.x)),
                                 __hfma2(hd, u2h(wu2[2 * q]), u2h(posW2[d * 64 + 2 * q])));
            __half2 s1 = __hadd2(__hadd2(u2h(av.y), u2h(bm.y)),
                                 __hfma2(hd, u2h(wu2[2 * q + 1]),
                                         u2h(posW2[d * 64 + 2 * q + 1])));
            __half2 h0 = __hmul2(s0, half_c), h1 = __hmul2(s1, half_c);
            __half2 t0 = tanh2(h0), t1 = tanh2(h1);
            *(uint2*)(Mh + c * PS + 2 * q) =
                make_uint2(h2u(__hfma2(h0, t0, h0)), h2u(__hfma2(h1, t1, h1)));
        }
        __syncthreads();
        float acc[4][4][4];
        ZERO444(acc);
        gemmh(Mh, Wh, acc, m0, n0c, lane);
#pragma unroll
        for (int mi = 0; mi < 4; ++mi) {
            int c0 = m0 + 16 * mi + g;
            bool ok0 = (unsigned)(c0 + dc) < (unsigned)WW;
            bool ok1 = (unsigned)(c0 + 8 + dc) < (unsigned)WW;
#pragma unroll
            for (int nj = 0; nj < 4; ++nj) {
                int col = n0c + 8 * nj + 2 * t;
                if (ok0)
                    agg[mi][nj][0] = __hadd2(
                        agg[mi][nj][0],
                        psw(acc[mi][nj][0] + b2m_s[col], acc[mi][nj][1] + b2m_s[col + 1]));
                if (ok1)
                    agg[mi][nj][1] = __hadd2(
                        agg[mi][nj][1],
                        psw(acc[mi][nj][2] + b2m_s[col], acc[mi][nj][3] + b2m_s[col + 1]));
            }
        }
    }
    __syncthreads();  // last gemm done; Mh reusable

    // -------- update MLP --------
    const float* U1 = upd1W + (size_t)l * 261 * 128;
    {
        int crn = 1 + (r > 0) + (r < HH - 1);
#pragma unroll
        for (int mi = 0; mi < 4; ++mi) {
#pragma unroll
            for (int hh = 0; hh < 2; ++hh) {
                int c0 = m0 + 16 * mi + g + 8 * hh;
                float inv = 1.0f / (float)(crn * (1 + (c0 > 0) + (c0 < WW - 1)) - 1);
                __half2 inv2 = __float2half2_rn(inv);
#pragma unroll
                for (int nj = 0; nj < 4; ++nj)
                    Mh[c0 * PS + (n0c >> 1) + 4 * nj + t] =
                        h2u(__hmul2(agg[mi][nj][hh], inv2));
            }
        }
    }
    load_wt_h(Wh, U1 + 128 * 128, tid);  // U1 agg rows
    if (tid < 128) {
        float s = upd1b[l * 128 + tid];
#pragma unroll
        for (int p = 0; p < NPRM; ++p)
            s = fmaf(cp_s[p], U1[(256 + p) * 128 + tid], s);
        pcu_s[tid] = s;
        b2u_s[tid] = upd2b[l * 128 + tid];
    }
    __syncthreads();
    float acc2[4][4][4];
    ZERO444(acc2);
    gemmh(Mh, Wh, acc2, m0, n0c, lane);
    __syncthreads();
    for (int i = tid; i < 4096; i += 256) {  // f -> Mh (fp16 hi)
        int c = i >> 5, q = i & 31;
        float4 fv = *(const float4*)(g_f + (size_t)(nb0 + c) * 128 + q * 4);
        *(uint2*)(Mh + c * PS + 2 * q) = make_uint2(
            h2u(__floats2half2_rn(fv.x, fv.y)), h2u(__floats2half2_rn(fv.z, fv.w)));
    }
    load_wt_h(Wh, U1, tid);  // U1 f rows
    __syncthreads();
    gemmh(Mh, Wh, acc2, m0, n0c, lane);  // accumulate
    __syncthreads();
#pragma unroll
    for (int mi = 0; mi < 4; ++mi) {  // h1 = swish(acc2 + pcu) -> Mh
#pragma unroll
        for (int nj = 0; nj < 4; ++nj) {
            int col = n0c + 8 * nj + 2 * t;
            int c0 = m0 + 16 * mi + g;
            Mh[c0 * PS + (col >> 1)] =
                h2u(psw(acc2[mi][nj][0] + pcu_s[col], acc2[mi][nj][1] + pcu_s[col + 1]));
            Mh[(c0 + 8) * PS + (col >> 1)] =
                h2u(psw(acc2[mi][nj][2] + pcu_s[col], acc2[mi][nj][3] + pcu_s[col + 1]));
        }
    }
    load_wt_h(Wh, upd2W + (size_t)l * 16384, tid);  // U2
    __syncthreads();
    float acc3[4][4][4];
    ZERO444(acc3);
    gemmh(Mh, Wh, acc3, m0, n0c, lane);
    __syncthreads();  // gemm done; stage may overwrite Mh/Wh

    // -------- residual + stores + layernorm stats --------
#pragma unroll
    for (int mi = 0; mi < 4; ++mi) {
#pragma unroll
        for (int half = 0; half < 2; ++half) {
            int c0 = m0 + 16 * mi + g + 8 * half;
#pragma unroll
            for (int nj = 0; nj < 4; ++nj) {
                int col = n0c + 8 * nj + 2 * t;
                float2 f2 = *(const float2*)(g_f + (size_t)(nb0 + c0) * 128 + col);
                float v0 = f2.x + tsw(acc3[mi][nj][2 * half + 0] + b2u_s[col]);
                float v1 = f2.y + tsw(acc3[mi][nj][2 * half + 1] + b2u_s[col + 1]);
                *(float2*)(g_tmp + (size_t)(nb0 + c0) * 128 + col) = make_float2(v0, v1);
                *(float2*)(stage + c0 * 132 + col) = make_float2(v0, v1);
            }
        }
    }
    __syncthreads();
    if (tid < 128) {
        float S = 0.0f, S2 = 0.0f;
#pragma unroll 4
        for (int gg = 0; gg < 128; ++gg) {
            float v = stage[gg * 132 + tid];
            S += v;
            S2 += v * v;
        }
        atomicAdd(&g_stats[(l & 1) * SBUF + b * 256 + tid], S);
        atomicAdd(&g_stats[(l & 1) * SBUF + b * 256 + 128 + tid], S2);
    }
}

// ================= fp32 kernels =================
#define ACC_ZERO(acc)                                                  \
    _Pragma("unroll") for (int _i = 0; _i < 4; ++_i)                   \
        _Pragma("unroll") for (int _j = 0; _j < 8; ++_j) acc[_i][_j] = 0.0f;

template <int RSTEP>
__device__ __forceinline__ void gemm128(const float* __restrict__ As, int lda,
                                        const float* __restrict__ Ws, int ldw,
                                        float acc[4][8], int tr, int tc) {
#pragma unroll 4
    for (int k4 = 0; k4 < 32; ++k4) {
        float4 a[4];
#pragma unroll
        for (int i = 0; i < 4; ++i)
            a[i] = *(const float4*)(As + (tr + i * RSTEP) * lda + k4 * 4);
        const float* wp = Ws + (k4 * 4) * ldw + tc * 8;
#pragma unroll
        for (int kk = 0; kk < 4; ++kk) {
            float4 b0 = *(const float4*)(wp + kk * ldw);
            float4 b1 = *(const float4*)(wp + kk * ldw + 4);
#pragma unroll
            for (int i = 0; i < 4; ++i) {
                float av = ((const float*)(a + i))[kk];
                acc[i][0] = fmaf(av, b0.x, acc[i][0]);
                acc[i][1] = fmaf(av, b0.y, acc[i][1]);
                acc[i][2] = fmaf(av, b0.z, acc[i][2]);
                acc[i][3] = fmaf(av, b0.w, acc[i][3]);
                acc[i][4] = fmaf(av, b1.x, acc[i][4]);
                acc[i][5] = fmaf(av, b1.y, acc[i][5]);
                acc[i][6] = fmaf(av, b1.z, acc[i][6]);
                acc[i][7] = fmaf(av, b1.w, acc[i][7]);
            }
        }
    }
}

__global__ __launch_bounds__(256, 2) void k_embed(
    const float* __restrict__ inp, const float* __restrict__ cp,
    const float* __restrict__ W1, const float* __restrict__ b1,
    const float* __restrict__ W2, const float* __restrict__ b2) {
    extern __shared__ float sm[];
    float* e_s = sm;
    float* W1_s = e_s + 64 * 8;
    float* b1_s = W1_s + 8 * 128;
    float* h1_s = b1_s + 128;
    float* W2_s = h1_s + 64 * 132;
    float* b2_s = W2_s + 128 * 128;
    int tid = threadIdx.x;
    int n0 = blockIdx.x * 64, b = n0 / HW;
    for (int i = tid; i < 8 * 128; i += 256) W1_s[i] = W1[i];
    if (tid < 128) { b1_s[tid] = b1[tid]; b2_s[tid] = b2[tid]; }
    for (int i = tid; i < 128 * 32; i += 256)
        ((float4*)W2_s)[i] = ((const float4*)W2)[i];
    if (tid < 64) {
        int n = n0 + tid, rc = n - b * HW;
        int r = rc >> 7, c = rc & 127;
        e_s[tid * 8 + 0] = inp[b * NCH * HW + rc];
        e_s[tid * 8 + 1] = (float)r * (1.0f / 127.0f) * cp[b * NPRM + 1];
        e_s[tid * 8 + 2] = (float)c * (1.0f / 127.0f) * cp[b * NPRM + 0];
#pragma unroll
        for (int p = 0; p < NPRM; ++p) e_s[tid * 8 + 3 + p] = cp[b * NPRM + p];
    }
    __syncthreads();
    int tc = tid & 15, tr = tid >> 4;
#pragma unroll
    for (int i = 0; i < 4; ++i) {
        int row = tr + 16 * i;
#pragma unroll
        for (int j = 0; j < 8; ++j) {
            float s = b1_s[tc * 8 + j];
#pragma unroll
            for (int k = 0; k < 8; ++k)
                s = fmaf(e_s[row * 8 + k], W1_s[k * 128 + tc * 8 + j], s);
            h1_s[row * 132 + tc * 8 + j] = swishf(s);
        }
    }
    __syncthreads();
    float acc[4][8];
    ACC_ZERO(acc);
    gemm128<16>(h1_s, 132, W2_s, 128, acc, tr, tc);
#pragma unroll
    for (int i = 0; i < 4; ++i) {
        int row = tr + 16 * i;
#pragma unroll
        for (int j = 0; j < 8; ++j)
            g_f[(size_t)(n0 + row) * 128 + tc * 8 + j] =
                swishf(acc[i][j] + b2_s[tc * 8 + j]);
    }
}

// k_out with fused final layernorm (stats buffer (NL-1)&1 = 1)
__global__ __launch_bounds__(256, 2) void k_out(
    const float* __restrict__ inp, const float* __restrict__ W1,
    const float* __restrict__ b1, const float* __restrict__ W2,
    const float* __restrict__ b2, float* __restrict__ out) {
    extern __shared__ float sm[];
    float* f_s = sm;
    float* W1_s = f_s + 128 * 132;
    float* b1_s = W1_s + 128 * 64;
    float* W2_s = b1_s + 64;
    float* red_s = W2_s + 64;
    float* mean_s = red_s + 128 * 8;
    float* rstd_s = mean_s + 128;
    int tid = threadIdx.x;
    int n0 = blockIdx.x * 128, b = n0 / HW;
    if (tid < 128) {
        const float* st = g_stats + ((NL - 1) & 1) * SBUF + b * 256;
        float m = st[tid] * (1.0f / (float)HW);
        float v = st[128 + tid] * (1.0f / (float)HW) - m * m;
        mean_s[tid] = m;
        rstd_s[tid] = rsqrtf(v + EPSV);
    }
    __syncthreads();
    for (int i = tid; i < 128 * 32; i += 256) {
        int c = i >> 5, q = i & 31, j = q * 4;
        float4 v = *(const float4*)(g_tmp + (size_t)(n0 + c) * 128 + j);
        v.x = (v.x - mean_s[j + 0]) * rstd_s[j + 0];
        v.y = (v.y - mean_s[j + 1]) * rstd_s[j + 1];
        v.z = (v.z - mean_s[j + 2]) * rstd_s[j + 2];
        v.w = (v.w - mean_s[j + 3]) * rstd_s[j + 3];
        ((float4*)(f_s + c * 132))[q] = v;
    }
    for (int i = tid; i < 128 * 16; i += 256)
        ((float4*)W1_s)[i] = ((const float4*)W1)[i];
    if (tid < 64) { b1_s[tid] = b1[tid]; W2_s[tid] = W2[tid]; }
    __syncthreads();
    int tc = tid & 7, tr = tid >> 3;
    float acc[4][8];
    ACC_ZERO(acc);
    gemm128<32>(f_s, 132, W1_s, 64, acc, tr, tc);
#pragma unroll
    for (int i = 0; i < 4; ++i) {
        float p = 0.0f;
#pragma unroll
        for (int j = 0; j < 8; ++j)
            p += swishf(acc[i][j] + b1_s[tc * 8 + j]) * W2_s[tc * 8 + j];
        red_s[(tr + 32 * i) * 8 + tc] = p;
    }
    __syncthreads();
    if (tid < 128) {
        float d = b2[0];
#pragma unroll
        for (int t = 0; t < 8; ++t) d += red_s[tid * 8 + t];
        int n = n0 + tid;
        out[n] = inp[b * NCH * HW + (n - b * HW)] + DTV * d;
    }
}

// ---------------- host launcher ----------------
extern "C" void kernel_launch(void* const* d_in, const int* in_sizes, int n_in,
                              void* d_out, int out_size) {
    const float* inp   = (const float*)d_in[0];
    const float* cp    = (const float*)d_in[1];
    const float* embW1 = (const float*)d_in[3];
    const float* embb1 = (const float*)d_in[4];
    const float* embW2 = (const float*)d_in[5];
    const float* embb2 = (const float*)d_in[6];
    const float* msg1W = (const float*)d_in[7];
    const float* msg1b = (const float*)d_in[8];
    const float* msg2W = (const float*)d_in[9];
    const float* msg2b = (const float*)d_in[10];
    const float* upd1W = (const float*)d_in[11];
    const float* upd1b = (const float*)d_in[12];
    const float* upd2W = (const float*)d_in[13];
    const float* upd2b = (const float*)d_in[14];
    const float* outW1 = (const float*)d_in[15];
    const float* outb1 = (const float*)d_in[16];
    const float* outW2 = (const float*)d_in[17];
    const float* outb2 = (const float*)d_in[18];
    float* out = (float*)d_out;

    const size_t smE = (size_t)(64 * 8 + 8 * 128 + 128 + 64 * 132 + 128 * 128 + 128) * 4;
    const size_t smO = (size_t)(128 * 132 + 128 * 64 + 64 + 64 + 128 * 8 + 256) * 4;
    const size_t smMA = 71168;
    const size_t smEG = 112416;

    cudaFuncSetAttribute(k_embed, cudaFuncAttributeMaxDynamicSharedMemorySize, (int)smE);
    cudaFuncSetAttribute(k_out, cudaFuncAttributeMaxDynamicSharedMemorySize, (int)smO);
    cudaFuncSetAttribute(k_msgA_mm, cudaFuncAttributeMaxDynamicSharedMemorySize, (int)smMA);
    cudaFuncSetAttribute(k_edge_mm, cudaFuncAttributeMaxDynamicSharedMemorySize, (int)smEG);

    k_embed<<<NN / 64, 256, smE>>>(inp, cp, embW1, embb1, embW2, embb2);
    for (int l = 0; l < NL; ++l) {
        k_msgA_mm<<<NN / 128, 256, smMA>>>(cp, msg1W, msg1b, l);
        k_edge_mm<<<NN / 128, 256, smEG>>>(inp, cp, msg1W, msg2W, msg2b,
                                           upd1W, upd1b, upd2W, upd2b, l);
    }
    k_out<<<NN / 128, 256, smO>>>(inp, outW1, outb1, outW2, outb2, out);
}

// round 11
// speedup vs baseline: 5.4535x; 1.1121x over previous
#include <cuda_runtime.h>
#include <cuda_fp16.h>
#include <cstdint>

#define HH 128
#define WW 128
#define HW 16384
#define NN 65536
#define HID 128
#define NL 6
#define NPRM 5
#define EPSV 1e-5f
#define DTV 0.1f
#define NCH 3
#define NBATCH 4
#define PS 68  // uint32 (half2) words per plane row (row stride 272B)
#define SBUF 1024
#define WTHALVES 17408  // 128 rows * 136 halves per transposed weight plane

__device__ float g_f[(size_t)NN * HID];
__device__ __half g_Ah[(size_t)NN * HID];
__device__ __half g_Bh[(size_t)NN * HID];
__device__ float g_tmp[(size_t)NN * HID];
__device__ float g_stats[2 * SBUF];
__device__ __half g_wth[(size_t)36 * WTHALVES];  // 6 layers x 6 matrices

__constant__ int c_dr[8] = {-1, -1, -1, 0, 0, 1, 1, 1};
__constant__ int c_dc[8] = {-1, 0, 1, -1, 1, -1, 0, 1};

__device__ __forceinline__ float swishf(float x) {
    return __fdividef(x, 1.0f + __expf(-x));
}
__device__ __forceinline__ float tsw(float x) {
    float h = 0.5f * x, th;
    asm("tanh.approx.f32 %0, %1;" : "=f"(th) : "f"(h));
    return h + h * th;
}
__device__ __forceinline__ __half2 u2h(uint32_t u) {
    return *reinterpret_cast<__half2*>(&u);
}
__device__ __forceinline__ uint32_t h2u(__half2 h) {
    return *reinterpret_cast<uint32_t*>(&h);
}
__device__ __forceinline__ __half2 tanh2(__half2 x) {
    uint32_t r;
    asm("tanh.approx.f16x2 %0, %1;" : "=r"(r) : "r"(h2u(x)));
    return u2h(r);
}
__device__ __forceinline__ __half2 psw(float x0, float x1) {
    __half2 h = __floats2half2_rn(0.5f * x0, 0.5f * x1);
    __half2 t = tanh2(h);
    return __hfma2(h, t, h);
}

// ---- one-time weight transpose: W[k][n] fp32 -> Wt[n][k] fp16 (global) ----
__global__ void k_prep(const float* __restrict__ msg1W,
                       const float* __restrict__ msg2W,
                       const float* __restrict__ upd1W,
                       const float* __restrict__ upd2W) {
    int m_idx = blockIdx.x, l = m_idx / 6, m = m_idx % 6;
    const float* W;
    switch (m) {
        case 0: W = msg1W + (size_t)l * 264 * 128; break;              // msg1 W_t
        case 1: W = msg1W + (size_t)l * 264 * 128 + 128 * 128; break;  // msg1 W_s
        case 2: W = msg2W + (size_t)l * 16384; break;                  // msg2
        case 3: W = upd1W + (size_t)l * 261 * 128 + 128 * 128; break;  // U1 agg
        case 4: W = upd1W + (size_t)l * 261 * 128; break;              // U1 f
        default: W = upd2W + (size_t)l * 16384; break;                 // U2
    }
    __half* H = g_wth + (size_t)m_idx * WTHALVES;
    for (int i = threadIdx.x; i < 16384; i += 256) {
        int n = i & 127, k = i >> 7;
        H[n * 136 + k] = __float2half_rn(W[k * 128 + n]);
    }
}
// block-level: straight uint4 copy of a pre-transposed plane into smem
__device__ __forceinline__ void copy_wt(uint32_t* Hw, int mat, int tid) {
    const uint4* s = (const uint4*)(g_wth + (size_t)mat * WTHALVES);
    uint4* d = (uint4*)Hw;
    for (int i = tid; i < 2176; i += 256) d[i] = s[i];
}

// ---------------- fp16 GEMM (m16n8k16) with ldmatrix ----------------
__device__ __forceinline__ void hmma(float* a_, uint32_t a0, uint32_t a1, uint32_t a2,
                                     uint32_t a3, uint32_t b0, uint32_t b1) {
    asm volatile(
        "mma.sync.aligned.m16n8k16.row.col.f32.f16.f16.f32 "
        "{%0,%1,%2,%3},{%4,%5,%6,%7},{%8,%9},{%0,%1,%2,%3};"
        : "+f"(a_[0]), "+f"(a_[1]), "+f"(a_[2]), "+f"(a_[3])
        : "r"(a0), "r"(a1), "r"(a2), "r"(a3), "r"(b0), "r"(b1));
}
__device__ __forceinline__ void ldsm4(uint32_t* r, uint32_t addr) {
    asm volatile("ldmatrix.sync.aligned.m8n8.x4.shared.b16 {%0,%1,%2,%3}, [%4];"
                 : "=r"(r[0]), "=r"(r[1]), "=r"(r[2]), "=r"(r[3]) : "r"(addr));
}
__device__ __forceinline__ void ldsm2(uint32_t* r, uint32_t addr) {
    asm volatile("ldmatrix.sync.aligned.m8n8.x2.shared.b16 {%0,%1}, [%2];"
                 : "=r"(r[0]), "=r"(r[1]) : "r"(addr));
}
#define ZERO444(a)                                                     \
    _Pragma("unroll") for (int _i = 0; _i < 4; ++_i)                   \
        _Pragma("unroll") for (int _j = 0; _j < 4; ++_j)               \
            _Pragma("unroll") for (int _q = 0; _q < 4; ++_q) a[_i][_j][_q] = 0.0f;

__device__ __forceinline__ void gemmh(const uint32_t* __restrict__ Ah,
                                      const uint32_t* __restrict__ Bh,
                                      float acc[4][4][4], int m0, int n0c, int lane) {
    uint32_t abase = (uint32_t)__cvta_generic_to_shared(Ah) +
                     (uint32_t)(m0 + (lane & 15)) * 272 + ((lane >> 4) & 1) * 16;
    uint32_t bbase = (uint32_t)__cvta_generic_to_shared(Bh) +
                     (uint32_t)(n0c + (lane & 7)) * 272 + ((lane >> 3) & 1) * 16;
#pragma unroll 1
    for (int s = 0; s < 8; ++s) {
        uint32_t bh[4][2];
#pragma unroll
        for (int nj = 0; nj < 4; ++nj)
            ldsm2(bh[nj], bbase + nj * (8 * 272) + s * 32);
#pragma unroll
        for (int mi = 0; mi < 4; ++mi) {
            uint32_t a[4];
            ldsm4(a, abase + mi * (16 * 272) + s * 32);
#pragma unroll
            for (int nj = 0; nj < 4; ++nj)
                hmma(acc[mi][nj], a[0], a[1], a[2], a[3], bh[nj][0], bh[nj][1]);
        }
    }
}

// ------ k_msgA_mm: (fused prev-layer norm) + A = f@W_t + pc, Bm = f@W_s ------
__global__ __launch_bounds__(256, 3) void k_msgA_mm(
    const float* __restrict__ cp, const float* __restrict__ msg1W,
    const float* __restrict__ msg1b, int l) {
    extern __shared__ char smem[];
    uint32_t* Fh = (uint32_t*)smem;             // 34816
    uint32_t* Wh = (uint32_t*)(smem + 34816);   // 34816
    float* pc_s = (float*)(smem + 69632);       // 512
    float* mean_s = (float*)(smem + 70144);     // 512
    float* rstd_s = (float*)(smem + 70656);     // 512 -> 71168

    const int tid = threadIdx.x, warp = tid >> 5, lane = tid & 31;
    const int g = lane >> 2, t = lane & 3;
    const int m0 = (warp >> 2) * 64, n0c = (warp & 3) * 32;
    const int nb0 = blockIdx.x << 7, b = nb0 >> 14;
    const float* Wl1 = msg1W + (size_t)l * 264 * 128;

    if (blockIdx.x == 0)
        for (int i = tid; i < SBUF; i += 256) g_stats[(l & 1) * SBUF + i] = 0.0f;
    if (tid < 128) {
        float s = msg1b[l * 128 + tid];
#pragma unroll
        for (int p = 0; p < NPRM; ++p)
            s = fmaf(cp[b * NPRM + p], Wl1[(259 + p) * 128 + tid], s);
        pc_s[tid] = s;
    }
    if (l > 0) {  // fused layernorm of previous layer's g_tmp
        if (tid < 128) {
            const float* st = g_stats + ((l - 1) & 1) * SBUF + b * 256;
            float m = st[tid] * (1.0f / (float)HW);
            float v = st[128 + tid] * (1.0f / (float)HW) - m * m;
            mean_s[tid] = m;
            rstd_s[tid] = rsqrtf(v + EPSV);
        }
        __syncthreads();
        for (int i = tid; i < 4096; i += 256) {
            int c = i >> 5, q = i & 31, j = q * 4;
            float4 v = *(const float4*)(g_tmp + (size_t)(nb0 + c) * 128 + j);
            v.x = (v.x - mean_s[j + 0]) * rstd_s[j + 0];
            v.y = (v.y - mean_s[j + 1]) * rstd_s[j + 1];
            v.z = (v.z - mean_s[j + 2]) * rstd_s[j + 2];
            v.w = (v.w - mean_s[j + 3]) * rstd_s[j + 3];
            *(float4*)(g_f + (size_t)(nb0 + c) * 128 + j) = v;  // edge reads this
            *(uint2*)(Fh + c * PS + 2 * q) = make_uint2(
                h2u(__floats2half2_rn(v.x, v.y)), h2u(__floats2half2_rn(v.z, v.w)));
        }
    } else {
        for (int i = tid; i < 4096; i += 256) {
            int c = i >> 5, q = i & 31;
            float4 fv = *(const float4*)(g_f + (size_t)(nb0 + c) * 128 + q * 4);
            *(uint2*)(Fh + c * PS + 2 * q) = make_uint2(
                h2u(__floats2half2_rn(fv.x, fv.y)), h2u(__floats2half2_rn(fv.z, fv.w)));
        }
    }
    copy_wt(Wh, l * 6 + 0, tid);  // W_t
    __syncthreads();

    float acc[4][4][4];
    ZERO444(acc);
    gemmh(Fh, Wh, acc, m0, n0c, lane);
#pragma unroll
    for (int mi = 0; mi < 4; ++mi) {
        int c0 = m0 + 16 * mi + g;
#pragma unroll
        for (int nj = 0; nj < 4; ++nj) {
            int col = n0c + 8 * nj + 2 * t;
            *(uint32_t*)(g_Ah + (size_t)(nb0 + c0) * 128 + col) =
                h2u(__floats2half2_rn(acc[mi][nj][0] + pc_s[col],
                                      acc[mi][nj][1] + pc_s[col + 1]));
            *(uint32_t*)(g_Ah + (size_t)(nb0 + c0 + 8) * 128 + col) =
                h2u(__floats2half2_rn(acc[mi][nj][2] + pc_s[col],
                                      acc[mi][nj][3] + pc_s[col + 1]));
        }
    }
    __syncthreads();
    copy_wt(Wh, l * 6 + 1, tid);  // W_s
    __syncthreads();
    ZERO444(acc);
    gemmh(Fh, Wh, acc, m0, n0c, lane);
#pragma unroll
    for (int mi = 0; mi < 4; ++mi) {
        int c0 = m0 + 16 * mi + g;
#pragma unroll
        for (int nj = 0; nj < 4; ++nj) {
            int col = n0c + 8 * nj + 2 * t;
            *(uint32_t*)(g_Bh + (size_t)(nb0 + c0) * 128 + col) =
                h2u(__floats2half2_rn(acc[mi][nj][0], acc[mi][nj][1]));
            *(uint32_t*)(g_Bh + (size_t)(nb0 + c0 + 8) * 128 + col) =
                h2u(__floats2half2_rn(acc[mi][nj][2], acc[mi][nj][3]));
        }
    }
}

// ------------- k_edge_mm: messages + agg + update MLP -------------
__global__ __launch_bounds__(256, 2) void k_edge_mm(
    const float* __restrict__ inp, const float* __restrict__ cp,
    const float* __restrict__ msg1W, const float* __restrict__ msg2b,
    const float* __restrict__ upd1W, const float* __restrict__ upd1b,
    const float* __restrict__ upd2b, int l) {
    extern __shared__ char smem[];
    uint32_t* Mh = (uint32_t*)smem;               // 34816
    uint32_t* Wh = (uint32_t*)(smem + 34816);     // 34816
    uint32_t* Ac = (uint32_t*)(smem + 69632);     // 34816
    uint32_t* posW2 = (uint32_t*)(smem + 104448); // 2048
    uint32_t* wu2 = (uint32_t*)(smem + 106496);   // 256
    float* b2m_s = (float*)(smem + 106752);       // 512
    float* pcu_s = (float*)(smem + 107264);       // 512
    float* b2u_s = (float*)(smem + 107776);       // 512
    uint32_t* du2a = (uint32_t*)(smem + 108288);  // 4096
    float* cp_s = (float*)(smem + 112384);        // 32 -> 112416
    float* stage = (float*)smem;                  // late reuse

    const int tid = threadIdx.x, warp = tid >> 5, lane = tid & 31;
    const int g = lane >> 2, t = lane & 3;
    const int m0 = (warp >> 2) * 64, n0c = (warp & 3) * 32;
    const int gr = blockIdx.x, b = gr >> 7, r = gr & 127, nb0 = gr << 7;
    const float* W1l = msg1W + (size_t)l * 264 * 128;

    if (tid < 8) cp_s[tid] = (tid < NPRM) ? cp[b * NPRM + tid] : 0.0f;
    if (tid < 128) b2m_s[tid] = msg2b[l * 128 + tid];
    if (tid < 64)
        wu2[tid] = h2u(__floats2half2_rn(W1l[256 * 128 + 2 * tid],
                                         W1l[256 * 128 + 2 * tid + 1]));
    __syncthreads();
    for (int i = tid; i < 512; i += 256) {  // posW half2: [d][64]
        int d = i >> 6, j = i & 63;
        float pdx = (float)(-c_dr[d]) * (1.0f / 127.0f) * cp_s[1];
        float pdy = (float)(-c_dc[d]) * (1.0f / 127.0f) * cp_s[0];
        float v0 = pdx * W1l[257 * 128 + 2 * j] + pdy * W1l[258 * 128 + 2 * j];
        float v1 = pdx * W1l[257 * 128 + 2 * j + 1] + pdy * W1l[258 * 128 + 2 * j + 1];
        posW2[i] = h2u(__floats2half2_rn(v0, v1));
    }
    for (int i = tid; i < 1024; i += 256) {  // du for ALL 8 directions upfront
        int d = i >> 7, c = i & 127;
        int n = nb0 + c, nb = n + c_dr[d] * WW + c_dc[d];
        nb = min(max(nb, 0), NN - 1);
        int bb = nb >> 14;
        float du = inp[b * NCH * HW + (n - b * HW)] -
                   inp[bb * NCH * HW + (nb - bb * HW)];
        du2a[i] = h2u(__half2half2(__float2half_rn(du)));
    }
    for (int i = tid; i < 4096; i += 256) {  // cache A tile (half2)
        int c = i >> 5, q = i & 31;
        *(uint2*)(Ac + c * PS + 2 * q) =
            *(const uint2*)(g_Ah + (size_t)(nb0 + c) * 128 + q * 4);
    }
    copy_wt(Wh, l * 6 + 2, tid);  // msg2W

    __half2 agg[4][4][2];
#pragma unroll
    for (int i = 0; i < 4; ++i)
#pragma unroll
        for (int j = 0; j < 4; ++j) {
            agg[i][j][0] = __float2half2_rn(0.0f);
            agg[i][j][1] = __float2half2_rn(0.0f);
        }

#pragma unroll 1
    for (int d = 0; d < 8; ++d) {
        const int dr = c_dr[d], dc = c_dc[d];
        if ((unsigned)(r + dr) >= (unsigned)HH) continue;
        __syncthreads();  // prior gemm reads done (first iter: smem fills done)
        for (int i = tid; i < 4096; i += 256) {  // M build, all half2
            int c = i >> 5, q = i & 31;
            int nb = nb0 + c + dr * WW + dc;
            nb = min(max(nb, 0), NN - 1);
            uint2 bm = *(const uint2*)(g_Bh + (size_t)nb * 128 + q * 4);
            uint2 av = *(const uint2*)(Ac + c * PS + 2 * q);
            __half2 hd = u2h(du2a[d * 128 + c]);
            __half2 half_c = __float2half2_rn(0.5f);
            __half2 s0 = __hadd2(__hadd2(u2h(av.x), u2h(bm.x)),
                                 __hfma2(hd, u2h(wu2[2 * q]), u2h(posW2[d * 64 + 2 * q])));
            __half2 s1 = __hadd2(__hadd2(u2h(av.y), u2h(bm.y)),
                                 __hfma2(hd, u2h(wu2[2 * q + 1]),
                                         u2h(posW2[d * 64 + 2 * q + 1])));
            __half2 h0 = __hmul2(s0, half_c), h1 = __hmul2(s1, half_c);
            __half2 t0 = tanh2(h0), t1 = tanh2(h1);
            *(uint2*)(Mh + c * PS + 2 * q) =
                make_uint2(h2u(__hfma2(h0, t0, h0)), h2u(__hfma2(h1, t1, h1)));
        }
        __syncthreads();
        float acc[4][4][4];
        ZERO444(acc);
        gemmh(Mh, Wh, acc, m0, n0c, lane);
#pragma unroll
        for (int mi = 0; mi < 4; ++mi) {
            int c0 = m0 + 16 * mi + g;
            bool ok0 = (unsigned)(c0 + dc) < (unsigned)WW;
            bool ok1 = (unsigned)(c0 + 8 + dc) < (unsigned)WW;
#pragma unroll
            for (int nj = 0; nj < 4; ++nj) {
                int col = n0c + 8 * nj + 2 * t;
                if (ok0)
                    agg[mi][nj][0] = __hadd2(
                        agg[mi][nj][0],
                        psw(acc[mi][nj][0] + b2m_s[col], acc[mi][nj][1] + b2m_s[col + 1]));
                if (ok1)
                    agg[mi][nj][1] = __hadd2(
                        agg[mi][nj][1],
                        psw(acc[mi][nj][2] + b2m_s[col], acc[mi][nj][3] + b2m_s[col + 1]));
            }
        }
    }
    __syncthreads();  // last gemm done; Mh reusable

    // -------- update MLP --------
    const float* U1 = upd1W + (size_t)l * 261 * 128;
    {
        int crn = 1 + (r > 0) + (r < HH - 1);
#pragma unroll
        for (int mi = 0; mi < 4; ++mi) {
#pragma unroll
            for (int hh = 0; hh < 2; ++hh) {
                int c0 = m0 + 16 * mi + g + 8 * hh;
                float inv = 1.0f / (float)(crn * (1 + (c0 > 0) + (c0 < WW - 1)) - 1);
                __half2 inv2 = __float2half2_rn(inv);
#pragma unroll
                for (int nj = 0; nj < 4; ++nj)
                    Mh[c0 * PS + (n0c >> 1) + 4 * nj + t] =
                        h2u(__hmul2(agg[mi][nj][hh], inv2));
            }
        }
    }
    copy_wt(Wh, l * 6 + 3, tid);  // U1 agg rows
    if (tid < 128) {
        float s = upd1b[l * 128 + tid];
#pragma unroll
        for (int p = 0; p < NPRM; ++p)
            s = fmaf(cp_s[p], U1[(256 + p) * 128 + tid], s);
        pcu_s[tid] = s;
        b2u_s[tid] = upd2b[l * 128 + tid];
    }
    __syncthreads();
    float acc2[4][4][4];
    ZERO444(acc2);
    gemmh(Mh, Wh, acc2, m0, n0c, lane);
    __syncthreads();
    for (int i = tid; i < 4096; i += 256) {  // f -> Mh (fp16 hi)
        int c = i >> 5, q = i & 31;
        float4 fv = *(const float4*)(g_f + (size_t)(nb0 + c) * 128 + q * 4);
        *(uint2*)(Mh + c * PS + 2 * q) = make_uint2(
            h2u(__floats2half2_rn(fv.x, fv.y)), h2u(__floats2half2_rn(fv.z, fv.w)));
    }
    copy_wt(Wh, l * 6 + 4, tid);  // U1 f rows
    __syncthreads();
    gemmh(Mh, Wh, acc2, m0, n0c, lane);  // accumulate
    __syncthreads();
#pragma unroll
    for (int mi = 0; mi < 4; ++mi) {  // h1 = swish(acc2 + pcu) -> Mh
#pragma unroll
        for (int nj = 0; nj < 4; ++nj) {
            int col = n0c + 8 * nj + 2 * t;
            int c0 = m0 + 16 * mi + g;
            Mh[c0 * PS + (col >> 1)] =
                h2u(psw(acc2[mi][nj][0] + pcu_s[col], acc2[mi][nj][1] + pcu_s[col + 1]));
            Mh[(c0 + 8) * PS + (col >> 1)] =
                h2u(psw(acc2[mi][nj][2] + pcu_s[col], acc2[mi][nj][3] + pcu_s[col + 1]));
        }
    }
    copy_wt(Wh, l * 6 + 5, tid);  // U2
    __syncthreads();
    float acc3[4][4][4];
    ZERO444(acc3);
    gemmh(Mh, Wh, acc3, m0, n0c, lane);
    __syncthreads();  // gemm done; stage may overwrite Mh/Wh

    // -------- residual + stores + layernorm stats --------
#pragma unroll
    for (int mi = 0; mi < 4; ++mi) {
#pragma unroll
        for (int half = 0; half < 2; ++half) {
            int c0 = m0 + 16 * mi + g + 8 * half;
#pragma unroll
            for (int nj = 0; nj < 4; ++nj) {
                int col = n0c + 8 * nj + 2 * t;
                float2 f2 = *(const float2*)(g_f + (size_t)(nb0 + c0) * 128 + col);
                float v0 = f2.x + tsw(acc3[mi][nj][2 * half + 0] + b2u_s[col]);
                float v1 = f2.y + tsw(acc3[mi][nj][2 * half + 1] + b2u_s[col + 1]);
                *(float2*)(g_tmp + (size_t)(nb0 + c0) * 128 + col) = make_float2(v0, v1);
                *(float2*)(stage + c0 * 132 + col) = make_float2(v0, v1);
            }
        }
    }
    __syncthreads();
    if (tid < 128) {
        float S = 0.0f, S2 = 0.0f;
#pragma unroll 4
        for (int gg = 0; gg < 128; ++gg) {
            float v = stage[gg * 132 + tid];
            S += v;
            S2 += v * v;
        }
        atomicAdd(&g_stats[(l & 1) * SBUF + b * 256 + tid], S);
        atomicAdd(&g_stats[(l & 1) * SBUF + b * 256 + 128 + tid], S2);
    }
}

// ================= fp32 kernels =================
#define ACC_ZERO(acc)                                                  \
    _Pragma("unroll") for (int _i = 0; _i < 4; ++_i)                   \
        _Pragma("unroll") for (int _j = 0; _j < 8; ++_j) acc[_i][_j] = 0.0f;

template <int RSTEP>
__device__ __forceinline__ void gemm128(const float* __restrict__ As, int lda,
                                        const float* __restrict__ Ws, int ldw,
                                        float acc[4][8], int tr, int tc) {
#pragma unroll 4
    for (int k4 = 0; k4 < 32; ++k4) {
        float4 a[4];
#pragma unroll
        for (int i = 0; i < 4; ++i)
            a[i] = *(const float4*)(As + (tr + i * RSTEP) * lda + k4 * 4);
        const float* wp = Ws + (k4 * 4) * ldw + tc * 8;
#pragma unroll
        for (int kk = 0; kk < 4; ++kk) {
            float4 b0 = *(const float4*)(wp + kk * ldw);
            float4 b1 = *(const float4*)(wp + kk * ldw + 4);
#pragma unroll
            for (int i = 0; i < 4; ++i) {
                float av = ((const float*)(a + i))[kk];
                acc[i][0] = fmaf(av, b0.x, acc[i][0]);
                acc[i][1] = fmaf(av, b0.y, acc[i][1]);
                acc[i][2] = fmaf(av, b0.z, acc[i][2]);
                acc[i][3] = fmaf(av, b0.w, acc[i][3]);
                acc[i][4] = fmaf(av, b1.x, acc[i][4]);
                acc[i][5] = fmaf(av, b1.y, acc[i][5]);
                acc[i][6] = fmaf(av, b1.z, acc[i][6]);
                acc[i][7] = fmaf(av, b1.w, acc[i][7]);
            }
        }
    }
}

__global__ __launch_bounds__(256, 2) void k_embed(
    const float* __restrict__ inp, const float* __restrict__ cp,
    const float* __restrict__ W1, const float* __restrict__ b1,
    const float* __restrict__ W2, const float* __restrict__ b2) {
    extern __shared__ float sm[];
    float* e_s = sm;
    float* W1_s = e_s + 64 * 8;
    float* b1_s = W1_s + 8 * 128;
    float* h1_s = b1_s + 128;
    float* W2_s = h1_s + 64 * 132;
    float* b2_s = W2_s + 128 * 128;
    int tid = threadIdx.x;
    int n0 = blockIdx.x * 64, b = n0 / HW;
    for (int i = tid; i < 8 * 128; i += 256) W1_s[i] = W1[i];
    if (tid < 128) { b1_s[tid] = b1[tid]; b2_s[tid] = b2[tid]; }
    for (int i = tid; i < 128 * 32; i += 256)
        ((float4*)W2_s)[i] = ((const float4*)W2)[i];
    if (tid < 64) {
        int n = n0 + tid, rc = n - b * HW;
        int r = rc >> 7, c = rc & 127;
        e_s[tid * 8 + 0] = inp[b * NCH * HW + rc];
        e_s[tid * 8 + 1] = (float)r * (1.0f / 127.0f) * cp[b * NPRM + 1];
        e_s[tid * 8 + 2] = (float)c * (1.0f / 127.0f) * cp[b * NPRM + 0];
#pragma unroll
        for (int p = 0; p < NPRM; ++p) e_s[tid * 8 + 3 + p] = cp[b * NPRM + p];
    }
    __syncthreads();
    int tc = tid & 15, tr = tid >> 4;
#pragma unroll
    for (int i = 0; i < 4; ++i) {
        int row = tr + 16 * i;
#pragma unroll
        for (int j = 0; j < 8; ++j) {
            float s = b1_s[tc * 8 + j];
#pragma unroll
            for (int k = 0; k < 8; ++k)
                s = fmaf(e_s[row * 8 + k], W1_s[k * 128 + tc * 8 + j], s);
            h1_s[row * 132 + tc * 8 + j] = swishf(s);
        }
    }
    __syncthreads();
    float acc[4][8];
    ACC_ZERO(acc);
    gemm128<16>(h1_s, 132, W2_s, 128, acc, tr, tc);
#pragma unroll
    for (int i = 0; i < 4; ++i) {
        int row = tr + 16 * i;
#pragma unroll
        for (int j = 0; j < 8; ++j)
            g_f[(size_t)(n0 + row) * 128 + tc * 8 + j] =
                swishf(acc[i][j] + b2_s[tc * 8 + j]);
    }
}

// k_out with fused final layernorm (stats buffer (NL-1)&1 = 1)
__global__ __launch_bounds__(256, 2) void k_out(
    const float* __restrict__ inp, const float* __restrict__ W1,
    const float* __restrict__ b1, const float* __restrict__ W2,
    const float* __restrict__ b2, float* __restrict__ out) {
    extern __shared__ float sm[];
    float* f_s = sm;
    float* W1_s = f_s + 128 * 132;
    float* b1_s = W1_s + 128 * 64;
    float* W2_s = b1_s + 64;
    float* red_s = W2_s + 64;
    float* mean_s = red_s + 128 * 8;
    float* rstd_s = mean_s + 128;
    int tid = threadIdx.x;
    int n0 = blockIdx.x * 128, b = n0 / HW;
    if (tid < 128) {
        const float* st = g_stats + ((NL - 1) & 1) * SBUF + b * 256;
        float m = st[tid] * (1.0f / (float)HW);
        float v = st[128 + tid] * (1.0f / (float)HW) - m * m;
        mean_s[tid] = m;
        rstd_s[tid] = rsqrtf(v + EPSV);
    }
    __syncthreads();
    for (int i = tid; i < 128 * 32; i += 256) {
        int c = i >> 5, q = i & 31, j = q * 4;
        float4 v = *(const float4*)(g_tmp + (size_t)(n0 + c) * 128 + j);
        v.x = (v.x - mean_s[j + 0]) * rstd_s[j + 0];
        v.y = (v.y - mean_s[j + 1]) * rstd_s[j + 1];
        v.z = (v.z - mean_s[j + 2]) * rstd_s[j + 2];
        v.w = (v.w - mean_s[j + 3]) * rstd_s[j + 3];
        ((float4*)(f_s + c * 132))[q] = v;
    }
    for (int i = tid; i < 128 * 16; i += 256)
        ((float4*)W1_s)[i] = ((const float4*)W1)[i];
    if (tid < 64) { b1_s[tid] = b1[tid]; W2_s[tid] = W2[tid]; }
    __syncthreads();
    int tc = tid & 7, tr = tid >> 3;
    float acc[4][8];
    ACC_ZERO(acc);
    gemm128<32>(f_s, 132, W1_s, 64, acc, tr, tc);
#pragma unroll
    for (int i = 0; i < 4; ++i) {
        float p = 0.0f;
#pragma unroll
        for (int j = 0; j < 8; ++j)
            p += swishf(acc[i][j] + b1_s[tc * 8 + j]) * W2_s[tc * 8 + j];
        red_s[(tr + 32 * i) * 8 + tc] = p;
    }
    __syncthreads();
    if (tid < 128) {
        float d = b2[0];
#pragma unroll
        for (int t = 0; t < 8; ++t) d += red_s[tid * 8 + t];
        int n = n0 + tid;
        out[n] = inp[b * NCH * HW + (n - b * HW)] + DTV * d;
    }
}

// ---------------- host launcher ----------------
extern "C" void kernel_launch(void* const* d_in, const int* in_sizes, int n_in,
                              void* d_out, int out_size) {
    const float* inp   = (const float*)d_in[0];
    const float* cp    = (const float*)d_in[1];
    const float* embW1 = (const float*)d_in[3];
    const float* embb1 = (const float*)d_in[4];
    const float* embW2 = (const float*)d_in[5];
    const float* embb2 = (const float*)d_in[6];
    const float* msg1W = (const float*)d_in[7];
    const float* msg1b = (const float*)d_in[8];
    const float* msg2W = (const float*)d_in[9];
    const float* msg2b = (const float*)d_in[10];
    const float* upd1W = (const float*)d_in[11];
    const float* upd1b = (const float*)d_in[12];
    const float* upd2W = (const float*)d_in[13];
    const float* upd2b = (const float*)d_in[14];
    const float* outW1 = (const float*)d_in[15];
    const float* outb1 = (const float*)d_in[16];
    const float* outW2 = (const float*)d_in[17];
    const float* outb2 = (const float*)d_in[18];
    float* out = (float*)d_out;

    const size_t smE = (size_t)(64 * 8 + 8 * 128 + 128 + 64 * 132 + 128 * 128 + 128) * 4;
    const size_t smO = (size_t)(128 * 132 + 128 * 64 + 64 + 64 + 128 * 8 + 256) * 4;
    const size_t smMA = 71168;
    const size_t smEG = 112416;

    cudaFuncSetAttribute(k_embed, cudaFuncAttributeMaxDynamicSharedMemorySize, (int)smE);
    cudaFuncSetAttribute(k_out, cudaFuncAttributeMaxDynamicSharedMemorySize, (int)smO);
    cudaFuncSetAttribute(k_msgA_mm, cudaFuncAttributeMaxDynamicSharedMemorySize, (int)smMA);
    cudaFuncSetAttribute(k_edge_mm, cudaFuncAttributeMaxDynamicSharedMemorySize, (int)smEG);

    k_prep<<<36, 256>>>(msg1W, msg2W, upd1W, upd2W);
    k_embed<<<NN / 64, 256, smE>>>(inp, cp, embW1, embb1, embW2, embb2);
    for (int l = 0; l < NL; ++l) {
        k_msgA_mm<<<NN / 128, 256, smMA>>>(cp, msg1W, msg1b, l);
        k_edge_mm<<<NN / 128, 256, smEG>>>(inp, cp, msg1W, msg2b,
                                           upd1W, upd1b, upd2b, l);
    }
    k_out<<<NN / 128, 256, smO>>>(inp, outW1, outb1, outW2, outb2, out);
}

// round 13
// speedup vs baseline: 6.0870x; 1.1162x over previous
#include <cuda_runtime.h>
#include <cuda_fp16.h>
#include <cstdint>

#define HH 128
#define WW 128
#define HW 16384
#define NN 65536
#define HID 128
#define NL 6
#define NPRM 5
#define EPSV 1e-5f
#define DTV 0.1f
#define NCH 3
#define NBATCH 4
#define PS 68  // uint32 (half2) words per plane row (row stride 272B)
#define SBUF 1024
#define WTHALVES 17408  // 128 rows * 136 halves per transposed weight plane

__device__ float g_f[(size_t)NN * HID];
__device__ __half g_Ah[(size_t)NN * HID];
__device__ __half g_Bh[(size_t)NN * HID];
__device__ float g_tmp[(size_t)NN * HID];
__device__ float g_stats[2 * SBUF];
__device__ __half g_wth[(size_t)36 * WTHALVES];  // 6 layers x 6 matrices

__constant__ int c_dr[8] = {-1, -1, -1, 0, 0, 1, 1, 1};
__constant__ int c_dc[8] = {-1, 0, 1, -1, 1, -1, 0, 1};

__device__ __forceinline__ float swishf(float x) {
    return __fdividef(x, 1.0f + __expf(-x));
}
__device__ __forceinline__ float tsw(float x) {
    float h = 0.5f * x, th;
    asm("tanh.approx.f32 %0, %1;" : "=f"(th) : "f"(h));
    return h + h * th;
}
__device__ __forceinline__ __half2 u2h(uint32_t u) {
    return *reinterpret_cast<__half2*>(&u);
}
__device__ __forceinline__ uint32_t h2u(__half2 h) {
    return *reinterpret_cast<uint32_t*>(&h);
}
__device__ __forceinline__ __half2 tanh2(__half2 x) {
    uint32_t r;
    asm("tanh.approx.f16x2 %0, %1;" : "=r"(r) : "r"(h2u(x)));
    return u2h(r);
}
__device__ __forceinline__ __half2 psw(float x0, float x1) {
    __half2 h = __floats2half2_rn(0.5f * x0, 0.5f * x1);
    __half2 t = tanh2(h);
    return __hfma2(h, t, h);
}
// half2 swish: x*sigmoid(x) = h + h*tanh(h), h = x/2
__device__ __forceinline__ __half2 psw2(__half2 x) {
    __half2 h = __hmul2(x, __float2half2_rn(0.5f));
    __half2 t = tanh2(h);
    return __hfma2(h, t, h);
}

// ---- one-time weight transpose: W[k][n] fp32 -> Wt[n][k] fp16 (global) ----
__global__ void k_prep(const float* __restrict__ msg1W,
                       const float* __restrict__ msg2W,
                       const float* __restrict__ upd1W,
                       const float* __restrict__ upd2W) {
    int m_idx = blockIdx.x, l = m_idx / 6, m = m_idx % 6;
    const float* W;
    switch (m) {
        case 0: W = msg1W + (size_t)l * 264 * 128; break;              // msg1 W_t
        case 1: W = msg1W + (size_t)l * 264 * 128 + 128 * 128; break;  // msg1 W_s
        case 2: W = msg2W + (size_t)l * 16384; break;                  // msg2
        case 3: W = upd1W + (size_t)l * 261 * 128 + 128 * 128; break;  // U1 agg
        case 4: W = upd1W + (size_t)l * 261 * 128; break;              // U1 f
        default: W = upd2W + (size_t)l * 16384; break;                 // U2
    }
    __half* H = g_wth + (size_t)m_idx * WTHALVES;
    for (int i = threadIdx.x; i < 16384; i += 256) {
        int n = i & 127, k = i >> 7;
        H[n * 136 + k] = __float2half_rn(W[k * 128 + n]);
    }
}
__device__ __forceinline__ void copy_wt(uint32_t* Hw, int mat, int tid) {
    const uint4* s = (const uint4*)(g_wth + (size_t)mat * WTHALVES);
    uint4* d = (uint4*)Hw;
    for (int i = tid; i < 2176; i += 256) d[i] = s[i];
}

// ---------------- fp16 GEMMs (m16n8k16) with ldmatrix ----------------
__device__ __forceinline__ void hmma(float* a_, uint32_t a0, uint32_t a1, uint32_t a2,
                                     uint32_t a3, uint32_t b0, uint32_t b1) {
    asm volatile(
        "mma.sync.aligned.m16n8k16.row.col.f32.f16.f16.f32 "
        "{%0,%1,%2,%3},{%4,%5,%6,%7},{%8,%9},{%0,%1,%2,%3};"
        : "+f"(a_[0]), "+f"(a_[1]), "+f"(a_[2]), "+f"(a_[3])
        : "r"(a0), "r"(a1), "r"(a2), "r"(a3), "r"(b0), "r"(b1));
}
// f16-accumulator variant: d = {rows c0 half2, rows c0+8 half2}
__device__ __forceinline__ void hmma16(uint32_t* d, uint32_t a0, uint32_t a1,
                                       uint32_t a2, uint32_t a3, uint32_t b0,
                                       uint32_t b1) {
    asm volatile(
        "mma.sync.aligned.m16n8k16.row.col.f16.f16.f16.f16 "
        "{%0,%1},{%2,%3,%4,%5},{%6,%7},{%0,%1};"
        : "+r"(d[0]), "+r"(d[1])
        : "r"(a0), "r"(a1), "r"(a2), "r"(a3), "r"(b0), "r"(b1));
}
__device__ __forceinline__ void ldsm4(uint32_t* r, uint32_t addr) {
    asm volatile("ldmatrix.sync.aligned.m8n8.x4.shared.b16 {%0,%1,%2,%3}, [%4];"
                 : "=r"(r[0]), "=r"(r[1]), "=r"(r[2]), "=r"(r[3]) : "r"(addr));
}
__device__ __forceinline__ void ldsm2(uint32_t* r, uint32_t addr) {
    asm volatile("ldmatrix.sync.aligned.m8n8.x2.shared.b16 {%0,%1}, [%2];"
                 : "=r"(r[0]), "=r"(r[1]) : "r"(addr));
}
#define ZERO444(a)                                                     \
    _Pragma("unroll") for (int _i = 0; _i < 4; ++_i)                   \
        _Pragma("unroll") for (int _j = 0; _j < 4; ++_j)               \
            _Pragma("unroll") for (int _q = 0; _q < 4; ++_q) a[_i][_j][_q] = 0.0f;
#define ZERO442(a)                                                     \
    _Pragma("unroll") for (int _i = 0; _i < 4; ++_i)                   \
        _Pragma("unroll") for (int _j = 0; _j < 4; ++_j)               \
            _Pragma("unroll") for (int _q = 0; _q < 2; ++_q) a[_i][_j][_q] = 0u;

// fp32-acc GEMM (update path)
__device__ __forceinline__ void gemmh(const uint32_t* __restrict__ Ah,
                                      const uint32_t* __restrict__ Bh,
                                      float acc[4][4][4], int m0, int n0c, int lane) {
    uint32_t abase = (uint32_t)__cvta_generic_to_shared(Ah) +
                     (uint32_t)(m0 + (lane & 15)) * 272 + ((lane >> 4) & 1) * 16;
    uint32_t bbase = (uint32_t)__cvta_generic_to_shared(Bh) +
                     (uint32_t)(n0c + (lane & 7)) * 272 + ((lane >> 3) & 1) * 16;
#pragma unroll 1
    for (int s = 0; s < 8; ++s) {
        uint32_t bh[4][2];
#pragma unroll
        for (int nj = 0; nj < 4; ++nj)
            ldsm2(bh[nj], bbase + nj * (8 * 272) + s * 32);
#pragma unroll
        for (int mi = 0; mi < 4; ++mi) {
            uint32_t a[4];
            ldsm4(a, abase + mi * (16 * 272) + s * 32);
#pragma unroll
            for (int nj = 0; nj < 4; ++nj)
                hmma(acc[mi][nj], a[0], a[1], a[2], a[3], bh[nj][0], bh[nj][1]);
        }
    }
}
// f16-acc GEMM (message path; lower reg pressure, unrolled x2)
__device__ __forceinline__ void gemmh16(const uint32_t* __restrict__ Ah,
                                        const uint32_t* __restrict__ Bh,
                                        uint32_t accd[4][4][2], int m0, int n0c,
                                        int lane) {
    uint32_t abase = (uint32_t)__cvta_generic_to_shared(Ah) +
                     (uint32_t)(m0 + (lane & 15)) * 272 + ((lane >> 4) & 1) * 16;
    uint32_t bbase = (uint32_t)__cvta_generic_to_shared(Bh) +
                     (uint32_t)(n0c + (lane & 7)) * 272 + ((lane >> 3) & 1) * 16;
#pragma unroll 2
    for (int s = 0; s < 8; ++s) {
        uint32_t bh[4][2];
#pragma unroll
        for (int nj = 0; nj < 4; ++nj)
            ldsm2(bh[nj], bbase + nj * (8 * 272) + s * 32);
#pragma unroll
        for (int mi = 0; mi < 4; ++mi) {
            uint32_t a[4];
            ldsm4(a, abase + mi * (16 * 272) + s * 32);
#pragma unroll
            for (int nj = 0; nj < 4; ++nj)
                hmma16(accd[mi][nj], a[0], a[1], a[2], a[3], bh[nj][0], bh[nj][1]);
        }
    }
}

// ------ k_msgA_mm: (fused prev-layer norm) + A = f@W_t + pc, Bm = f@W_s ------
__global__ __launch_bounds__(256, 3) void k_msgA_mm(
    const float* __restrict__ cp, const float* __restrict__ msg1W,
    const float* __restrict__ msg1b, int l) {
    extern __shared__ char smem[];
    uint32_t* Fh = (uint32_t*)smem;             // 34816
    uint32_t* Wh = (uint32_t*)(smem + 34816);   // 34816
    uint32_t* pc2_s = (uint32_t*)(smem + 69632); // 256
    float* mean_s = (float*)(smem + 70144);     // 512
    float* rstd_s = (float*)(smem + 70656);     // 512 -> 71168

    const int tid = threadIdx.x, warp = tid >> 5, lane = tid & 31;
    const int g = lane >> 2, t = lane & 3;
    const int m0 = (warp >> 2) * 64, n0c = (warp & 3) * 32;
    const int nb0 = blockIdx.x << 7, b = nb0 >> 14;
    const float* Wl1 = msg1W + (size_t)l * 264 * 128;

    if (blockIdx.x == 0)
        for (int i = tid; i < SBUF; i += 256) g_stats[(l & 1) * SBUF + i] = 0.0f;
    if (tid < 64) {
        float s0 = msg1b[l * 128 + 2 * tid], s1 = msg1b[l * 128 + 2 * tid + 1];
#pragma unroll
        for (int p = 0; p < NPRM; ++p) {
            float cpv = cp[b * NPRM + p];
            s0 = fmaf(cpv, Wl1[(259 + p) * 128 + 2 * tid], s0);
            s1 = fmaf(cpv, Wl1[(259 + p) * 128 + 2 * tid + 1], s1);
        }
        pc2_s[tid] = h2u(__floats2half2_rn(s0, s1));
    }
    if (l > 0) {  // fused layernorm of previous layer's g_tmp
        if (tid < 128) {
            const float* st = g_stats + ((l - 1) & 1) * SBUF + b * 256;
            float m = st[tid] * (1.0f / (float)HW);
            float v = st[128 + tid] * (1.0f / (float)HW) - m * m;
            mean_s[tid] = m;
            rstd_s[tid] = rsqrtf(v + EPSV);
        }
        __syncthreads();
        for (int i = tid; i < 4096; i += 256) {
            int c = i >> 5, q = i & 31, j = q * 4;
            float4 v = *(const float4*)(g_tmp + (size_t)(nb0 + c) * 128 + j);
            v.x = (v.x - mean_s[j + 0]) * rstd_s[j + 0];
            v.y = (v.y - mean_s[j + 1]) * rstd_s[j + 1];
            v.z = (v.z - mean_s[j + 2]) * rstd_s[j + 2];
            v.w = (v.w - mean_s[j + 3]) * rstd_s[j + 3];
            *(float4*)(g_f + (size_t)(nb0 + c) * 128 + j) = v;  // edge reads this
            *(uint2*)(Fh + c * PS + 2 * q) = make_uint2(
                h2u(__floats2half2_rn(v.x, v.y)), h2u(__floats2half2_rn(v.z, v.w)));
        }
    } else {
        for (int i = tid; i < 4096; i += 256) {
            int c = i >> 5, q = i & 31;
            float4 fv = *(const float4*)(g_f + (size_t)(nb0 + c) * 128 + q * 4);
            *(uint2*)(Fh + c * PS + 2 * q) = make_uint2(
                h2u(__floats2half2_rn(fv.x, fv.y)), h2u(__floats2half2_rn(fv.z, fv.w)));
        }
    }
    copy_wt(Wh, l * 6 + 0, tid);  // W_t
    __syncthreads();

    uint32_t accd[4][4][2];
    ZERO442(accd);
    gemmh16(Fh, Wh, accd, m0, n0c, lane);
#pragma unroll
    for (int mi = 0; mi < 4; ++mi) {
        int c0 = m0 + 16 * mi + g;
#pragma unroll
        for (int nj = 0; nj < 4; ++nj) {
            int col = n0c + 8 * nj + 2 * t;
            __half2 pc = u2h(pc2_s[col >> 1]);
            *(uint32_t*)(g_Ah + (size_t)(nb0 + c0) * 128 + col) =
                h2u(__hadd2(u2h(accd[mi][nj][0]), pc));
            *(uint32_t*)(g_Ah + (size_t)(nb0 + c0 + 8) * 128 + col) =
                h2u(__hadd2(u2h(accd[mi][nj][1]), pc));
        }
    }
    __syncthreads();
    copy_wt(Wh, l * 6 + 1, tid);  // W_s
    __syncthreads();
    ZERO442(accd);
    gemmh16(Fh, Wh, accd, m0, n0c, lane);
#pragma unroll
    for (int mi = 0; mi < 4; ++mi) {
        int c0 = m0 + 16 * mi + g;
#pragma unroll
        for (int nj = 0; nj < 4; ++nj) {
            int col = n0c + 8 * nj + 2 * t;
            *(uint32_t*)(g_Bh + (size_t)(nb0 + c0) * 128 + col) = accd[mi][nj][0];
            *(uint32_t*)(g_Bh + (size_t)(nb0 + c0 + 8) * 128 + col) = accd[mi][nj][1];
        }
    }
}

// ------------- k_edge_mm: messages + agg + update MLP -------------
__global__ __launch_bounds__(256, 2) void k_edge_mm(
    const float* __restrict__ inp, const float* __restrict__ cp,
    const float* __restrict__ msg1W, const float* __restrict__ msg2b,
    const float* __restrict__ upd1W, const float* __restrict__ upd1b,
    const float* __restrict__ upd2b, int l) {
    extern __shared__ char smem[];
    uint32_t* Mh = (uint32_t*)smem;               // 34816
    uint32_t* Wh = (uint32_t*)(smem + 34816);     // 34816
    uint32_t* Ac = (uint32_t*)(smem + 69632);     // 34816
    uint32_t* posW2 = (uint32_t*)(smem + 104448); // 2048
    uint32_t* wu2 = (uint32_t*)(smem + 106496);   // 256
    uint32_t* b2m2 = (uint32_t*)(smem + 106752);  // 256
    float* pcu_s = (float*)(smem + 107264);       // 512
    float* b2u_s = (float*)(smem + 107776);       // 512
    uint32_t* du2a = (uint32_t*)(smem + 108288);  // 4096
    float* cp_s = (float*)(smem + 112384);        // 32 -> 112416
    float* stage = (float*)smem;                  // late reuse

    const int tid = threadIdx.x, warp = tid >> 5, lane = tid & 31;
    const int g = lane >> 2, t = lane & 3;
    const int m0 = (warp >> 2) * 64, n0c = (warp & 3) * 32;
    const int gr = blockIdx.x, b = gr >> 7, r = gr & 127, nb0 = gr << 7;
    const float* W1l = msg1W + (size_t)l * 264 * 128;

    if (tid < 8) cp_s[tid] = (tid < NPRM) ? cp[b * NPRM + tid] : 0.0f;
    if (tid < 64) {
        b2m2[tid] = h2u(__floats2half2_rn(msg2b[l * 128 + 2 * tid],
                                          msg2b[l * 128 + 2 * tid + 1]));
        wu2[tid] = h2u(__floats2half2_rn(W1l[256 * 128 + 2 * tid],
                                         W1l[256 * 128 + 2 * tid + 1]));
    }
    __syncthreads();
    for (int i = tid; i < 512; i += 256) {  // posW half2: [d][64]
        int d = i >> 6, j = i & 63;
        float pdx = (float)(-c_dr[d]) * (1.0f / 127.0f) * cp_s[1];
        float pdy = (float)(-c_dc[d]) * (1.0f / 127.0f) * cp_s[0];
        float v0 = pdx * W1l[257 * 128 + 2 * j] + pdy * W1l[258 * 128 + 2 * j];
        float v1 = pdx * W1l[257 * 128 + 2 * j + 1] + pdy * W1l[258 * 128 + 2 * j + 1];
        posW2[i] = h2u(__floats2half2_rn(v0, v1));
    }
    for (int i = tid; i < 1024; i += 256) {  // du for ALL 8 directions upfront
        int d = i >> 7, c = i & 127;
        int n = nb0 + c, nb = n + c_dr[d] * WW + c_dc[d];
        nb = min(max(nb, 0), NN - 1);
        int bb = nb >> 14;
        float du = inp[b * NCH * HW + (n - b * HW)] -
                   inp[bb * NCH * HW + (nb - bb * HW)];
        du2a[i] = h2u(__half2half2(__float2half_rn(du)));
    }
    for (int i = tid; i < 4096; i += 256) {  // cache A tile (half2)
        int c = i >> 5, q = i & 31;
        *(uint2*)(Ac + c * PS + 2 * q) =
            *(const uint2*)(g_Ah + (size_t)(nb0 + c) * 128 + q * 4);
    }
    copy_wt(Wh, l * 6 + 2, tid);  // msg2W

    __half2 agg[4][4][2];
#pragma unroll
    for (int i = 0; i < 4; ++i)
#pragma unroll
        for (int j = 0; j < 4; ++j) {
            agg[i][j][0] = __float2half2_rn(0.0f);
            agg[i][j][1] = __float2half2_rn(0.0f);
        }

#pragma unroll 1
    for (int d = 0; d < 8; ++d) {
        const int dr = c_dr[d], dc = c_dc[d];
        if ((unsigned)(r + dr) >= (unsigned)HH) continue;
        __syncthreads();  // prior gemm reads done (first iter: smem fills done)
        for (int i = tid; i < 4096; i += 256) {  // M build, all half2
            int c = i >> 5, q = i & 31;
            int nb = nb0 + c + dr * WW + dc;
            nb = min(max(nb, 0), NN - 1);
            uint2 bm = *(const uint2*)(g_Bh + (size_t)nb * 128 + q * 4);
            uint2 av = *(const uint2*)(Ac + c * PS + 2 * q);
            __half2 hd = u2h(du2a[d * 128 + c]);
            __half2 half_c = __float2half2_rn(0.5f);
            __half2 s0 = __hadd2(__hadd2(u2h(av.x), u2h(bm.x)),
                                 __hfma2(hd, u2h(wu2[2 * q]), u2h(posW2[d * 64 + 2 * q])));
            __half2 s1 = __hadd2(__hadd2(u2h(av.y), u2h(bm.y)),
                                 __hfma2(hd, u2h(wu2[2 * q + 1]),
                                         u2h(posW2[d * 64 + 2 * q + 1])));
            __half2 h0 = __hmul2(s0, half_c), h1 = __hmul2(s1, half_c);
            __half2 t0 = tanh2(h0), t1 = tanh2(h1);
            *(uint2*)(Mh + c * PS + 2 * q) =
                make_uint2(h2u(__hfma2(h0, t0, h0)), h2u(__hfma2(h1, t1, h1)));
        }
        __syncthreads();
        uint32_t accd[4][4][2];
        ZERO442(accd);
        gemmh16(Mh, Wh, accd, m0, n0c, lane);
#pragma unroll
        for (int mi = 0; mi < 4; ++mi) {
            int c0 = m0 + 16 * mi + g;
            bool ok0 = (unsigned)(c0 + dc) < (unsigned)WW;
            bool ok1 = (unsigned)(c0 + 8 + dc) < (unsigned)WW;
#pragma unroll
            for (int nj = 0; nj < 4; ++nj) {
                int col = n0c + 8 * nj + 2 * t;
                __half2 bb = u2h(b2m2[col >> 1]);
                if (ok0)
                    agg[mi][nj][0] = __hadd2(
                        agg[mi][nj][0], psw2(__hadd2(u2h(accd[mi][nj][0]), bb)));
                if (ok1)
                    agg[mi][nj][1] = __hadd2(
                        agg[mi][nj][1], psw2(__hadd2(u2h(accd[mi][nj][1]), bb)));
            }
        }
    }
    __syncthreads();  // last gemm done; Mh reusable

    // -------- update MLP --------
    const float* U1 = upd1W + (size_t)l * 261 * 128;
    {
        int crn = 1 + (r > 0) + (r < HH - 1);
#pragma unroll
        for (int mi = 0; mi < 4; ++mi) {
#pragma unroll
            for (int hh = 0; hh < 2; ++hh) {
                int c0 = m0 + 16 * mi + g + 8 * hh;
                float inv = 1.0f / (float)(crn * (1 + (c0 > 0) + (c0 < WW - 1)) - 1);
                __half2 inv2 = __float2half2_rn(inv);
#pragma unroll
                for (int nj = 0; nj < 4; ++nj)
                    Mh[c0 * PS + (n0c >> 1) + 4 * nj + t] =
                        h2u(__hmul2(agg[mi][nj][hh], inv2));
            }
        }
    }
    copy_wt(Wh, l * 6 + 3, tid);  // U1 agg rows
    if (tid < 128) {
        float s = upd1b[l * 128 + tid];
#pragma unroll
        for (int p = 0; p < NPRM; ++p)
            s = fmaf(cp_s[p], U1[(256 + p) * 128 + tid], s);
        pcu_s[tid] = s;
        b2u_s[tid] = upd2b[l * 128 + tid];
    }
    __syncthreads();
    float acc2[4][4][4];
    ZERO444(acc2);
    gemmh(Mh, Wh, acc2, m0, n0c, lane);
    __syncthreads();
    for (int i = tid; i < 4096; i += 256) {  // f -> Mh (fp16 hi)
        int c = i >> 5, q = i & 31;
        float4 fv = *(const float4*)(g_f + (size_t)(nb0 + c) * 128 + q * 4);
        *(uint2*)(Mh + c * PS + 2 * q) = make_uint2(
            h2u(__floats2half2_rn(fv.x, fv.y)), h2u(__floats2half2_rn(fv.z, fv.w)));
    }
    copy_wt(Wh, l * 6 + 4, tid);  // U1 f rows
    __syncthreads();
    gemmh(Mh, Wh, acc2, m0, n0c, lane);  // accumulate
    __syncthreads();
#pragma unroll
    for (int mi = 0; mi < 4; ++mi) {  // h1 = swish(acc2 + pcu) -> Mh
#pragma unroll
        for (int nj = 0; nj < 4; ++nj) {
            int col = n0c + 8 * nj + 2 * t;
            int c0 = m0 + 16 * mi + g;
            Mh[c0 * PS + (col >> 1)] =
                h2u(psw(acc2[mi][nj][0] + pcu_s[col], acc2[mi][nj][1] + pcu_s[col + 1]));
            Mh[(c0 + 8) * PS + (col >> 1)] =
                h2u(psw(acc2[mi][nj][2] + pcu_s[col], acc2[mi][nj][3] + pcu_s[col + 1]));
        }
    }
    copy_wt(Wh, l * 6 + 5, tid);  // U2
    __syncthreads();
    float acc3[4][4][4];
    ZERO444(acc3);
    gemmh(Mh, Wh, acc3, m0, n0c, lane);
    __syncthreads();  // gemm done; stage may overwrite Mh/Wh

    // -------- residual + stores + layernorm stats --------
#pragma unroll
    for (int mi = 0; mi < 4; ++mi) {
#pragma unroll
        for (int half = 0; half < 2; ++half) {
            int c0 = m0 + 16 * mi + g + 8 * half;
#pragma unroll
            for (int nj = 0; nj < 4; ++nj) {
                int col = n0c + 8 * nj + 2 * t;
                float2 f2 = *(const float2*)(g_f + (size_t)(nb0 + c0) * 128 + col);
                float v0 = f2.x + tsw(acc3[mi][nj][2 * half + 0] + b2u_s[col]);
                float v1 = f2.y + tsw(acc3[mi][nj][2 * half + 1] + b2u_s[col + 1]);
                *(float2*)(g_tmp + (size_t)(nb0 + c0) * 128 + col) = make_float2(v0, v1);
                *(float2*)(stage + c0 * 132 + col) = make_float2(v0, v1);
            }
        }
    }
    __syncthreads();
    if (tid < 128) {
        float S = 0.0f, S2 = 0.0f;
#pragma unroll 4
        for (int gg = 0; gg < 128; ++gg) {
            float v = stage[gg * 132 + tid];
            S += v;
            S2 += v * v;
        }
        atomicAdd(&g_stats[(l & 1) * SBUF + b * 256 + tid], S);
        atomicAdd(&g_stats[(l & 1) * SBUF + b * 256 + 128 + tid], S2);
    }
}

// ================= fp32 kernels =================
#define ACC_ZERO(acc)                                                  \
    _Pragma("unroll") for (int _i = 0; _i < 4; ++_i)                   \
        _Pragma("unroll") for (int _j = 0; _j < 8; ++_j) acc[_i][_j] = 0.0f;

template <int RSTEP>
__device__ __forceinline__ void gemm128(const float* __restrict__ As, int lda,
                                        const float* __restrict__ Ws, int ldw,
                                        float acc[4][8], int tr, int tc) {
#pragma unroll 4
    for (int k4 = 0; k4 < 32; ++k4) {
        float4 a[4];
#pragma unroll
        for (int i = 0; i < 4; ++i)
            a[i] = *(const float4*)(As + (tr + i * RSTEP) * lda + k4 * 4);
        const float* wp = Ws + (k4 * 4) * ldw + tc * 8;
#pragma unroll
        for (int kk = 0; kk < 4; ++kk) {
            float4 b0 = *(const float4*)(wp + kk * ldw);
            float4 b1 = *(const float4*)(wp + kk * ldw + 4);
#pragma unroll
            for (int i = 0; i < 4; ++i) {
                float av = ((const float*)(a + i))[kk];
                acc[i][0] = fmaf(av, b0.x, acc[i][0]);
                acc[i][1] = fmaf(av, b0.y, acc[i][1]);
                acc[i][2] = fmaf(av, b0.z, acc[i][2]);
                acc[i][3] = fmaf(av, b0.w, acc[i][3]);
                acc[i][4] = fmaf(av, b1.x, acc[i][4]);
                acc[i][5] = fmaf(av, b1.y, acc[i][5]);
                acc[i][6] = fmaf(av, b1.z, acc[i][6]);
                acc[i][7] = fmaf(av, b1.w, acc[i][7]);
            }
        }
    }
}

__global__ __launch_bounds__(256, 2) void k_embed(
    const float* __restrict__ inp, const float* __restrict__ cp,
    const float* __restrict__ W1, const float* __restrict__ b1,
    const float* __restrict__ W2, const float* __restrict__ b2) {
    extern __shared__ float sm[];
    float* e_s = sm;
    float* W1_s = e_s + 64 * 8;
    float* b1_s = W1_s + 8 * 128;
    float* h1_s = b1_s + 128;
    float* W2_s = h1_s + 64 * 132;
    float* b2_s = W2_s + 128 * 128;
    int tid = threadIdx.x;
    int n0 = blockIdx.x * 64, b = n0 / HW;
    for (int i = tid; i < 8 * 128; i += 256) W1_s[i] = W1[i];
    if (tid < 128) { b1_s[tid] = b1[tid]; b2_s[tid] = b2[tid]; }
    for (int i = tid; i < 128 * 32; i += 256)
        ((float4*)W2_s)[i] = ((const float4*)W2)[i];
    if (tid < 64) {
        int n = n0 + tid, rc = n - b * HW;
        int r = rc >> 7, c = rc & 127;
        e_s[tid * 8 + 0] = inp[b * NCH * HW + rc];
        e_s[tid * 8 + 1] = (float)r * (1.0f / 127.0f) * cp[b * NPRM + 1];
        e_s[tid * 8 + 2] = (float)c * (1.0f / 127.0f) * cp[b * NPRM + 0];
#pragma unroll
        for (int p = 0; p < NPRM; ++p) e_s[tid * 8 + 3 + p] = cp[b * NPRM + p];
    }
    __syncthreads();
    int tc = tid & 15, tr = tid >> 4;
#pragma unroll
    for (int i = 0; i < 4; ++i) {
        int row = tr + 16 * i;
#pragma unroll
        for (int j = 0; j < 8; ++j) {
            float s = b1_s[tc * 8 + j];
#pragma unroll
            for (int k = 0; k < 8; ++k)
                s = fmaf(e_s[row * 8 + k], W1_s[k * 128 + tc * 8 + j], s);
            h1_s[row * 132 + tc * 8 + j] = swishf(s);
        }
    }
    __syncthreads();
    float acc[4][8];
    ACC_ZERO(acc);
    gemm128<16>(h1_s, 132, W2_s, 128, acc, tr, tc);
#pragma unroll
    for (int i = 0; i < 4; ++i) {
        int row = tr + 16 * i;
#pragma unroll
        for (int j = 0; j < 8; ++j)
            g_f[(size_t)(n0 + row) * 128 + tc * 8 + j] =
                swishf(acc[i][j] + b2_s[tc * 8 + j]);
    }
}

// k_out with fused final layernorm (stats buffer (NL-1)&1 = 1)
__global__ __launch_bounds__(256, 2) void k_out(
    const float* __restrict__ inp, const float* __restrict__ W1,
    const float* __restrict__ b1, const float* __restrict__ W2,
    const float* __restrict__ b2, float* __restrict__ out) {
    extern __shared__ float sm[];
    float* f_s = sm;
    float* W1_s = f_s + 128 * 132;
    float* b1_s = W1_s + 128 * 64;
    float* W2_s = b1_s + 64;
    float* red_s = W2_s + 64;
    float* mean_s = red_s + 128 * 8;
    float* rstd_s = mean_s + 128;
    int tid = threadIdx.x;
    int n0 = blockIdx.x * 128, b = n0 / HW;
    if (tid < 128) {
        const float* st = g_stats + ((NL - 1) & 1) * SBUF + b * 256;
        float m = st[tid] * (1.0f / (float)HW);
        float v = st[128 + tid] * (1.0f / (float)HW) - m * m;
        mean_s[tid] = m;
        rstd_s[tid] = rsqrtf(v + EPSV);
    }
    __syncthreads();
    for (int i = tid; i < 128 * 32; i += 256) {
        int c = i >> 5, q = i & 31, j = q * 4;
        float4 v = *(const float4*)(g_tmp + (size_t)(n0 + c) * 128 + j);
        v.x = (v.x - mean_s[j + 0]) * rstd_s[j + 0];
        v.y = (v.y - mean_s[j + 1]) * rstd_s[j + 1];
        v.z = (v.z - mean_s[j + 2]) * rstd_s[j + 2];
        v.w = (v.w - mean_s[j + 3]) * rstd_s[j + 3];
        ((float4*)(f_s + c * 132))[q] = v;
    }
    for (int i = tid; i < 128 * 16; i += 256)
        ((float4*)W1_s)[i] = ((const float4*)W1)[i];
    if (tid < 64) { b1_s[tid] = b1[tid]; W2_s[tid] = W2[tid]; }
    __syncthreads();
    int tc = tid & 7, tr = tid >> 3;
    float acc[4][8];
    ACC_ZERO(acc);
    gemm128<32>(f_s, 132, W1_s, 64, acc, tr, tc);
#pragma unroll
    for (int i = 0; i < 4; ++i) {
        float p = 0.0f;
#pragma unroll
        for (int j = 0; j < 8; ++j)
            p += swishf(acc[i][j] + b1_s[tc * 8 + j]) * W2_s[tc * 8 + j];
        red_s[(tr + 32 * i) * 8 + tc] = p;
    }
    __syncthreads();
    if (tid < 128) {
        float d = b2[0];
#pragma unroll
        for (int t = 0; t < 8; ++t) d += red_s[tid * 8 + t];
        int n = n0 + tid;
        out[n] = inp[b * NCH * HW + (n - b * HW)] + DTV * d;
    }
}

// ---------------- host launcher ----------------
extern "C" void kernel_launch(void* const* d_in, const int* in_sizes, int n_in,
                              void* d_out, int out_size) {
    const float* inp   = (const float*)d_in[0];
    const float* cp    = (const float*)d_in[1];
    const float* embW1 = (const float*)d_in[3];
    const float* embb1 = (const float*)d_in[4];
    const float* embW2 = (const float*)d_in[5];
    const float* embb2 = (const float*)d_in[6];
    const float* msg1W = (const float*)d_in[7];
    const float* msg1b = (const float*)d_in[8];
    const float* msg2W = (const float*)d_in[9];
    const float* msg2b = (const float*)d_in[10];
    const float* upd1W = (const float*)d_in[11];
    const float* upd1b = (const float*)d_in[12];
    const float* upd2W = (const float*)d_in[13];
    const float* upd2b = (const float*)d_in[14];
    const float* outW1 = (const float*)d_in[15];
    const float* outb1 = (const float*)d_in[16];
    const float* outW2 = (const float*)d_in[17];
    const float* outb2 = (const float*)d_in[18];
    float* out = (float*)d_out;

    const size_t smE = (size_t)(64 * 8 + 8 * 128 + 128 + 64 * 132 + 128 * 128 + 128) * 4;
    const size_t smO = (size_t)(128 * 132 + 128 * 64 + 64 + 64 + 128 * 8 + 256) * 4;
    const size_t smMA = 71168;
    const size_t smEG = 112416;

    cudaFuncSetAttribute(k_embed, cudaFuncAttributeMaxDynamicSharedMemorySize, (int)smE);
    cudaFuncSetAttribute(k_out, cudaFuncAttributeMaxDynamicSharedMemorySize, (int)smO);
    cudaFuncSetAttribute(k_msgA_mm, cudaFuncAttributeMaxDynamicSharedMemorySize, (int)smMA);
    cudaFuncSetAttribute(k_edge_mm, cudaFuncAttributeMaxDynamicSharedMemorySize, (int)smEG);

    k_prep<<<36, 256>>>(msg1W, msg2W, upd1W, upd2W);
    k_embed<<<NN / 64, 256, smE>>>(inp, cp, embW1, embb1, embW2, embb2);
    for (int l = 0; l < NL; ++l) {
        k_msgA_mm<<<NN / 128, 256, smMA>>>(cp, msg1W, msg1b, l);
        k_edge_mm<<<NN / 128, 256, smEG>>>(inp, cp, msg1W, msg2b,
                                           upd1W, upd1b, upd2b, l);
    }
    k_out<<<NN / 128, 256, smO>>>(inp, outW1, outb1, outW2, outb2, out);
}

// round 14
// speedup vs baseline: 6.2478x; 1.0264x over previous
#include <cuda_runtime.h>
#include <cuda_fp16.h>
#include <cstdint>

#define HH 128
#define WW 128
#define HW 16384
#define NN 65536
#define HID 128
#define NL 6
#define NPRM 5
#define EPSV 1e-5f
#define DTV 0.1f
#define NCH 3
#define NBATCH 4
#define PS 68  // uint32 (half2) words per plane row (row stride 272B)
#define SBUF 1024
#define WTHALVES 17408  // 128 rows * 136 halves per transposed weight plane

__device__ float g_f[(size_t)NN * HID];
__device__ __half g_Ah[(size_t)NN * HID];
__device__ __half g_Bh[(size_t)NN * HID];
__device__ float g_tmp[(size_t)NN * HID];
__device__ float g_stats[2 * SBUF];
__device__ __half g_wth[(size_t)36 * WTHALVES];  // 6 layers x 6 matrices

__constant__ int c_dr[8] = {-1, -1, -1, 0, 0, 1, 1, 1};
__constant__ int c_dc[8] = {-1, 0, 1, -1, 1, -1, 0, 1};

__device__ __forceinline__ float swishf(float x) {
    return __fdividef(x, 1.0f + __expf(-x));
}
__device__ __forceinline__ float tsw(float x) {
    float h = 0.5f * x, th;
    asm("tanh.approx.f32 %0, %1;" : "=f"(th) : "f"(h));
    return h + h * th;
}
__device__ __forceinline__ __half2 u2h(uint32_t u) {
    return *reinterpret_cast<__half2*>(&u);
}
__device__ __forceinline__ uint32_t h2u(__half2 h) {
    return *reinterpret_cast<uint32_t*>(&h);
}
__device__ __forceinline__ __half2 tanh2(__half2 x) {
    uint32_t r;
    asm("tanh.approx.f16x2 %0, %1;" : "=r"(r) : "r"(h2u(x)));
    return u2h(r);
}
__device__ __forceinline__ __half2 psw(float x0, float x1) {
    __half2 h = __floats2half2_rn(0.5f * x0, 0.5f * x1);
    __half2 t = tanh2(h);
    return __hfma2(h, t, h);
}
__device__ __forceinline__ __half2 psw2(__half2 x) {
    __half2 h = __hmul2(x, __float2half2_rn(0.5f));
    __half2 t = tanh2(h);
    return __hfma2(h, t, h);
}

// ---- one-time weight transpose: W[k][n] fp32 -> Wt[n][k] fp16 (global) ----
__global__ void k_prep(const float* __restrict__ msg1W,
                       const float* __restrict__ msg2W,
                       const float* __restrict__ upd1W,
                       const float* __restrict__ upd2W) {
    int m_idx = blockIdx.x, l = m_idx / 6, m = m_idx % 6;
    const float* W;
    switch (m) {
        case 0: W = msg1W + (size_t)l * 264 * 128; break;              // msg1 W_t
        case 1: W = msg1W + (size_t)l * 264 * 128 + 128 * 128; break;  // msg1 W_s
        case 2: W = msg2W + (size_t)l * 16384; break;                  // msg2
        case 3: W = upd1W + (size_t)l * 261 * 128 + 128 * 128; break;  // U1 agg
        case 4: W = upd1W + (size_t)l * 261 * 128; break;              // U1 f
        default: W = upd2W + (size_t)l * 16384; break;                 // U2
    }
    __half* H = g_wth + (size_t)m_idx * WTHALVES;
    for (int i = threadIdx.x; i < 16384; i += 256) {
        int n = i & 127, k = i >> 7;
        H[n * 136 + k] = __float2half_rn(W[k * 128 + n]);
    }
}
__device__ __forceinline__ void copy_wt(uint32_t* Hw, int mat, int tid) {
    const uint4* s = (const uint4*)(g_wth + (size_t)mat * WTHALVES);
    uint4* d = (uint4*)Hw;
    for (int i = tid; i < 2176; i += 256) d[i] = s[i];
}

// ---------------- fp16 GEMMs (m16n8k16) with ldmatrix ----------------
__device__ __forceinline__ void hmma(float* a_, uint32_t a0, uint32_t a1, uint32_t a2,
                                     uint32_t a3, uint32_t b0, uint32_t b1) {
    asm volatile(
        "mma.sync.aligned.m16n8k16.row.col.f32.f16.f16.f32 "
        "{%0,%1,%2,%3},{%4,%5,%6,%7},{%8,%9},{%0,%1,%2,%3};"
        : "+f"(a_[0]), "+f"(a_[1]), "+f"(a_[2]), "+f"(a_[3])
        : "r"(a0), "r"(a1), "r"(a2), "r"(a3), "r"(b0), "r"(b1));
}
__device__ __forceinline__ void hmma16(uint32_t* d, uint32_t a0, uint32_t a1,
                                       uint32_t a2, uint32_t a3, uint32_t b0,
                                       uint32_t b1) {
    asm volatile(
        "mma.sync.aligned.m16n8k16.row.col.f16.f16.f16.f16 "
        "{%0,%1},{%2,%3,%4,%5},{%6,%7},{%0,%1};"
        : "+r"(d[0]), "+r"(d[1])
        : "r"(a0), "r"(a1), "r"(a2), "r"(a3), "r"(b0), "r"(b1));
}
__device__ __forceinline__ void ldsm4(uint32_t* r, uint32_t addr) {
    asm volatile("ldmatrix.sync.aligned.m8n8.x4.shared.b16 {%0,%1,%2,%3}, [%4];"
                 : "=r"(r[0]), "=r"(r[1]), "=r"(r[2]), "=r"(r[3]) : "r"(addr));
}
__device__ __forceinline__ void ldsm2(uint32_t* r, uint32_t addr) {
    asm volatile("ldmatrix.sync.aligned.m8n8.x2.shared.b16 {%0,%1}, [%2];"
                 : "=r"(r[0]), "=r"(r[1]) : "r"(addr));
}
#define ZERO444(a)                                                     \
    _Pragma("unroll") for (int _i = 0; _i < 4; ++_i)                   \
        _Pragma("unroll") for (int _j = 0; _j < 4; ++_j)               \
            _Pragma("unroll") for (int _q = 0; _q < 4; ++_q) a[_i][_j][_q] = 0.0f;
#define ZERO442(a)                                                     \
    _Pragma("unroll") for (int _i = 0; _i < 4; ++_i)                   \
        _Pragma("unroll") for (int _j = 0; _j < 4; ++_j)               \
            _Pragma("unroll") for (int _q = 0; _q < 2; ++_q) a[_i][_j][_q] = 0u;

// fp32-acc GEMM (update path)
__device__ __forceinline__ void gemmh(const uint32_t* __restrict__ Ah,
                                      const uint32_t* __restrict__ Bh,
                                      float acc[4][4][4], int m0, int n0c, int lane) {
    uint32_t abase = (uint32_t)__cvta_generic_to_shared(Ah) +
                     (uint32_t)(m0 + (lane & 15)) * 272 + ((lane >> 4) & 1) * 16;
    uint32_t bbase = (uint32_t)__cvta_generic_to_shared(Bh) +
                     (uint32_t)(n0c + (lane & 7)) * 272 + ((lane >> 3) & 1) * 16;
#pragma unroll 1
    for (int s = 0; s < 8; ++s) {
        uint32_t bh[4][2];
#pragma unroll
        for (int nj = 0; nj < 4; ++nj)
            ldsm2(bh[nj], bbase + nj * (8 * 272) + s * 32);
#pragma unroll
        for (int mi = 0; mi < 4; ++mi) {
            uint32_t a[4];
            ldsm4(a, abase + mi * (16 * 272) + s * 32);
#pragma unroll
            for (int nj = 0; nj < 4; ++nj)
                hmma(acc[mi][nj], a[0], a[1], a[2], a[3], bh[nj][0], bh[nj][1]);
        }
    }
}
// f16-acc GEMM (message path)
__device__ __forceinline__ void gemmh16(const uint32_t* __restrict__ Ah,
                                        const uint32_t* __restrict__ Bh,
                                        uint32_t accd[4][4][2], int m0, int n0c,
                                        int lane) {
    uint32_t abase = (uint32_t)__cvta_generic_to_shared(Ah) +
                     (uint32_t)(m0 + (lane & 15)) * 272 + ((lane >> 4) & 1) * 16;
    uint32_t bbase = (uint32_t)__cvta_generic_to_shared(Bh) +
                     (uint32_t)(n0c + (lane & 7)) * 272 + ((lane >> 3) & 1) * 16;
#pragma unroll 2
    for (int s = 0; s < 8; ++s) {
        uint32_t bh[4][2];
#pragma unroll
        for (int nj = 0; nj < 4; ++nj)
            ldsm2(bh[nj], bbase + nj * (8 * 272) + s * 32);
#pragma unroll
        for (int mi = 0; mi < 4; ++mi) {
            uint32_t a[4];
            ldsm4(a, abase + mi * (16 * 272) + s * 32);
#pragma unroll
            for (int nj = 0; nj < 4; ++nj)
                hmma16(accd[mi][nj], a[0], a[1], a[2], a[3], bh[nj][0], bh[nj][1]);
        }
    }
}

// ------ k_msgA_mm: (fused prev-layer norm) + A = f@W_t + pc, Bm = f@W_s ------
__global__ __launch_bounds__(256, 3) void k_msgA_mm(
    const float* __restrict__ cp, const float* __restrict__ msg1W,
    const float* __restrict__ msg1b, int l) {
    extern __shared__ char smem[];
    uint32_t* Fh = (uint32_t*)smem;             // 34816
    uint32_t* Wh = (uint32_t*)(smem + 34816);   // 34816
    uint32_t* pc2_s = (uint32_t*)(smem + 69632); // 256
    float* mean_s = (float*)(smem + 70144);     // 512
    float* rstd_s = (float*)(smem + 70656);     // 512 -> 71168

    const int tid = threadIdx.x, warp = tid >> 5, lane = tid & 31;
    const int g = lane >> 2, t = lane & 3;
    const int m0 = (warp >> 2) * 64, n0c = (warp & 3) * 32;
    const int nb0 = blockIdx.x << 7, b = nb0 >> 14;
    const float* Wl1 = msg1W + (size_t)l * 264 * 128;

    if (blockIdx.x == 0)
        for (int i = tid; i < SBUF; i += 256) g_stats[(l & 1) * SBUF + i] = 0.0f;
    if (tid < 64) {
        float s0 = msg1b[l * 128 + 2 * tid], s1 = msg1b[l * 128 + 2 * tid + 1];
#pragma unroll
        for (int p = 0; p < NPRM; ++p) {
            float cpv = cp[b * NPRM + p];
            s0 = fmaf(cpv, Wl1[(259 + p) * 128 + 2 * tid], s0);
            s1 = fmaf(cpv, Wl1[(259 + p) * 128 + 2 * tid + 1], s1);
        }
        pc2_s[tid] = h2u(__floats2half2_rn(s0, s1));
    }
    if (l > 0) {  // fused layernorm of previous layer's g_tmp
        if (tid < 128) {
            const float* st = g_stats + ((l - 1) & 1) * SBUF + b * 256;
            float m = st[tid] * (1.0f / (float)HW);
            float v = st[128 + tid] * (1.0f / (float)HW) - m * m;
            mean_s[tid] = m;
            rstd_s[tid] = rsqrtf(v + EPSV);
        }
        __syncthreads();
        for (int i = tid; i < 4096; i += 256) {
            int c = i >> 5, q = i & 31, j = q * 4;
            float4 v = *(const float4*)(g_tmp + (size_t)(nb0 + c) * 128 + j);
            v.x = (v.x - mean_s[j + 0]) * rstd_s[j + 0];
            v.y = (v.y - mean_s[j + 1]) * rstd_s[j + 1];
            v.z = (v.z - mean_s[j + 2]) * rstd_s[j + 2];
            v.w = (v.w - mean_s[j + 3]) * rstd_s[j + 3];
            *(float4*)(g_f + (size_t)(nb0 + c) * 128 + j) = v;  // edge reads this
            *(uint2*)(Fh + c * PS + 2 * q) = make_uint2(
                h2u(__floats2half2_rn(v.x, v.y)), h2u(__floats2half2_rn(v.z, v.w)));
        }
    } else {
        for (int i = tid; i < 4096; i += 256) {
            int c = i >> 5, q = i & 31;
            float4 fv = *(const float4*)(g_f + (size_t)(nb0 + c) * 128 + q * 4);
            *(uint2*)(Fh + c * PS + 2 * q) = make_uint2(
                h2u(__floats2half2_rn(fv.x, fv.y)), h2u(__floats2half2_rn(fv.z, fv.w)));
        }
    }
    copy_wt(Wh, l * 6 + 0, tid);  // W_t
    __syncthreads();

    uint32_t accd[4][4][2];
    ZERO442(accd);
    gemmh16(Fh, Wh, accd, m0, n0c, lane);
#pragma unroll
    for (int mi = 0; mi < 4; ++mi) {
        int c0 = m0 + 16 * mi + g;
#pragma unroll
        for (int nj = 0; nj < 4; ++nj) {
            int col = n0c + 8 * nj + 2 * t;
            __half2 pc = u2h(pc2_s[col >> 1]);
            *(uint32_t*)(g_Ah + (size_t)(nb0 + c0) * 128 + col) =
                h2u(__hadd2(u2h(accd[mi][nj][0]), pc));
            *(uint32_t*)(g_Ah + (size_t)(nb0 + c0 + 8) * 128 + col) =
                h2u(__hadd2(u2h(accd[mi][nj][1]), pc));
        }
    }
    __syncthreads();
    copy_wt(Wh, l * 6 + 1, tid);  // W_s
    __syncthreads();
    ZERO442(accd);
    gemmh16(Fh, Wh, accd, m0, n0c, lane);
#pragma unroll
    for (int mi = 0; mi < 4; ++mi) {
        int c0 = m0 + 16 * mi + g;
#pragma unroll
        for (int nj = 0; nj < 4; ++nj) {
            int col = n0c + 8 * nj + 2 * t;
            *(uint32_t*)(g_Bh + (size_t)(nb0 + c0) * 128 + col) = accd[mi][nj][0];
            *(uint32_t*)(g_Bh + (size_t)(nb0 + c0 + 8) * 128 + col) = accd[mi][nj][1];
        }
    }
}

// ------------- k_edge_mm: messages + agg + update MLP -------------
__global__ __launch_bounds__(256, 2) void k_edge_mm(
    const float* __restrict__ inp, const float* __restrict__ cp,
    const float* __restrict__ msg1W, const float* __restrict__ msg2b,
    const float* __restrict__ upd1W, const float* __restrict__ upd1b,
    const float* __restrict__ upd2b, int l) {
    extern __shared__ char smem[];
    uint32_t* Mh0 = (uint32_t*)smem;              // 34816
    uint32_t* Mh1 = (uint32_t*)(smem + 34816);    // 34816
    uint32_t* Wh = (uint32_t*)(smem + 69632);     // 34816
    uint32_t* posW2 = (uint32_t*)(smem + 104448); // 2048
    uint32_t* wu2 = (uint32_t*)(smem + 106496);   // 256
    uint32_t* b2m2 = (uint32_t*)(smem + 106752);  // 256
    float* pcu_s = (float*)(smem + 107264);       // 512
    float* b2u_s = (float*)(smem + 107776);       // 512
    uint32_t* du2a = (uint32_t*)(smem + 108288);  // 4096
    float* cp_s = (float*)(smem + 112384);        // 32 -> 112416
    float* stage = (float*)smem;                  // late reuse (67584 < Mh0+Mh1)

    const int tid = threadIdx.x, warp = tid >> 5, lane = tid & 31;
    const int g = lane >> 2, t = lane & 3;
    const int m0 = (warp >> 2) * 64, n0c = (warp & 3) * 32;
    const int gr = blockIdx.x, b = gr >> 7, r = gr & 127, nb0 = gr << 7;
    const float* W1l = msg1W + (size_t)l * 264 * 128;

    if (tid < 8) cp_s[tid] = (tid < NPRM) ? cp[b * NPRM + tid] : 0.0f;
    if (tid < 64) {
        b2m2[tid] = h2u(__floats2half2_rn(msg2b[l * 128 + 2 * tid],
                                          msg2b[l * 128 + 2 * tid + 1]));
        wu2[tid] = h2u(__floats2half2_rn(W1l[256 * 128 + 2 * tid],
                                         W1l[256 * 128 + 2 * tid + 1]));
    }
    __syncthreads();
    for (int i = tid; i < 512; i += 256) {  // posW half2: [d][64]
        int d = i >> 6, j = i & 63;
        float pdx = (float)(-c_dr[d]) * (1.0f / 127.0f) * cp_s[1];
        float pdy = (float)(-c_dc[d]) * (1.0f / 127.0f) * cp_s[0];
        float v0 = pdx * W1l[257 * 128 + 2 * j] + pdy * W1l[258 * 128 + 2 * j];
        float v1 = pdx * W1l[257 * 128 + 2 * j + 1] + pdy * W1l[258 * 128 + 2 * j + 1];
        posW2[i] = h2u(__floats2half2_rn(v0, v1));
    }
    for (int i = tid; i < 1024; i += 256) {  // du for ALL 8 directions upfront
        int d = i >> 7, c = i & 127;
        int n = nb0 + c, nb = n + c_dr[d] * WW + c_dc[d];
        nb = min(max(nb, 0), NN - 1);
        int bb = nb >> 14;
        float du = inp[b * NCH * HW + (n - b * HW)] -
                   inp[bb * NCH * HW + (nb - bb * HW)];
        du2a[i] = h2u(__half2half2(__float2half_rn(du)));
    }
    copy_wt(Wh, l * 6 + 2, tid);  // msg2W
    __syncthreads();              // init fills visible

    __half2 agg[4][4][2];
#pragma unroll
    for (int i = 0; i < 4; ++i)
#pragma unroll
        for (int j = 0; j < 4; ++j) {
            agg[i][j][0] = __float2half2_rn(0.0f);
            agg[i][j][1] = __float2half2_rn(0.0f);
        }

    int ad = 0;  // active-direction counter (buffer parity)
#pragma unroll 1
    for (int d = 0; d < 8; ++d) {
        const int dr = c_dr[d], dc = c_dc[d];
        if ((unsigned)(r + dr) >= (unsigned)HH) continue;
        uint32_t* Mb = (ad & 1) ? Mh1 : Mh0;
        // build M into Mb (other buffer may still be read by previous gemm)
        for (int i = tid; i < 4096; i += 256) {
            int c = i >> 5, q = i & 31;
            int nb = nb0 + c + dr * WW + dc;
            nb = min(max(nb, 0), NN - 1);
            uint2 bm = *(const uint2*)(g_Bh + (size_t)nb * 128 + q * 4);
            uint2 av = *(const uint2*)(g_Ah + (size_t)(nb0 + c) * 128 + q * 4);
            __half2 hd = u2h(du2a[d * 128 + c]);
            __half2 half_c = __float2half2_rn(0.5f);
            __half2 s0 = __hadd2(__hadd2(u2h(av.x), u2h(bm.x)),
                                 __hfma2(hd, u2h(wu2[2 * q]), u2h(posW2[d * 64 + 2 * q])));
            __half2 s1 = __hadd2(__hadd2(u2h(av.y), u2h(bm.y)),
                                 __hfma2(hd, u2h(wu2[2 * q + 1]),
                                         u2h(posW2[d * 64 + 2 * q + 1])));
            __half2 h0 = __hmul2(s0, half_c), h1 = __hmul2(s1, half_c);
            __half2 t0 = tanh2(h0), t1 = tanh2(h1);
            *(uint2*)(Mb + c * PS + 2 * q) =
                make_uint2(h2u(__hfma2(h0, t0, h0)), h2u(__hfma2(h1, t1, h1)));
        }
        __syncthreads();  // Mb visible; also proves gemm(ad-1) done by all
        uint32_t accd[4][4][2];
        ZERO442(accd);
        gemmh16(Mb, Wh, accd, m0, n0c, lane);
#pragma unroll
        for (int mi = 0; mi < 4; ++mi) {
            int c0 = m0 + 16 * mi + g;
            bool ok0 = (unsigned)(c0 + dc) < (unsigned)WW;
            bool ok1 = (unsigned)(c0 + 8 + dc) < (unsigned)WW;
#pragma unroll
            for (int nj = 0; nj < 4; ++nj) {
                int col = n0c + 8 * nj + 2 * t;
                __half2 bb = u2h(b2m2[col >> 1]);
                if (ok0)
                    agg[mi][nj][0] = __hadd2(
                        agg[mi][nj][0], psw2(__hadd2(u2h(accd[mi][nj][0]), bb)));
                if (ok1)
                    agg[mi][nj][1] = __hadd2(
                        agg[mi][nj][1], psw2(__hadd2(u2h(accd[mi][nj][1]), bb)));
            }
        }
        ++ad;
    }
    __syncthreads();  // all message gemms done; Mh0/Mh1/Wh free

    // -------- update MLP --------
    const float* U1 = upd1W + (size_t)l * 261 * 128;
    {   // agg -> Mh0
        int crn = 1 + (r > 0) + (r < HH - 1);
#pragma unroll
        for (int mi = 0; mi < 4; ++mi) {
#pragma unroll
            for (int hh = 0; hh < 2; ++hh) {
                int c0 = m0 + 16 * mi + g + 8 * hh;
                float inv = 1.0f / (float)(crn * (1 + (c0 > 0) + (c0 < WW - 1)) - 1);
                __half2 inv2 = __float2half2_rn(inv);
#pragma unroll
                for (int nj = 0; nj < 4; ++nj)
                    Mh0[c0 * PS + (n0c >> 1) + 4 * nj + t] =
                        h2u(__hmul2(agg[mi][nj][hh], inv2));
            }
        }
    }
    for (int i = tid; i < 4096; i += 256) {  // f -> Mh1 (fp16)
        int c = i >> 5, q = i & 31;
        float4 fv = *(const float4*)(g_f + (size_t)(nb0 + c) * 128 + q * 4);
        *(uint2*)(Mh1 + c * PS + 2 * q) = make_uint2(
            h2u(__floats2half2_rn(fv.x, fv.y)), h2u(__floats2half2_rn(fv.z, fv.w)));
    }
    copy_wt(Wh, l * 6 + 3, tid);  // U1 agg rows
    if (tid < 128) {
        float s = upd1b[l * 128 + tid];
#pragma unroll
        for (int p = 0; p < NPRM; ++p)
            s = fmaf(cp_s[p], U1[(256 + p) * 128 + tid], s);
        pcu_s[tid] = s;
        b2u_s[tid] = upd2b[l * 128 + tid];
    }
    __syncthreads();
    float acc2[4][4][4];
    ZERO444(acc2);
    gemmh(Mh0, Wh, acc2, m0, n0c, lane);
    __syncthreads();
    copy_wt(Wh, l * 6 + 4, tid);  // U1 f rows
    __syncthreads();
    gemmh(Mh1, Wh, acc2, m0, n0c, lane);  // accumulate
    __syncthreads();
#pragma unroll
    for (int mi = 0; mi < 4; ++mi) {  // h1 = swish(acc2 + pcu) -> Mh0
#pragma unroll
        for (int nj = 0; nj < 4; ++nj) {
            int col = n0c + 8 * nj + 2 * t;
            int c0 = m0 + 16 * mi + g;
            Mh0[c0 * PS + (col >> 1)] =
                h2u(psw(acc2[mi][nj][0] + pcu_s[col], acc2[mi][nj][1] + pcu_s[col + 1]));
            Mh0[(c0 + 8) * PS + (col >> 1)] =
                h2u(psw(acc2[mi][nj][2] + pcu_s[col], acc2[mi][nj][3] + pcu_s[col + 1]));
        }
    }
    copy_wt(Wh, l * 6 + 5, tid);  // U2
    __syncthreads();
    float acc3[4][4][4];
    ZERO444(acc3);
    gemmh(Mh0, Wh, acc3, m0, n0c, lane);
    __syncthreads();  // gemm done; stage may overwrite Mh0/Mh1

    // -------- residual + stores + layernorm stats --------
#pragma unroll
    for (int mi = 0; mi < 4; ++mi) {
#pragma unroll
        for (int half = 0; half < 2; ++half) {
            int c0 = m0 + 16 * mi + g + 8 * half;
#pragma unroll
            for (int nj = 0; nj < 4; ++nj) {
                int col = n0c + 8 * nj + 2 * t;
                float2 f2 = *(const float2*)(g_f + (size_t)(nb0 + c0) * 128 + col);
                float v0 = f2.x + tsw(acc3[mi][nj][2 * half + 0] + b2u_s[col]);
                float v1 = f2.y + tsw(acc3[mi][nj][2 * half + 1] + b2u_s[col + 1]);
                *(float2*)(g_tmp + (size_t)(nb0 + c0) * 128 + col) = make_float2(v0, v1);
                *(float2*)(stage + c0 * 132 + col) = make_float2(v0, v1);
            }
        }
    }
    __syncthreads();
    if (tid < 128) {
        float S = 0.0f, S2 = 0.0f;
#pragma unroll 4
        for (int gg = 0; gg < 128; ++gg) {
            float v = stage[gg * 132 + tid];
            S += v;
            S2 += v * v;
        }
        atomicAdd(&g_stats[(l & 1) * SBUF + b * 256 + tid], S);
        atomicAdd(&g_stats[(l & 1) * SBUF + b * 256 + 128 + tid], S2);
    }
}

// ================= fp32 kernels =================
#define ACC_ZERO(acc)                                                  \
    _Pragma("unroll") for (int _i = 0; _i < 4; ++_i)                   \
        _Pragma("unroll") for (int _j = 0; _j < 8; ++_j) acc[_i][_j] = 0.0f;

template <int RSTEP>
__device__ __forceinline__ void gemm128(const float* __restrict__ As, int lda,
                                        const float* __restrict__ Ws, int ldw,
                                        float acc[4][8], int tr, int tc) {
#pragma unroll 4
    for (int k4 = 0; k4 < 32; ++k4) {
        float4 a[4];
#pragma unroll
        for (int i = 0; i < 4; ++i)
            a[i] = *(const float4*)(As + (tr + i * RSTEP) * lda + k4 * 4);
        const float* wp = Ws + (k4 * 4) * ldw + tc * 8;
#pragma unroll
        for (int kk = 0; kk < 4; ++kk) {
            float4 b0 = *(const float4*)(wp + kk * ldw);
            float4 b1 = *(const float4*)(wp + kk * ldw + 4);
#pragma unroll
            for (int i = 0; i < 4; ++i) {
                float av = ((const float*)(a + i))[kk];
                acc[i][0] = fmaf(av, b0.x, acc[i][0]);
                acc[i][1] = fmaf(av, b0.y, acc[i][1]);
                acc[i][2] = fmaf(av, b0.z, acc[i][2]);
                acc[i][3] = fmaf(av, b0.w, acc[i][3]);
                acc[i][4] = fmaf(av, b1.x, acc[i][4]);
                acc[i][5] = fmaf(av, b1.y, acc[i][5]);
                acc[i][6] = fmaf(av, b1.z, acc[i][6]);
                acc[i][7] = fmaf(av, b1.w, acc[i][7]);
            }
        }
    }
}

__global__ __launch_bounds__(256, 2) void k_embed(
    const float* __restrict__ inp, const float* __restrict__ cp,
    const float* __restrict__ W1, const float* __restrict__ b1,
    const float* __restrict__ W2, const float* __restrict__ b2) {
    extern __shared__ float sm[];
    float* e_s = sm;
    float* W1_s = e_s + 64 * 8;
    float* b1_s = W1_s + 8 * 128;
    float* h1_s = b1_s + 128;
    float* W2_s = h1_s + 64 * 132;
    float* b2_s = W2_s + 128 * 128;
    int tid = threadIdx.x;
    int n0 = blockIdx.x * 64, b = n0 / HW;
    for (int i = tid; i < 8 * 128; i += 256) W1_s[i] = W1[i];
    if (tid < 128) { b1_s[tid] = b1[tid]; b2_s[tid] = b2[tid]; }
    for (int i = tid; i < 128 * 32; i += 256)
        ((float4*)W2_s)[i] = ((const float4*)W2)[i];
    if (tid < 64) {
        int n = n0 + tid, rc = n - b * HW;
        int r = rc >> 7, c = rc & 127;
        e_s[tid * 8 + 0] = inp[b * NCH * HW + rc];
        e_s[tid * 8 + 1] = (float)r * (1.0f / 127.0f) * cp[b * NPRM + 1];
        e_s[tid * 8 + 2] = (float)c * (1.0f / 127.0f) * cp[b * NPRM + 0];
#pragma unroll
        for (int p = 0; p < NPRM; ++p) e_s[tid * 8 + 3 + p] = cp[b * NPRM + p];
    }
    __syncthreads();
    int tc = tid & 15, tr = tid >> 4;
#pragma unroll
    for (int i = 0; i < 4; ++i) {
        int row = tr + 16 * i;
#pragma unroll
        for (int j = 0; j < 8; ++j) {
            float s = b1_s[tc * 8 + j];
#pragma unroll
            for (int k = 0; k < 8; ++k)
                s = fmaf(e_s[row * 8 + k], W1_s[k * 128 + tc * 8 + j], s);
            h1_s[row * 132 + tc * 8 + j] = swishf(s);
        }
    }
    __syncthreads();
    float acc[4][8];
    ACC_ZERO(acc);
    gemm128<16>(h1_s, 132, W2_s, 128, acc, tr, tc);
#pragma unroll
    for (int i = 0; i < 4; ++i) {
        int row = tr + 16 * i;
#pragma unroll
        for (int j = 0; j < 8; ++j)
            g_f[(size_t)(n0 + row) * 128 + tc * 8 + j] =
                swishf(acc[i][j] + b2_s[tc * 8 + j]);
    }
}

// k_out with fused final layernorm (stats buffer (NL-1)&1 = 1)
__global__ __launch_bounds__(256, 2) void k_out(
    const float* __restrict__ inp, const float* __restrict__ W1,
    const float* __restrict__ b1, const float* __restrict__ W2,
    const float* __restrict__ b2, float* __restrict__ out) {
    extern __shared__ float sm[];
    float* f_s = sm;
    float* W1_s = f_s + 128 * 132;
    float* b1_s = W1_s + 128 * 64;
    float* W2_s = b1_s + 64;
    float* red_s = W2_s + 64;
    float* mean_s = red_s + 128 * 8;
    float* rstd_s = mean_s + 128;
    int tid = threadIdx.x;
    int n0 = blockIdx.x * 128, b = n0 / HW;
    if (tid < 128) {
        const float* st = g_stats + ((NL - 1) & 1) * SBUF + b * 256;
        float m = st[tid] * (1.0f / (float)HW);
        float v = st[128 + tid] * (1.0f / (float)HW) - m * m;
        mean_s[tid] = m;
        rstd_s[tid] = rsqrtf(v + EPSV);
    }
    __syncthreads();
    for (int i = tid; i < 128 * 32; i += 256) {
        int c = i >> 5, q = i & 31, j = q * 4;
        float4 v = *(const float4*)(g_tmp + (size_t)(n0 + c) * 128 + j);
        v.x = (v.x - mean_s[j + 0]) * rstd_s[j + 0];
        v.y = (v.y - mean_s[j + 1]) * rstd_s[j + 1];
        v.z = (v.z - mean_s[j + 2]) * rstd_s[j + 2];
        v.w = (v.w - mean_s[j + 3]) * rstd_s[j + 3];
        ((float4*)(f_s + c * 132))[q] = v;
    }
    for (int i = tid; i < 128 * 16; i += 256)
        ((float4*)W1_s)[i] = ((const float4*)W1)[i];
    if (tid < 64) { b1_s[tid] = b1[tid]; W2_s[tid] = W2[tid]; }
    __syncthreads();
    int tc = tid & 7, tr = tid >> 3;
    float acc[4][8];
    ACC_ZERO(acc);
    gemm128<32>(f_s, 132, W1_s, 64, acc, tr, tc);
#pragma unroll
    for (int i = 0; i < 4; ++i) {
        float p = 0.0f;
#pragma unroll
        for (int j = 0; j < 8; ++j)
            p += swishf(acc[i][j] + b1_s[tc * 8 + j]) * W2_s[tc * 8 + j];
        red_s[(tr + 32 * i) * 8 + tc] = p;
    }
    __syncthreads();
    if (tid < 128) {
        float d = b2[0];
#pragma unroll
        for (int t = 0; t < 8; ++t) d += red_s[tid * 8 + t];
        int n = n0 + tid;
        out[n] = inp[b * NCH * HW + (n - b * HW)] + DTV * d;
    }
}

// ---------------- host launcher ----------------
extern "C" void kernel_launch(void* const* d_in, const int* in_sizes, int n_in,
                              void* d_out, int out_size) {
    const float* inp   = (const float*)d_in[0];
    const float* cp    = (const float*)d_in[1];
    const float* embW1 = (const float*)d_in[3];
    const float* embb1 = (const float*)d_in[4];
    const float* embW2 = (const float*)d_in[5];
    const float* embb2 = (const float*)d_in[6];
    const float* msg1W = (const float*)d_in[7];
    const float* msg1b = (const float*)d_in[8];
    const float* msg2W = (const float*)d_in[9];
    const float* msg2b = (const float*)d_in[10];
    const float* upd1W = (const float*)d_in[11];
    const float* upd1b = (const float*)d_in[12];
    const float* upd2W = (const float*)d_in[13];
    const float* upd2b = (const float*)d_in[14];
    const float* outW1 = (const float*)d_in[15];
    const float* outb1 = (const float*)d_in[16];
    const float* outW2 = (const float*)d_in[17];
    const float* outb2 = (const float*)d_in[18];
    float* out = (float*)d_out;

    const size_t smE = (size_t)(64 * 8 + 8 * 128 + 128 + 64 * 132 + 128 * 128 + 128) * 4;
    const size_t smO = (size_t)(128 * 132 + 128 * 64 + 64 + 64 + 128 * 8 + 256) * 4;
    const size_t smMA = 71168;
    const size_t smEG = 112416;

    cudaFuncSetAttribute(k_embed, cudaFuncAttributeMaxDynamicSharedMemorySize, (int)smE);
    cudaFuncSetAttribute(k_out, cudaFuncAttributeMaxDynamicSharedMemorySize, (int)smO);
    cudaFuncSetAttribute(k_msgA_mm, cudaFuncAttributeMaxDynamicSharedMemorySize, (int)smMA);
    cudaFuncSetAttribute(k_edge_mm, cudaFuncAttributeMaxDynamicSharedMemorySize, (int)smEG);

    k_prep<<<36, 256>>>(msg1W, msg2W, upd1W, upd2W);
    k_embed<<<NN / 64, 256, smE>>>(inp, cp, embW1, embb1, embW2, embb2);
    for (int l = 0; l < NL; ++l) {
        k_msgA_mm<<<NN / 128, 256, smMA>>>(cp, msg1W, msg1b, l);
        k_edge_mm<<<NN / 128, 256, smEG>>>(inp, cp, msg1W, msg2b,
                                           upd1W, upd1b, upd2b, l);
    }
    k_out<<<NN / 128, 256, smO>>>(inp, outW1, outb1, outW2, outb2, out);
}

// round 15
// speedup vs baseline: 6.4127x; 1.0264x over previous
#include <cuda_runtime.h>
#include <cuda_fp16.h>
#include <cstdint>

#define HH 128
#define WW 128
#define HW 16384
#define NN 65536
#define HID 128
#define NL 6
#define NPRM 5
#define EPSV 1e-5f
#define DTV 0.1f
#define NCH 3
#define NBATCH 4
#define PS 68  // uint32 (half2) words per plane row (row stride 272B)
#define SBUF 1024
#define WTHALVES 17408  // 128 rows * 136 halves per transposed weight plane

__device__ float g_f[(size_t)NN * HID];
__device__ __half g_Ah[(size_t)NN * HID];
__device__ __half g_Bh[(size_t)NN * HID];
__device__ float g_tmp[(size_t)NN * HID];
__device__ float g_stats[2 * SBUF];
__device__ __half g_wth[(size_t)36 * WTHALVES];  // 6 layers x 6 matrices

__constant__ int c_dr[8] = {-1, -1, -1, 0, 0, 1, 1, 1};
__constant__ int c_dc[8] = {-1, 0, 1, -1, 1, -1, 0, 1};

__device__ __forceinline__ float swishf(float x) {
    return __fdividef(x, 1.0f + __expf(-x));
}
__device__ __forceinline__ __half2 u2h(uint32_t u) {
    return *reinterpret_cast<__half2*>(&u);
}
__device__ __forceinline__ uint32_t h2u(__half2 h) {
    return *reinterpret_cast<uint32_t*>(&h);
}
__device__ __forceinline__ __half2 tanh2(__half2 x) {
    uint32_t r;
    asm("tanh.approx.f16x2 %0, %1;" : "=r"(r) : "r"(h2u(x)));
    return u2h(r);
}
// half2 swish: x*sigmoid(x) = h + h*tanh(h), h = x/2
__device__ __forceinline__ __half2 psw2(__half2 x) {
    __half2 h = __hmul2(x, __float2half2_rn(0.5f));
    __half2 t = tanh2(h);
    return __hfma2(h, t, h);
}

// ---- one-time weight transpose: W[k][n] fp32 -> Wt[n][k] fp16 (global) ----
__global__ void k_prep(const float* __restrict__ msg1W,
                       const float* __restrict__ msg2W,
                       const float* __restrict__ upd1W,
                       const float* __restrict__ upd2W) {
    int m_idx = blockIdx.x, l = m_idx / 6, m = m_idx % 6;
    const float* W;
    switch (m) {
        case 0: W = msg1W + (size_t)l * 264 * 128; break;              // msg1 W_t
        case 1: W = msg1W + (size_t)l * 264 * 128 + 128 * 128; break;  // msg1 W_s
        case 2: W = msg2W + (size_t)l * 16384; break;                  // msg2
        case 3: W = upd1W + (size_t)l * 261 * 128 + 128 * 128; break;  // U1 agg
        case 4: W = upd1W + (size_t)l * 261 * 128; break;              // U1 f
        default: W = upd2W + (size_t)l * 16384; break;                 // U2
    }
    __half* H = g_wth + (size_t)m_idx * WTHALVES;
    for (int i = threadIdx.x; i < 16384; i += 256) {
        int n = i & 127, k = i >> 7;
        H[n * 136 + k] = __float2half_rn(W[k * 128 + n]);
    }
}
__device__ __forceinline__ void copy_wt(uint32_t* Hw, int mat, int tid) {
    const uint4* s = (const uint4*)(g_wth + (size_t)mat * WTHALVES);
    uint4* d = (uint4*)Hw;
    for (int i = tid; i < 2176; i += 256) d[i] = s[i];
}

// ---------------- fp16 GEMMs (m16n8k16) with ldmatrix ----------------
__device__ __forceinline__ void hmma16(uint32_t* d, uint32_t a0, uint32_t a1,
                                       uint32_t a2, uint32_t a3, uint32_t b0,
                                       uint32_t b1) {
    asm volatile(
        "mma.sync.aligned.m16n8k16.row.col.f16.f16.f16.f16 "
        "{%0,%1},{%2,%3,%4,%5},{%6,%7},{%0,%1};"
        : "+r"(d[0]), "+r"(d[1])
        : "r"(a0), "r"(a1), "r"(a2), "r"(a3), "r"(b0), "r"(b1));
}
__device__ __forceinline__ void ldsm4(uint32_t* r, uint32_t addr) {
    asm volatile("ldmatrix.sync.aligned.m8n8.x4.shared.b16 {%0,%1,%2,%3}, [%4];"
                 : "=r"(r[0]), "=r"(r[1]), "=r"(r[2]), "=r"(r[3]) : "r"(addr));
}
__device__ __forceinline__ void ldsm2(uint32_t* r, uint32_t addr) {
    asm volatile("ldmatrix.sync.aligned.m8n8.x2.shared.b16 {%0,%1}, [%2];"
                 : "=r"(r[0]), "=r"(r[1]) : "r"(addr));
}
#define ZERO442(a)                                                     \
    _Pragma("unroll") for (int _i = 0; _i < 4; ++_i)                   \
        _Pragma("unroll") for (int _j = 0; _j < 4; ++_j)               \
            _Pragma("unroll") for (int _q = 0; _q < 2; ++_q) a[_i][_j][_q] = 0u;

// f16-acc GEMM: D[64x32] per warp
__device__ __forceinline__ void gemmh16(const uint32_t* __restrict__ Ah,
                                        const uint32_t* __restrict__ Bh,
                                        uint32_t accd[4][4][2], int m0, int n0c,
                                        int lane) {
    uint32_t abase = (uint32_t)__cvta_generic_to_shared(Ah) +
                     (uint32_t)(m0 + (lane & 15)) * 272 + ((lane >> 4) & 1) * 16;
    uint32_t bbase = (uint32_t)__cvta_generic_to_shared(Bh) +
                     (uint32_t)(n0c + (lane & 7)) * 272 + ((lane >> 3) & 1) * 16;
#pragma unroll 2
    for (int s = 0; s < 8; ++s) {
        uint32_t bh[4][2];
#pragma unroll
        for (int nj = 0; nj < 4; ++nj)
            ldsm2(bh[nj], bbase + nj * (8 * 272) + s * 32);
#pragma unroll
        for (int mi = 0; mi < 4; ++mi) {
            uint32_t a[4];
            ldsm4(a, abase + mi * (16 * 272) + s * 32);
#pragma unroll
            for (int nj = 0; nj < 4; ++nj)
                hmma16(accd[mi][nj], a[0], a[1], a[2], a[3], bh[nj][0], bh[nj][1]);
        }
    }
}

// ------ k_msgA_mm: (fused prev-layer norm) + A = f@W_t + pc, Bm = f@W_s ------
__global__ __launch_bounds__(256, 3) void k_msgA_mm(
    const float* __restrict__ cp, const float* __restrict__ msg1W,
    const float* __restrict__ msg1b, int l) {
    extern __shared__ char smem[];
    uint32_t* Fh = (uint32_t*)smem;             // 34816
    uint32_t* Wh = (uint32_t*)(smem + 34816);   // 34816
    uint32_t* pc2_s = (uint32_t*)(smem + 69632); // 256
    float* mean_s = (float*)(smem + 70144);     // 512
    float* rstd_s = (float*)(smem + 70656);     // 512 -> 71168

    const int tid = threadIdx.x, warp = tid >> 5, lane = tid & 31;
    const int g = lane >> 2, t = lane & 3;
    const int m0 = (warp >> 2) * 64, n0c = (warp & 3) * 32;
    const int nb0 = blockIdx.x << 7, b = nb0 >> 14;
    const float* Wl1 = msg1W + (size_t)l * 264 * 128;

    if (blockIdx.x == 0)
        for (int i = tid; i < SBUF; i += 256) g_stats[(l & 1) * SBUF + i] = 0.0f;
    if (tid < 64) {
        float s0 = msg1b[l * 128 + 2 * tid], s1 = msg1b[l * 128 + 2 * tid + 1];
#pragma unroll
        for (int p = 0; p < NPRM; ++p) {
            float cpv = cp[b * NPRM + p];
            s0 = fmaf(cpv, Wl1[(259 + p) * 128 + 2 * tid], s0);
            s1 = fmaf(cpv, Wl1[(259 + p) * 128 + 2 * tid + 1], s1);
        }
        pc2_s[tid] = h2u(__floats2half2_rn(s0, s1));
    }
    if (l > 0) {  // fused layernorm of previous layer's g_tmp
        if (tid < 128) {
            const float* st = g_stats + ((l - 1) & 1) * SBUF + b * 256;
            float m = st[tid] * (1.0f / (float)HW);
            float v = st[128 + tid] * (1.0f / (float)HW) - m * m;
            mean_s[tid] = m;
            rstd_s[tid] = rsqrtf(v + EPSV);
        }
        __syncthreads();
#pragma unroll 4
        for (int i = tid; i < 4096; i += 256) {
            int c = i >> 5, q = i & 31, j = q * 4;
            float4 v = *(const float4*)(g_tmp + (size_t)(nb0 + c) * 128 + j);
            v.x = (v.x - mean_s[j + 0]) * rstd_s[j + 0];
            v.y = (v.y - mean_s[j + 1]) * rstd_s[j + 1];
            v.z = (v.z - mean_s[j + 2]) * rstd_s[j + 2];
            v.w = (v.w - mean_s[j + 3]) * rstd_s[j + 3];
            *(float4*)(g_f + (size_t)(nb0 + c) * 128 + j) = v;  // edge reads this
            *(uint2*)(Fh + c * PS + 2 * q) = make_uint2(
                h2u(__floats2half2_rn(v.x, v.y)), h2u(__floats2half2_rn(v.z, v.w)));
        }
    } else {
#pragma unroll 4
        for (int i = tid; i < 4096; i += 256) {
            int c = i >> 5, q = i & 31;
            float4 fv = *(const float4*)(g_f + (size_t)(nb0 + c) * 128 + q * 4);
            *(uint2*)(Fh + c * PS + 2 * q) = make_uint2(
                h2u(__floats2half2_rn(fv.x, fv.y)), h2u(__floats2half2_rn(fv.z, fv.w)));
        }
    }
    copy_wt(Wh, l * 6 + 0, tid);  // W_t
    __syncthreads();

    uint32_t accd[4][4][2];
    ZERO442(accd);
    gemmh16(Fh, Wh, accd, m0, n0c, lane);
#pragma unroll
    for (int mi = 0; mi < 4; ++mi) {
        int c0 = m0 + 16 * mi + g;
#pragma unroll
        for (int nj = 0; nj < 4; ++nj) {
            int col = n0c + 8 * nj + 2 * t;
            __half2 pc = u2h(pc2_s[col >> 1]);
            *(uint32_t*)(g_Ah + (size_t)(nb0 + c0) * 128 + col) =
                h2u(__hadd2(u2h(accd[mi][nj][0]), pc));
            *(uint32_t*)(g_Ah + (size_t)(nb0 + c0 + 8) * 128 + col) =
                h2u(__hadd2(u2h(accd[mi][nj][1]), pc));
        }
    }
    __syncthreads();
    copy_wt(Wh, l * 6 + 1, tid);  // W_s
    __syncthreads();
    ZERO442(accd);
    gemmh16(Fh, Wh, accd, m0, n0c, lane);
#pragma unroll
    for (int mi = 0; mi < 4; ++mi) {
        int c0 = m0 + 16 * mi + g;
#pragma unroll
        for (int nj = 0; nj < 4; ++nj) {
            int col = n0c + 8 * nj + 2 * t;
            *(uint32_t*)(g_Bh + (size_t)(nb0 + c0) * 128 + col) = accd[mi][nj][0];
            *(uint32_t*)(g_Bh + (size_t)(nb0 + c0 + 8) * 128 + col) = accd[mi][nj][1];
        }
    }
}

// ------------- k_edge_mm: messages + agg + update MLP -------------
__global__ __launch_bounds__(256, 2) void k_edge_mm(
    const float* __restrict__ inp, const float* __restrict__ cp,
    const float* __restrict__ msg1W, const float* __restrict__ msg2b,
    const float* __restrict__ upd1W, const float* __restrict__ upd1b,
    const float* __restrict__ upd2b, int l) {
    extern __shared__ char smem[];
    uint32_t* Mh0 = (uint32_t*)smem;              // 34816
    uint32_t* Mh1 = (uint32_t*)(smem + 34816);    // 34816
    uint32_t* Wh = (uint32_t*)(smem + 69632);     // 34816
    uint32_t* posW2 = (uint32_t*)(smem + 104448); // 2048
    uint32_t* wu2 = (uint32_t*)(smem + 106496);   // 256
    uint32_t* b2m2 = (uint32_t*)(smem + 106752);  // 256
    uint32_t* pc2u = (uint32_t*)(smem + 107264);  // 256
    uint32_t* b2u2 = (uint32_t*)(smem + 107520);  // 256
    uint32_t* du2a = (uint32_t*)(smem + 108288);  // 4096
    float* cp_s = (float*)(smem + 112384);        // 32 -> 112416
    float* stage = (float*)smem;                  // late reuse (67584 < Mh0+Mh1)

    const int tid = threadIdx.x, warp = tid >> 5, lane = tid & 31;
    const int g = lane >> 2, t = lane & 3;
    const int m0 = (warp >> 2) * 64, n0c = (warp & 3) * 32;
    const int gr = blockIdx.x, b = gr >> 7, r = gr & 127, nb0 = gr << 7;
    const float* W1l = msg1W + (size_t)l * 264 * 128;
    const float* U1 = upd1W + (size_t)l * 261 * 128;

    if (tid < 8) cp_s[tid] = (tid < NPRM) ? cp[b * NPRM + tid] : 0.0f;
    if (tid < 64) {
        b2m2[tid] = h2u(__floats2half2_rn(msg2b[l * 128 + 2 * tid],
                                          msg2b[l * 128 + 2 * tid + 1]));
        wu2[tid] = h2u(__floats2half2_rn(W1l[256 * 128 + 2 * tid],
                                         W1l[256 * 128 + 2 * tid + 1]));
        b2u2[tid] = h2u(__floats2half2_rn(upd2b[l * 128 + 2 * tid],
                                          upd2b[l * 128 + 2 * tid + 1]));
    }
    __syncthreads();
    if (tid < 64) {  // pcu as half2 (needs cp_s)
        float s0 = upd1b[l * 128 + 2 * tid], s1 = upd1b[l * 128 + 2 * tid + 1];
#pragma unroll
        for (int p = 0; p < NPRM; ++p) {
            s0 = fmaf(cp_s[p], U1[(256 + p) * 128 + 2 * tid], s0);
            s1 = fmaf(cp_s[p], U1[(256 + p) * 128 + 2 * tid + 1], s1);
        }
        pc2u[tid] = h2u(__floats2half2_rn(s0, s1));
    }
    for (int i = tid; i < 512; i += 256) {  // posW half2: [d][64]
        int d = i >> 6, j = i & 63;
        float pdx = (float)(-c_dr[d]) * (1.0f / 127.0f) * cp_s[1];
        float pdy = (float)(-c_dc[d]) * (1.0f / 127.0f) * cp_s[0];
        float v0 = pdx * W1l[257 * 128 + 2 * j] + pdy * W1l[258 * 128 + 2 * j];
        float v1 = pdx * W1l[257 * 128 + 2 * j + 1] + pdy * W1l[258 * 128 + 2 * j + 1];
        posW2[i] = h2u(__floats2half2_rn(v0, v1));
    }
#pragma unroll 2
    for (int i = tid; i < 1024; i += 256) {  // du for ALL 8 directions upfront
        int d = i >> 7, c = i & 127;
        int n = nb0 + c, nb = n + c_dr[d] * WW + c_dc[d];
        nb = min(max(nb, 0), NN - 1);
        int bb = nb >> 14;
        float du = inp[b * NCH * HW + (n - b * HW)] -
                   inp[bb * NCH * HW + (nb - bb * HW)];
        du2a[i] = h2u(__half2half2(__float2half_rn(du)));
    }
    copy_wt(Wh, l * 6 + 2, tid);  // msg2W
    __syncthreads();              // init fills visible

    __half2 agg[4][4][2];
#pragma unroll
    for (int i = 0; i < 4; ++i)
#pragma unroll
        for (int j = 0; j < 4; ++j) {
            agg[i][j][0] = __float2half2_rn(0.0f);
            agg[i][j][1] = __float2half2_rn(0.0f);
        }

    int ad = 0;  // active-direction counter (buffer parity)
#pragma unroll 1
    for (int d = 0; d < 8; ++d) {
        const int dr = c_dr[d], dc = c_dc[d];
        if ((unsigned)(r + dr) >= (unsigned)HH) continue;
        uint32_t* Mb = (ad & 1) ? Mh1 : Mh0;
        // build M into Mb (other buffer may still be read by previous gemm)
#pragma unroll 4
        for (int i = tid; i < 4096; i += 256) {
            int c = i >> 5, q = i & 31;
            int nb = nb0 + c + dr * WW + dc;
            nb = min(max(nb, 0), NN - 1);
            uint2 bm = *(const uint2*)(g_Bh + (size_t)nb * 128 + q * 4);
            uint2 av = *(const uint2*)(g_Ah + (size_t)(nb0 + c) * 128 + q * 4);
            __half2 hd = u2h(du2a[d * 128 + c]);
            __half2 s0 = __hadd2(__hadd2(u2h(av.x), u2h(bm.x)),
                                 __hfma2(hd, u2h(wu2[2 * q]), u2h(posW2[d * 64 + 2 * q])));
            __half2 s1 = __hadd2(__hadd2(u2h(av.y), u2h(bm.y)),
                                 __hfma2(hd, u2h(wu2[2 * q + 1]),
                                         u2h(posW2[d * 64 + 2 * q + 1])));
            *(uint2*)(Mb + c * PS + 2 * q) = make_uint2(h2u(psw2(s0)), h2u(psw2(s1)));
        }
        __syncthreads();  // Mb visible; also proves gemm(ad-1) done by all
        uint32_t accd[4][4][2];
        ZERO442(accd);
        gemmh16(Mb, Wh, accd, m0, n0c, lane);
#pragma unroll
        for (int mi = 0; mi < 4; ++mi) {
            int c0 = m0 + 16 * mi + g;
            bool ok0 = (unsigned)(c0 + dc) < (unsigned)WW;
            bool ok1 = (unsigned)(c0 + 8 + dc) < (unsigned)WW;
#pragma unroll
            for (int nj = 0; nj < 4; ++nj) {
                int col = n0c + 8 * nj + 2 * t;
                __half2 bb = u2h(b2m2[col >> 1]);
                if (ok0)
                    agg[mi][nj][0] = __hadd2(
                        agg[mi][nj][0], psw2(__hadd2(u2h(accd[mi][nj][0]), bb)));
                if (ok1)
                    agg[mi][nj][1] = __hadd2(
                        agg[mi][nj][1], psw2(__hadd2(u2h(accd[mi][nj][1]), bb)));
            }
        }
        ++ad;
    }
    __syncthreads();  // all message gemms done; Mh0/Mh1/Wh free

    // -------- update MLP (all f16 accumulators) --------
    {   // agg -> Mh0
        int crn = 1 + (r > 0) + (r < HH - 1);
#pragma unroll
        for (int mi = 0; mi < 4; ++mi) {
#pragma unroll
            for (int hh = 0; hh < 2; ++hh) {
                int c0 = m0 + 16 * mi + g + 8 * hh;
                float inv = 1.0f / (float)(crn * (1 + (c0 > 0) + (c0 < WW - 1)) - 1);
                __half2 inv2 = __float2half2_rn(inv);
#pragma unroll
                for (int nj = 0; nj < 4; ++nj)
                    Mh0[c0 * PS + (n0c >> 1) + 4 * nj + t] =
                        h2u(__hmul2(agg[mi][nj][hh], inv2));
            }
        }
    }
#pragma unroll 4
    for (int i = tid; i < 4096; i += 256) {  // f -> Mh1 (fp16)
        int c = i >> 5, q = i & 31;
        float4 fv = *(const float4*)(g_f + (size_t)(nb0 + c) * 128 + q * 4);
        *(uint2*)(Mh1 + c * PS + 2 * q) = make_uint2(
            h2u(__floats2half2_rn(fv.x, fv.y)), h2u(__floats2half2_rn(fv.z, fv.w)));
    }
    copy_wt(Wh, l * 6 + 3, tid);  // U1 agg rows
    __syncthreads();
    uint32_t acc2d[4][4][2];
    ZERO442(acc2d);
    gemmh16(Mh0, Wh, acc2d, m0, n0c, lane);
    __syncthreads();
    copy_wt(Wh, l * 6 + 4, tid);  // U1 f rows
    __syncthreads();
    gemmh16(Mh1, Wh, acc2d, m0, n0c, lane);  // accumulate
    __syncthreads();
#pragma unroll
    for (int mi = 0; mi < 4; ++mi) {  // h1 = swish(acc2 + pcu) -> Mh0
#pragma unroll
        for (int nj = 0; nj < 4; ++nj) {
            int col = n0c + 8 * nj + 2 * t;
            int c0 = m0 + 16 * mi + g;
            __half2 pc = u2h(pc2u[col >> 1]);
            Mh0[c0 * PS + (col >> 1)] =
                h2u(psw2(__hadd2(u2h(acc2d[mi][nj][0]), pc)));
            Mh0[(c0 + 8) * PS + (col >> 1)] =
                h2u(psw2(__hadd2(u2h(acc2d[mi][nj][1]), pc)));
        }
    }
    copy_wt(Wh, l * 6 + 5, tid);  // U2
    __syncthreads();
    uint32_t acc3d[4][4][2];
    ZERO442(acc3d);
    gemmh16(Mh0, Wh, acc3d, m0, n0c, lane);
    __syncthreads();  // gemm done; stage may overwrite Mh0/Mh1

    // -------- residual + stores + layernorm stats --------
#pragma unroll
    for (int mi = 0; mi < 4; ++mi) {
#pragma unroll
        for (int half = 0; half < 2; ++half) {
            int c0 = m0 + 16 * mi + g + 8 * half;
#pragma unroll
            for (int nj = 0; nj < 4; ++nj) {
                int col = n0c + 8 * nj + 2 * t;
                float2 f2 = *(const float2*)(g_f + (size_t)(nb0 + c0) * 128 + col);
                __half2 upd = psw2(__hadd2(u2h(acc3d[mi][nj][half]),
                                           u2h(b2u2[col >> 1])));
                float v0 = f2.x + __low2float(upd);
                float v1 = f2.y + __high2float(upd);
                *(float2*)(g_tmp + (size_t)(nb0 + c0) * 128 + col) = make_float2(v0, v1);
                *(float2*)(stage + c0 * 132 + col) = make_float2(v0, v1);
            }
        }
    }
    __syncthreads();
    if (tid < 128) {
        float S = 0.0f, S2 = 0.0f;
#pragma unroll 4
        for (int gg = 0; gg < 128; ++gg) {
            float v = stage[gg * 132 + tid];
            S += v;
            S2 += v * v;
        }
        atomicAdd(&g_stats[(l & 1) * SBUF + b * 256 + tid], S);
        atomicAdd(&g_stats[(l & 1) * SBUF + b * 256 + 128 + tid], S2);
    }
}

// ================= fp32 kernels =================
#define ACC_ZERO(acc)                                                  \
    _Pragma("unroll") for (int _i = 0; _i < 4; ++_i)                   \
        _Pragma("unroll") for (int _j = 0; _j < 8; ++_j) acc[_i][_j] = 0.0f;

template <int RSTEP>
__device__ __forceinline__ void gemm128(const float* __restrict__ As, int lda,
                                        const float* __restrict__ Ws, int ldw,
                                        float acc[4][8], int tr, int tc) {
#pragma unroll 4
    for (int k4 = 0; k4 < 32; ++k4) {
        float4 a[4];
#pragma unroll
        for (int i = 0; i < 4; ++i)
            a[i] = *(const float4*)(As + (tr + i * RSTEP) * lda + k4 * 4);
        const float* wp = Ws + (k4 * 4) * ldw + tc * 8;
#pragma unroll
        for (int kk = 0; kk < 4; ++kk) {
            float4 b0 = *(const float4*)(wp + kk * ldw);
            float4 b1 = *(const float4*)(wp + kk * ldw + 4);
#pragma unroll
            for (int i = 0; i < 4; ++i) {
                float av = ((const float*)(a + i))[kk];
                acc[i][0] = fmaf(av, b0.x, acc[i][0]);
                acc[i][1] = fmaf(av, b0.y, acc[i][1]);
                acc[i][2] = fmaf(av, b0.z, acc[i][2]);
                acc[i][3] = fmaf(av, b0.w, acc[i][3]);
                acc[i][4] = fmaf(av, b1.x, acc[i][4]);
                acc[i][5] = fmaf(av, b1.y, acc[i][5]);
                acc[i][6] = fmaf(av, b1.z, acc[i][6]);
                acc[i][7] = fmaf(av, b1.w, acc[i][7]);
            }
        }
    }
}

__global__ __launch_bounds__(256, 2) void k_embed(
    const float* __restrict__ inp, const float* __restrict__ cp,
    const float* __restrict__ W1, const float* __restrict__ b1,
    const float* __restrict__ W2, const float* __restrict__ b2) {
    extern __shared__ float sm[];
    float* e_s = sm;
    float* W1_s = e_s + 64 * 8;
    float* b1_s = W1_s + 8 * 128;
    float* h1_s = b1_s + 128;
    float* W2_s = h1_s + 64 * 132;
    float* b2_s = W2_s + 128 * 128;
    int tid = threadIdx.x;
    int n0 = blockIdx.x * 64, b = n0 / HW;
    for (int i = tid; i < 8 * 128; i += 256) W1_s[i] = W1[i];
    if (tid < 128) { b1_s[tid] = b1[tid]; b2_s[tid] = b2[tid]; }
    for (int i = tid; i < 128 * 32; i += 256)
        ((float4*)W2_s)[i] = ((const float4*)W2)[i];
    if (tid < 64) {
        int n = n0 + tid, rc = n - b * HW;
        int r = rc >> 7, c = rc & 127;
        e_s[tid * 8 + 0] = inp[b * NCH * HW + rc];
        e_s[tid * 8 + 1] = (float)r * (1.0f / 127.0f) * cp[b * NPRM + 1];
        e_s[tid * 8 + 2] = (float)c * (1.0f / 127.0f) * cp[b * NPRM + 0];
#pragma unroll
        for (int p = 0; p < NPRM; ++p) e_s[tid * 8 + 3 + p] = cp[b * NPRM + p];
    }
    __syncthreads();
    int tc = tid & 15, tr = tid >> 4;
#pragma unroll
    for (int i = 0; i < 4; ++i) {
        int row = tr + 16 * i;
#pragma unroll
        for (int j = 0; j < 8; ++j) {
            float s = b1_s[tc * 8 + j];
#pragma unroll
            for (int k = 0; k < 8; ++k)
                s = fmaf(e_s[row * 8 + k], W1_s[k * 128 + tc * 8 + j], s);
            h1_s[row * 132 + tc * 8 + j] = swishf(s);
        }
    }
    __syncthreads();
    float acc[4][8];
    ACC_ZERO(acc);
    gemm128<16>(h1_s, 132, W2_s, 128, acc, tr, tc);
#pragma unroll
    for (int i = 0; i < 4; ++i) {
        int row = tr + 16 * i;
#pragma unroll
        for (int j = 0; j < 8; ++j)
            g_f[(size_t)(n0 + row) * 128 + tc * 8 + j] =
                swishf(acc[i][j] + b2_s[tc * 8 + j]);
    }
}

// k_out with fused final layernorm (stats buffer (NL-1)&1 = 1)
__global__ __launch_bounds__(256, 2) void k_out(
    const float* __restrict__ inp, const float* __restrict__ W1,
    const float* __restrict__ b1, const float* __restrict__ W2,
    const float* __restrict__ b2, float* __restrict__ out) {
    extern __shared__ float sm[];
    float* f_s = sm;
    float* W1_s = f_s + 128 * 132;
    float* b1_s = W1_s + 128 * 64;
    float* W2_s = b1_s + 64;
    float* red_s = W2_s + 64;
    float* mean_s = red_s + 128 * 8;
    float* rstd_s = mean_s + 128;
    int tid = threadIdx.x;
    int n0 = blockIdx.x * 128, b = n0 / HW;
    if (tid < 128) {
        const float* st = g_stats + ((NL - 1) & 1) * SBUF + b * 256;
        float m = st[tid] * (1.0f / (float)HW);
        float v = st[128 + tid] * (1.0f / (float)HW) - m * m;
        mean_s[tid] = m;
        rstd_s[tid] = rsqrtf(v + EPSV);
    }
    __syncthreads();
    for (int i = tid; i < 128 * 32; i += 256) {
        int c = i >> 5, q = i & 31, j = q * 4;
        float4 v = *(const float4*)(g_tmp + (size_t)(n0 + c) * 128 + j);
        v.x = (v.x - mean_s[j + 0]) * rstd_s[j + 0];
        v.y = (v.y - mean_s[j + 1]) * rstd_s[j + 1];
        v.z = (v.z - mean_s[j + 2]) * rstd_s[j + 2];
        v.w = (v.w - mean_s[j + 3]) * rstd_s[j + 3];
        ((float4*)(f_s + c * 132))[q] = v;
    }
    for (int i = tid; i < 128 * 16; i += 256)
        ((float4*)W1_s)[i] = ((const float4*)W1)[i];
    if (tid < 64) { b1_s[tid] = b1[tid]; W2_s[tid] = W2[tid]; }
    __syncthreads();
    int tc = tid & 7, tr = tid >> 3;
    float acc[4][8];
    ACC_ZERO(acc);
    gemm128<32>(f_s, 132, W1_s, 64, acc, tr, tc);
#pragma unroll
    for (int i = 0; i < 4; ++i) {
        float p = 0.0f;
#pragma unroll
        for (int j = 0; j < 8; ++j)
            p += swishf(acc[i][j] + b1_s[tc * 8 + j]) * W2_s[tc * 8 + j];
        red_s[(tr + 32 * i) * 8 + tc] = p;
    }
    __syncthreads();
    if (tid < 128) {
        float d = b2[0];
#pragma unroll
        for (int t = 0; t < 8; ++t) d += red_s[tid * 8 + t];
        int n = n0 + tid;
        out[n] = inp[b * NCH * HW + (n - b * HW)] + DTV * d;
    }
}

// ---------------- host launcher ----------------
extern "C" void kernel_launch(void* const* d_in, const int* in_sizes, int n_in,
                              void* d_out, int out_size) {
    const float* inp   = (const float*)d_in[0];
    const float* cp    = (const float*)d_in[1];
    const float* embW1 = (const float*)d_in[3];
    const float* embb1 = (const float*)d_in[4];
    const float* embW2 = (const float*)d_in[5];
    const float* embb2 = (const float*)d_in[6];
    const float* msg1W = (const float*)d_in[7];
    const float* msg1b = (const float*)d_in[8];
    const float* msg2W = (const float*)d_in[9];
    const float* msg2b = (const float*)d_in[10];
    const float* upd1W = (const float*)d_in[11];
    const float* upd1b = (const float*)d_in[12];
    const float* upd2W = (const float*)d_in[13];
    const float* upd2b = (const float*)d_in[14];
    const float* outW1 = (const float*)d_in[15];
    const float* outb1 = (const float*)d_in[16];
    const float* outW2 = (const float*)d_in[17];
    const float* outb2 = (const float*)d_in[18];
    float* out = (float*)d_out;

    const size_t smE = (size_t)(64 * 8 + 8 * 128 + 128 + 64 * 132 + 128 * 128 + 128) * 4;
    const size_t smO = (size_t)(128 * 132 + 128 * 64 + 64 + 64 + 128 * 8 + 256) * 4;
    const size_t smMA = 71168;
    const size_t smEG = 112416;

    cudaFuncSetAttribute(k_embed, cudaFuncAttributeMaxDynamicSharedMemorySize, (int)smE);
    cudaFuncSetAttribute(k_out, cudaFuncAttributeMaxDynamicSharedMemorySize, (int)smO);
    cudaFuncSetAttribute(k_msgA_mm, cudaFuncAttributeMaxDynamicSharedMemorySize, (int)smMA);
    cudaFuncSetAttribute(k_edge_mm, cudaFuncAttributeMaxDynamicSharedMemorySize, (int)smEG);

    k_prep<<<36, 256>>>(msg1W, msg2W, upd1W, upd2W);
    k_embed<<<NN / 64, 256, smE>>>(inp, cp, embW1, embb1, embW2, embb2);
    for (int l = 0; l < NL; ++l) {
        k_msgA_mm<<<NN / 128, 256, smMA>>>(cp, msg1W, msg1b, l);
        k_edge_mm<<<NN / 128, 256, smEG>>>(inp, cp, msg1W, msg2b,
                                           upd1W, upd1b, upd2b, l);
    }
    k_out<<<NN / 128, 256, smO>>>(inp, outW1, outb1, outW2, outb2, out);
}